// round 1
// baseline (speedup 1.0000x reference)
#include <cuda_runtime.h>
#include <math.h>

#define NN 50000
#define EE 800000
#define EP 200000
#define HIDF 128
#define HANIN 256

// ---------------- scratch (static __device__ — allocation-free) ----------------
__device__ float g_ha[NN * HANIN];          // 51.2MB
__device__ float g_ht[NN * HANIN];          // 51.2MB
__device__ float g_fs[NN * HIDF];           // 25.6MB (reused per graph)
__device__ float g_fd[NN * HIDF];           // 25.6MB
__device__ float g_z[4 * NN * HIDF];        // 102.4MB  (pre-relu GAT outputs)
__device__ float g_logits[EE * 4];          // 12.8MB (logits, then ex)
__device__ unsigned g_m[4 * NN * 4];        // encoded segment max
__device__ float g_s[4 * NN * 4];           // segment sum of exp
__device__ float g_haout[NN * HIDF];
__device__ float g_htout[NN * HIDF];
__device__ float g_pa[NN * HIDF];
__device__ float g_pt[NN * HIDF];
__device__ float g_watt[4];
__device__ float g_beta[4];

// ---------------- helpers ----------------
__device__ __forceinline__ unsigned fenc(float f) {
    unsigned u = __float_as_uint(f);
    return (u & 0x80000000u) ? ~u : (u | 0x80000000u);
}
__device__ __forceinline__ float fdec(unsigned u) {
    return (u & 0x80000000u) ? __uint_as_float(u ^ 0x80000000u) : __uint_as_float(~u);
}

// ---------------- generic SGEMM: C = A[M,K] @ B[K,N] + bias ----------------
// BM=BN=128, BK=16, 256 threads, 8x8 per thread. K % 16 == 0, N % 128 == 0.
__global__ __launch_bounds__(256) void sgemm128(
    const float* __restrict__ A, const float* __restrict__ B,
    const float* __restrict__ bias, float* __restrict__ C,
    int M, int N, int K)
{
    __shared__ float As[16][128];
    __shared__ float Bs[16][128];
    const int tid = threadIdx.x;
    const int tx = tid & 15, ty = tid >> 4;
    const int rowBase = blockIdx.y * 128;
    const int colBase = blockIdx.x * 128;

    float acc[8][8];
#pragma unroll
    for (int i = 0; i < 8; i++)
#pragma unroll
        for (int j = 0; j < 8; j++) acc[i][j] = 0.f;

    for (int k0 = 0; k0 < K; k0 += 16) {
#pragma unroll
        for (int s = 0; s < 2; s++) {
            int slot = tid + s * 256;               // 0..511
            // A tile: 128 rows x 4 float4
            int r = slot >> 2, c4 = (slot & 3) * 4;
            float4 v = make_float4(0.f, 0.f, 0.f, 0.f);
            int gr = rowBase + r;
            if (gr < M) v = *reinterpret_cast<const float4*>(A + (size_t)gr * K + k0 + c4);
            As[c4 + 0][r] = v.x; As[c4 + 1][r] = v.y; As[c4 + 2][r] = v.z; As[c4 + 3][r] = v.w;
            // B tile: 16 rows x 32 float4
            int rb = slot >> 5, cb = (slot & 31) * 4;
            float4 w = *reinterpret_cast<const float4*>(B + (size_t)(k0 + rb) * N + colBase + cb);
            *reinterpret_cast<float4*>(&Bs[rb][cb]) = w;
        }
        __syncthreads();
#pragma unroll
        for (int kk = 0; kk < 16; kk++) {
            float ra[8], rb[8];
#pragma unroll
            for (int i = 0; i < 8; i++) ra[i] = As[kk][ty * 8 + i];
#pragma unroll
            for (int j = 0; j < 8; j++) rb[j] = Bs[kk][tx * 8 + j];
#pragma unroll
            for (int i = 0; i < 8; i++)
#pragma unroll
                for (int j = 0; j < 8; j++) acc[i][j] = fmaf(ra[i], rb[j], acc[i][j]);
        }
        __syncthreads();
    }
#pragma unroll
    for (int i = 0; i < 8; i++) {
        int gr = rowBase + ty * 8 + i;
        if (gr >= M) continue;
#pragma unroll
        for (int j = 0; j < 8; j += 4) {
            int gc = colBase + tx * 8 + j;
            float4 o = make_float4(acc[i][j], acc[i][j + 1], acc[i][j + 2], acc[i][j + 3]);
            if (bias) { o.x += bias[gc]; o.y += bias[gc + 1]; o.z += bias[gc + 2]; o.w += bias[gc + 3]; }
            *reinterpret_cast<float4*>(C + (size_t)gr * N + gc) = o;
        }
    }
}

// ---------------- GATv2 pass A: per-edge logits + segment max ----------------
// one warp per edge; lane covers 4 consecutive feats; head = lane/8
__global__ void edge_logits(const float* __restrict__ fs, const float* __restrict__ fd,
                            const int* __restrict__ src, const int* __restrict__ dst,
                            const float* __restrict__ attn, float* __restrict__ logits,
                            unsigned* __restrict__ mmax, int E)
{
    int gw = (blockIdx.x * blockDim.x + threadIdx.x) >> 5;
    int lane = threadIdx.x & 31;
    if (gw >= E) return;
    int s = src[gw], d = dst[gw];
    float4 a = __ldg(reinterpret_cast<const float4*>(fs) + s * 32 + lane);
    float4 b = __ldg(reinterpret_cast<const float4*>(fd) + d * 32 + lane);
    float4 at = __ldg(reinterpret_cast<const float4*>(attn) + lane);
    float vx = a.x + b.x, vy = a.y + b.y, vz = a.z + b.z, vw = a.w + b.w;
    vx = vx > 0.f ? vx : 0.2f * vx;
    vy = vy > 0.f ? vy : 0.2f * vy;
    vz = vz > 0.f ? vz : 0.2f * vz;
    vw = vw > 0.f ? vw : 0.2f * vw;
    float p = vx * at.x + vy * at.y + vz * at.z + vw * at.w;
    p += __shfl_down_sync(0xffffffffu, p, 4, 8);
    p += __shfl_down_sync(0xffffffffu, p, 2, 8);
    p += __shfl_down_sync(0xffffffffu, p, 1, 8);
    if ((lane & 7) == 0) {
        int h = lane >> 3;
        logits[gw * 4 + h] = p;
        atomicMax(&mmax[d * 4 + h], fenc(p));
    }
}

// ---------------- pass B: ex = exp(logit - m[dst]); segment sum ----------------
__global__ void edge_exp(float* __restrict__ logits, const int* __restrict__ dst,
                         const unsigned* __restrict__ mmax, float* __restrict__ ssum, int E4)
{
    int i = blockIdx.x * blockDim.x + threadIdx.x;
    if (i >= E4) return;
    int e = i >> 2, h = i & 3;
    int d = dst[e];
    float m = fdec(mmax[d * 4 + h]);
    if (!isfinite(m)) m = 0.f;
    float ex = expf(logits[i] - m);
    logits[i] = ex;
    atomicAdd(&ssum[d * 4 + h], ex);
}

// ---------------- pass C: z[dst] += alpha * fs[src] (vector RED) ----------------
__global__ void edge_aggregate(const float* __restrict__ fs, const int* __restrict__ src,
                               const int* __restrict__ dst, const float* __restrict__ ex,
                               const float* __restrict__ ssum, float* __restrict__ zout, int E)
{
    int gw = (blockIdx.x * blockDim.x + threadIdx.x) >> 5;
    int lane = threadIdx.x & 31;
    if (gw >= E) return;
    int s = src[gw], d = dst[gw];
    int h = lane >> 3;
    float alpha = ex[gw * 4 + h] / ssum[d * 4 + h];
    float4 v = __ldg(reinterpret_cast<const float4*>(fs) + s * 32 + lane);
    float* p = zout + (size_t)d * 128 + lane * 4;
    asm volatile("red.global.add.v4.f32 [%0], {%1,%2,%3,%4};"
                 :: "l"(p), "f"(v.x * alpha), "f"(v.y * alpha), "f"(v.z * alpha), "f"(v.w * alpha)
                 : "memory");
}

// ---------------- semantic attention partial: sum_n tanh(relu(z_n)@Wa + ba) . Wo ----------------
// 128 threads, 8 rows per block. NN % 8 == 0.
__global__ void sematt_partial(const float* __restrict__ z, const float* __restrict__ Wa,
                               const float* __restrict__ ba, const float* __restrict__ Wo,
                               float* __restrict__ part)
{
    __shared__ float sz[8][128];
    __shared__ float sacc[8];
    int j = threadIdx.x;
    int r0 = blockIdx.x * 8;
    if (j < 8) sacc[j] = 0.f;
#pragma unroll
    for (int r = 0; r < 8; r++) {
        float v = z[(size_t)(r0 + r) * 128 + j];
        sz[r][j] = v > 0.f ? v : 0.f;
    }
    __syncthreads();
    float bj = ba[j];
    float acc[8];
#pragma unroll
    for (int r = 0; r < 8; r++) acc[r] = bj;
    for (int k = 0; k < 128; k++) {
        float w = Wa[k * 128 + j];
#pragma unroll
        for (int r = 0; r < 8; r++) acc[r] = fmaf(sz[r][k], w, acc[r]);
    }
    float wo = Wo[j];
#pragma unroll
    for (int r = 0; r < 8; r++) {
        float t = tanhf(acc[r]) * wo;
        for (int o = 16; o > 0; o >>= 1) t += __shfl_down_sync(0xffffffffu, t, o);
        if ((j & 31) == 0) atomicAdd(&sacc[r], t);
    }
    __syncthreads();
    if (j == 0) {
        float tot = 0.f;
#pragma unroll
        for (int r = 0; r < 8; r++) tot += sacc[r];
        atomicAdd(part, tot);
    }
}

__global__ void compute_beta()
{
    for (int grp = 0; grp < 2; grp++) {
        float w0 = g_watt[2 * grp] * (1.f / NN);
        float w1 = g_watt[2 * grp + 1] * (1.f / NN);
        float m = fmaxf(w0, w1);
        float e0 = expf(w0 - m), e1 = expf(w1 - m);
        float inv = 1.f / (e0 + e1);
        g_beta[2 * grp] = e0 * inv;
        g_beta[2 * grp + 1] = e1 * inv;
    }
}

// out = beta0*relu(z0) + beta1*relu(z1)
__global__ void combine(const float* __restrict__ z0, const float* __restrict__ z1,
                        float* __restrict__ out, int n, int betaIdx)
{
    int i = blockIdx.x * blockDim.x + threadIdx.x;
    if (i >= n) return;
    float b0 = g_beta[betaIdx], b1 = g_beta[betaIdx + 1];
    float a = z0[i], c = z1[i];
    out[i] = b0 * (a > 0.f ? a : 0.f) + b1 * (c > 0.f ? c : 0.f);
}

// ---------------- predictor: sigmoid(relu(pa[src]+pt[dst]+b1) . W2 + b2) ----------------
__global__ void predict_kernel(const float* __restrict__ pa, const float* __restrict__ pt,
                               const int* __restrict__ src, const int* __restrict__ dst,
                               const float* __restrict__ b1, const float* __restrict__ W2,
                               const float* __restrict__ b2, float* __restrict__ out, int E)
{
    int gw = (blockIdx.x * blockDim.x + threadIdx.x) >> 5;
    int lane = threadIdx.x & 31;
    if (gw >= E) return;
    int s = src[gw], d = dst[gw];
    float4 a = __ldg(reinterpret_cast<const float4*>(pa) + s * 32 + lane);
    float4 b = __ldg(reinterpret_cast<const float4*>(pt) + d * 32 + lane);
    float4 bb = __ldg(reinterpret_cast<const float4*>(b1) + lane);
    float4 w = __ldg(reinterpret_cast<const float4*>(W2) + lane);
    float ux = fmaxf(a.x + b.x + bb.x, 0.f);
    float uy = fmaxf(a.y + b.y + bb.y, 0.f);
    float uz = fmaxf(a.z + b.z + bb.z, 0.f);
    float uw = fmaxf(a.w + b.w + bb.w, 0.f);
    float dot = ux * w.x + uy * w.y + uz * w.z + uw * w.w;
    for (int o = 16; o > 0; o >>= 1) dot += __shfl_down_sync(0xffffffffu, dot, o);
    if (lane == 0) out[gw] = 1.f / (1.f + expf(-(dot + b2[0])));
}

// ---------------- host ----------------
extern "C" void kernel_launch(void* const* d_in, const int* in_sizes, int n_in,
                              void* d_out, int out_size)
{
    const float* prot   = (const float*)d_in[0];
    const float* gen    = (const float*)d_in[1];
    const float* W1     = (const float*)d_in[2];
    const float* b1     = (const float*)d_in[3];
    const float* W2     = (const float*)d_in[4];
    const float* b2     = (const float*)d_in[5];
    const float* gWs    = (const float*)d_in[6];
    const float* gbs    = (const float*)d_in[7];
    const float* gWd    = (const float*)d_in[8];
    const float* gbd    = (const float*)d_in[9];
    const float* gattn  = (const float*)d_in[10];
    const float* pAW1   = (const float*)d_in[11];
    const float* pAb1   = (const float*)d_in[12];
    const float* pAW2   = (const float*)d_in[13];
    const float* gAW1   = (const float*)d_in[14];
    const float* gAb1   = (const float*)d_in[15];
    const float* gAW2   = (const float*)d_in[16];
    const float* predW1 = (const float*)d_in[17];
    const float* predb1 = (const float*)d_in[18];
    const float* predW2 = (const float*)d_in[19];
    const float* predb2 = (const float*)d_in[20];
    const int* e_aa = (const int*)d_in[21];
    const int* e_ta = (const int*)d_in[22];
    const int* e_tt = (const int*)d_in[23];
    const int* e_at = (const int*)d_in[24];
    const int* pos_e = (const int*)d_in[25];
    const int* neg_e = (const int*)d_in[26];
    float* out = (float*)d_out;

    float *p_ha, *p_ht, *p_fs, *p_fd, *p_z, *p_logits, *p_s, *p_haout, *p_htout, *p_pa, *p_pt, *p_watt;
    unsigned* p_m;
    cudaGetSymbolAddress((void**)&p_ha, g_ha);
    cudaGetSymbolAddress((void**)&p_ht, g_ht);
    cudaGetSymbolAddress((void**)&p_fs, g_fs);
    cudaGetSymbolAddress((void**)&p_fd, g_fd);
    cudaGetSymbolAddress((void**)&p_z, g_z);
    cudaGetSymbolAddress((void**)&p_logits, g_logits);
    cudaGetSymbolAddress((void**)&p_m, g_m);
    cudaGetSymbolAddress((void**)&p_s, g_s);
    cudaGetSymbolAddress((void**)&p_haout, g_haout);
    cudaGetSymbolAddress((void**)&p_htout, g_htout);
    cudaGetSymbolAddress((void**)&p_pa, g_pa);
    cudaGetSymbolAddress((void**)&p_pt, g_pt);
    cudaGetSymbolAddress((void**)&p_watt, g_watt);

    // reset accumulators (graph-capturable async memsets)
    cudaMemsetAsync(p_z, 0, sizeof(float) * 4 * NN * HIDF);
    cudaMemsetAsync(p_m, 0, sizeof(unsigned) * 4 * NN * 4);
    cudaMemsetAsync(p_s, 0, sizeof(float) * 4 * NN * 4);
    cudaMemsetAsync(p_watt, 0, sizeof(float) * 4);

    const int MROWS = (NN + 127) / 128;  // 391

    // node feature projections
    sgemm128<<<dim3(2, MROWS), 256>>>(prot, W2, b2, p_ha, NN, 256, 1024);
    sgemm128<<<dim3(2, MROWS), 256>>>(gen, W1, b1, p_ht, NN, 256, 512);

    // per-metapath GATv2
    const int* edges[4] = { e_aa, e_ta, e_tt, e_at };
    for (int g = 0; g < 4; g++) {
        const float* Xs = (g == 0 || g == 3) ? p_ha : p_ht;  // src node type
        const float* Xd = (g == 0 || g == 1) ? p_ha : p_ht;  // dst node type
        sgemm128<<<dim3(1, MROWS), 256>>>(Xs, gWs + (size_t)g * 256 * 128, gbs + g * 128, p_fs, NN, 128, 256);
        sgemm128<<<dim3(1, MROWS), 256>>>(Xd, gWd + (size_t)g * 256 * 128, gbd + g * 128, p_fd, NN, 128, 256);
        const int* src = edges[g];
        const int* dst = edges[g] + EE;
        unsigned* mg = p_m + (size_t)g * NN * 4;
        float* sg = p_s + (size_t)g * NN * 4;
        float* zg = p_z + (size_t)g * NN * HIDF;
        edge_logits<<<(EE * 32 + 255) / 256, 256>>>(p_fs, p_fd, src, dst, gattn + g * 128, p_logits, mg, EE);
        edge_exp<<<(EE * 4 + 255) / 256, 256>>>(p_logits, dst, mg, sg, EE * 4);
        edge_aggregate<<<(EE * 32 + 255) / 256, 256>>>(p_fs, src, dst, p_logits, sg, zg, EE);
    }

    // semantic attention weights
    sematt_partial<<<NN / 8, 128>>>(p_z + 0 * (size_t)NN * HIDF, pAW1, pAb1, pAW2, p_watt + 0);
    sematt_partial<<<NN / 8, 128>>>(p_z + 1 * (size_t)NN * HIDF, pAW1, pAb1, pAW2, p_watt + 1);
    sematt_partial<<<NN / 8, 128>>>(p_z + 2 * (size_t)NN * HIDF, gAW1, gAb1, gAW2, p_watt + 2);
    sematt_partial<<<NN / 8, 128>>>(p_z + 3 * (size_t)NN * HIDF, gAW1, gAb1, gAW2, p_watt + 3);
    compute_beta<<<1, 1>>>();

    combine<<<(NN * HIDF + 255) / 256, 256>>>(p_z + 0 * (size_t)NN * HIDF, p_z + 1 * (size_t)NN * HIDF, p_haout, NN * HIDF, 0);
    combine<<<(NN * HIDF + 255) / 256, 256>>>(p_z + 2 * (size_t)NN * HIDF, p_z + 3 * (size_t)NN * HIDF, p_htout, NN * HIDF, 2);

    // predictor first layer, factorized over the concat
    sgemm128<<<dim3(1, MROWS), 256>>>(p_haout, predW1, nullptr, p_pa, NN, 128, 128);
    sgemm128<<<dim3(1, MROWS), 256>>>(p_htout, predW1 + 128 * 128, nullptr, p_pt, NN, 128, 128);

    // pos / neg scoring
    predict_kernel<<<(EP * 32 + 255) / 256, 256>>>(p_pa, p_pt, pos_e, pos_e + EP, predb1, predW2, predb2, out, EP);
    predict_kernel<<<(EP * 32 + 255) / 256, 256>>>(p_pa, p_pt, neg_e, neg_e + EP, predb1, predW2, predb2, out + EP, EP);
}

// round 3
// speedup vs baseline: 2.0559x; 2.0559x over previous
#include <cuda_runtime.h>
#include <cuda_bf16.h>
#include <math.h>
#include <cstdint>

#define NN 50000
#define EE 800000
#define EP 200000
#define HIDF 128

__device__ __forceinline__ uint32_t smem_u32(const void* p) {
    uint32_t a;
    asm("{ .reg .u64 t; cvta.to.shared.u64 t, %1; cvt.u32.u64 %0, t; }" : "=r"(a) : "l"(p));
    return a;
}

// ================= scratch (static __device__) =================
__device__ __nv_bfloat16 g_hab[NN * 256];
__device__ __nv_bfloat16 g_htb[NN * 256];
__device__ __nv_bfloat16 g_fsb[NN * 128];
__device__ __nv_bfloat16 g_fdb[NN * 128];
__device__ float g_z[4 * NN * HIDF];
__device__ float g_logits[EE * 4];
__device__ unsigned g_m[4 * NN * 4];
__device__ float g_s[4 * NN * 4];
__device__ __nv_bfloat16 g_haoutb[NN * 128];
__device__ __nv_bfloat16 g_htoutb[NN * 128];
__device__ float g_pa[NN * 128];
__device__ float g_pt[NN * 128];
__device__ float g_watt[4];
__device__ float g_beta[4];
__device__ __nv_bfloat16 g_wt[688128];   // transposed bf16 weights

#define OFF_W2T 0
#define OFF_W1T 262144
#define OFF_GWS 393216
#define OFF_GWD 524288
#define OFF_PW1 655360

// in [K,N] fp32 -> out [N,K] bf16, batched over blockIdx.y
__global__ void transpose_bf16_kernel(const float* __restrict__ in, __nv_bfloat16* __restrict__ out,
                                      int K, int N) {
    int idx = blockIdx.x * blockDim.x + threadIdx.x;
    if (idx >= K * N) return;
    size_t base = (size_t)blockIdx.y * K * N;
    int k = idx / N, n = idx % N;
    out[base + (size_t)n * K + k] = __float2bfloat16(in[base + idx]);
}

// ================= HMMA GEMM =================
// C[M,N] = A[M,K] @ Bt[N,K]^T + bias.  A fp32 or bf16 row-major, Bt bf16 rows of stride ldb.
// 128x128x32 tiles, 256 threads (8 warps, 4 m x 2 n), mma.m16n8k16.row.col bf16.
#define BKP 40   // padded BK in halves (32 + 8)

template <int AF32, int BF16OUT>
__global__ void __launch_bounds__(256) gemm_mma(
    const void* __restrict__ Ain, const __nv_bfloat16* __restrict__ Bt,
    const float* __restrict__ bias, void* __restrict__ Cout,
    int M, int N, int K, int ldb)
{
    __shared__ __align__(16) __nv_bfloat16 sA[128][BKP];
    __shared__ __align__(16) __nv_bfloat16 sB[128][BKP];
    __shared__ float sbias[128];

    const int tid = threadIdx.x;
    const int wid = tid >> 5, lane = tid & 31;
    const int wm = wid & 3, wn = wid >> 2;   // warp tile: rows wm*32..+31, cols wn*64..+63
    const int row0 = blockIdx.y * 128, col0 = blockIdx.x * 128;

    if (tid < 128) sbias[tid] = bias ? __ldg(bias + col0 + tid) : 0.f;

    float c[2][8][4];
#pragma unroll
    for (int i = 0; i < 2; i++)
#pragma unroll
        for (int j = 0; j < 8; j++)
#pragma unroll
            for (int q = 0; q < 4; q++) c[i][j][q] = 0.f;

    for (int k0 = 0; k0 < K; k0 += 32) {
        // --- load A tile (convert if fp32) ---
        if (AF32) {
            const float* Af = (const float*)Ain;
#pragma unroll
            for (int it = 0; it < 4; it++) {
                int idx = it * 256 + tid;            // 0..1023
                int r = idx >> 3, cc = idx & 7;      // cc: 4-float units
                float4 v = make_float4(0.f, 0.f, 0.f, 0.f);
                if (row0 + r < M)
                    v = *reinterpret_cast<const float4*>(Af + (size_t)(row0 + r) * K + k0 + cc * 4);
                __nv_bfloat162 h0 = __floats2bfloat162_rn(v.x, v.y);
                __nv_bfloat162 h1 = __floats2bfloat162_rn(v.z, v.w);
                uint2 pk = make_uint2(*reinterpret_cast<uint32_t*>(&h0), *reinterpret_cast<uint32_t*>(&h1));
                *reinterpret_cast<uint2*>(&sA[r][cc * 4]) = pk;
            }
        } else {
            const __nv_bfloat16* Ab = (const __nv_bfloat16*)Ain;
#pragma unroll
            for (int it = 0; it < 2; it++) {
                int idx = it * 256 + tid;            // 0..511
                int r = idx >> 2, cc = idx & 3;      // cc: 8-half units
                uint4 v = make_uint4(0, 0, 0, 0);
                if (row0 + r < M)
                    v = *reinterpret_cast<const uint4*>(Ab + (size_t)(row0 + r) * K + k0 + cc * 8);
                *reinterpret_cast<uint4*>(&sA[r][cc * 8]) = v;
            }
        }
        // --- load B tile ---
#pragma unroll
        for (int it = 0; it < 2; it++) {
            int idx = it * 256 + tid;
            int n = idx >> 2, cc = idx & 3;
            uint4 v = *reinterpret_cast<const uint4*>(Bt + (size_t)(col0 + n) * ldb + k0 + cc * 8);
            *reinterpret_cast<uint4*>(&sB[n][cc * 8]) = v;
        }
        __syncthreads();

#pragma unroll
        for (int kk = 0; kk < 32; kk += 16) {
            // A fragments: 2 m-tiles
            uint32_t a[2][4];
#pragma unroll
            for (int mt = 0; mt < 2; mt++) {
                uint32_t addr = smem_u32(&sA[wm * 32 + mt * 16 + (lane & 15)][kk + ((lane >> 4) & 1) * 8]);
                asm volatile("ldmatrix.sync.aligned.m8n8.x4.shared.b16 {%0,%1,%2,%3}, [%4];"
                             : "=r"(a[mt][0]), "=r"(a[mt][1]), "=r"(a[mt][2]), "=r"(a[mt][3]) : "r"(addr));
            }
            // B fragments: 8 n-tiles
            uint32_t b[8][2];
#pragma unroll
            for (int nt = 0; nt < 8; nt++) {
                uint32_t addr = smem_u32(&sB[wn * 64 + nt * 8 + (lane & 7)][kk + ((lane >> 3) & 1) * 8]);
                asm volatile("ldmatrix.sync.aligned.m8n8.x2.shared.b16 {%0,%1}, [%2];"
                             : "=r"(b[nt][0]), "=r"(b[nt][1]) : "r"(addr));
            }
#pragma unroll
            for (int mt = 0; mt < 2; mt++)
#pragma unroll
                for (int nt = 0; nt < 8; nt++)
                    asm volatile(
                        "mma.sync.aligned.m16n8k16.row.col.f32.bf16.bf16.f32 "
                        "{%0,%1,%2,%3}, {%4,%5,%6,%7}, {%8,%9}, {%0,%1,%2,%3};"
                        : "+f"(c[mt][nt][0]), "+f"(c[mt][nt][1]), "+f"(c[mt][nt][2]), "+f"(c[mt][nt][3])
                        : "r"(a[mt][0]), "r"(a[mt][1]), "r"(a[mt][2]), "r"(a[mt][3]),
                          "r"(b[nt][0]), "r"(b[nt][1]));
        }
        __syncthreads();
    }

    // --- epilogue ---
#pragma unroll
    for (int mt = 0; mt < 2; mt++) {
#pragma unroll
        for (int half = 0; half < 2; half++) {
            int gr = row0 + wm * 32 + mt * 16 + (lane >> 2) + half * 8;
            if (gr >= M) continue;
#pragma unroll
            for (int nt = 0; nt < 8; nt++) {
                int lc = wn * 64 + nt * 8 + (lane & 3) * 2;
                float v0 = c[mt][nt][half * 2 + 0] + sbias[lc];
                float v1 = c[mt][nt][half * 2 + 1] + sbias[lc + 1];
                if (BF16OUT) {
                    __nv_bfloat162 h = __floats2bfloat162_rn(v0, v1);
                    *reinterpret_cast<__nv_bfloat162*>(
                        reinterpret_cast<__nv_bfloat16*>(Cout) + (size_t)gr * N + col0 + lc) = h;
                } else {
                    *reinterpret_cast<float2*>(
                        reinterpret_cast<float*>(Cout) + (size_t)gr * N + col0 + lc) = make_float2(v0, v1);
                }
            }
        }
    }
}

// ================= edge kernels =================
__device__ __forceinline__ unsigned fenc(float f) {
    unsigned u = __float_as_uint(f);
    return (u & 0x80000000u) ? ~u : (u | 0x80000000u);
}
__device__ __forceinline__ float fdec(unsigned u) {
    return (u & 0x80000000u) ? __uint_as_float(u ^ 0x80000000u) : __uint_as_float(~u);
}

__global__ void edge_logits(const __nv_bfloat16* __restrict__ fs, const __nv_bfloat16* __restrict__ fd,
                            const int* __restrict__ src, const int* __restrict__ dst,
                            const float* __restrict__ attn, float* __restrict__ logits,
                            unsigned* __restrict__ mmax, int E)
{
    int gw = (blockIdx.x * blockDim.x + threadIdx.x) >> 5;
    int lane = threadIdx.x & 31;
    if (gw >= E) return;
    int s = src[gw], d = dst[gw];
    uint2 ua = __ldg(reinterpret_cast<const uint2*>(fs) + (size_t)s * 32 + lane);
    uint2 ub = __ldg(reinterpret_cast<const uint2*>(fd) + (size_t)d * 32 + lane);
    float4 at = __ldg(reinterpret_cast<const float4*>(attn) + lane);
    float2 a0 = __bfloat1622float2(*reinterpret_cast<__nv_bfloat162*>(&ua.x));
    float2 a1 = __bfloat1622float2(*reinterpret_cast<__nv_bfloat162*>(&ua.y));
    float2 b0 = __bfloat1622float2(*reinterpret_cast<__nv_bfloat162*>(&ub.x));
    float2 b1 = __bfloat1622float2(*reinterpret_cast<__nv_bfloat162*>(&ub.y));
    float vx = a0.x + b0.x, vy = a0.y + b0.y, vz = a1.x + b1.x, vw = a1.y + b1.y;
    vx = vx > 0.f ? vx : 0.2f * vx;
    vy = vy > 0.f ? vy : 0.2f * vy;
    vz = vz > 0.f ? vz : 0.2f * vz;
    vw = vw > 0.f ? vw : 0.2f * vw;
    float p = vx * at.x + vy * at.y + vz * at.z + vw * at.w;
    p += __shfl_down_sync(0xffffffffu, p, 4, 8);
    p += __shfl_down_sync(0xffffffffu, p, 2, 8);
    p += __shfl_down_sync(0xffffffffu, p, 1, 8);
    if ((lane & 7) == 0) {
        int h = lane >> 3;
        logits[gw * 4 + h] = p;
        atomicMax(&mmax[d * 4 + h], fenc(p));
    }
}

__global__ void edge_exp(float* __restrict__ logits, const int* __restrict__ dst,
                         const unsigned* __restrict__ mmax, float* __restrict__ ssum, int E4)
{
    int i = blockIdx.x * blockDim.x + threadIdx.x;
    if (i >= E4) return;
    int e = i >> 2, h = i & 3;
    int d = dst[e];
    float m = fdec(mmax[d * 4 + h]);
    if (!isfinite(m)) m = 0.f;
    float ex = expf(logits[i] - m);
    logits[i] = ex;
    atomicAdd(&ssum[d * 4 + h], ex);
}

__global__ void edge_aggregate(const __nv_bfloat16* __restrict__ fs, const int* __restrict__ src,
                               const int* __restrict__ dst, const float* __restrict__ ex,
                               const float* __restrict__ ssum, float* __restrict__ zout, int E)
{
    int gw = (blockIdx.x * blockDim.x + threadIdx.x) >> 5;
    int lane = threadIdx.x & 31;
    if (gw >= E) return;
    int s = src[gw], d = dst[gw];
    int h = lane >> 3;
    float alpha = ex[gw * 4 + h] / ssum[d * 4 + h];
    uint2 ua = __ldg(reinterpret_cast<const uint2*>(fs) + (size_t)s * 32 + lane);
    float2 a0 = __bfloat1622float2(*reinterpret_cast<__nv_bfloat162*>(&ua.x));
    float2 a1 = __bfloat1622float2(*reinterpret_cast<__nv_bfloat162*>(&ua.y));
    float* p = zout + (size_t)d * 128 + lane * 4;
    asm volatile("red.global.add.v4.f32 [%0], {%1,%2,%3,%4};"
                 :: "l"(p), "f"(a0.x * alpha), "f"(a0.y * alpha), "f"(a1.x * alpha), "f"(a1.y * alpha)
                 : "memory");
}

// ================= semantic attention =================
__global__ void sematt_partial(const float* __restrict__ z, const float* __restrict__ Wa,
                               const float* __restrict__ ba, const float* __restrict__ Wo,
                               float* __restrict__ part)
{
    __shared__ float sz[8][128];
    __shared__ float sacc[8];
    int j = threadIdx.x;
    int r0 = blockIdx.x * 8;
    if (j < 8) sacc[j] = 0.f;
#pragma unroll
    for (int r = 0; r < 8; r++) {
        float v = z[(size_t)(r0 + r) * 128 + j];
        sz[r][j] = v > 0.f ? v : 0.f;
    }
    __syncthreads();
    float bj = ba[j];
    float acc[8];
#pragma unroll
    for (int r = 0; r < 8; r++) acc[r] = bj;
    for (int k = 0; k < 128; k++) {
        float w = Wa[k * 128 + j];
#pragma unroll
        for (int r = 0; r < 8; r++) acc[r] = fmaf(sz[r][k], w, acc[r]);
    }
    float wo = Wo[j];
#pragma unroll
    for (int r = 0; r < 8; r++) {
        float t = tanhf(acc[r]) * wo;
        for (int o = 16; o > 0; o >>= 1) t += __shfl_down_sync(0xffffffffu, t, o);
        if ((j & 31) == 0) atomicAdd(&sacc[r], t);
    }
    __syncthreads();
    if (j == 0) {
        float tot = 0.f;
#pragma unroll
        for (int r = 0; r < 8; r++) tot += sacc[r];
        atomicAdd(part, tot);
    }
}

__global__ void compute_beta()
{
    for (int grp = 0; grp < 2; grp++) {
        float w0 = g_watt[2 * grp] * (1.f / NN);
        float w1 = g_watt[2 * grp + 1] * (1.f / NN);
        float m = fmaxf(w0, w1);
        float e0 = expf(w0 - m), e1 = expf(w1 - m);
        float inv = 1.f / (e0 + e1);
        g_beta[2 * grp] = e0 * inv;
        g_beta[2 * grp + 1] = e1 * inv;
    }
}

__global__ void combine_bf16(const float* __restrict__ z0, const float* __restrict__ z1,
                             __nv_bfloat16* __restrict__ out, int n2, int betaIdx)
{
    int i = blockIdx.x * blockDim.x + threadIdx.x;
    if (i >= n2) return;
    float b0 = g_beta[betaIdx], b1 = g_beta[betaIdx + 1];
    float2 a = reinterpret_cast<const float2*>(z0)[i];
    float2 c = reinterpret_cast<const float2*>(z1)[i];
    float o0 = b0 * fmaxf(a.x, 0.f) + b1 * fmaxf(c.x, 0.f);
    float o1 = b0 * fmaxf(a.y, 0.f) + b1 * fmaxf(c.y, 0.f);
    reinterpret_cast<__nv_bfloat162*>(out)[i] = __floats2bfloat162_rn(o0, o1);
}

// ================= predictor =================
__global__ void predict_kernel(const float* __restrict__ pa, const float* __restrict__ pt,
                               const int* __restrict__ src, const int* __restrict__ dst,
                               const float* __restrict__ b1, const float* __restrict__ W2,
                               const float* __restrict__ b2, float* __restrict__ out, int E)
{
    int gw = (blockIdx.x * blockDim.x + threadIdx.x) >> 5;
    int lane = threadIdx.x & 31;
    if (gw >= E) return;
    int s = src[gw], d = dst[gw];
    float4 a = __ldg(reinterpret_cast<const float4*>(pa) + (size_t)s * 32 + lane);
    float4 b = __ldg(reinterpret_cast<const float4*>(pt) + (size_t)d * 32 + lane);
    float4 bb = __ldg(reinterpret_cast<const float4*>(b1) + lane);
    float4 w = __ldg(reinterpret_cast<const float4*>(W2) + lane);
    float ux = fmaxf(a.x + b.x + bb.x, 0.f);
    float uy = fmaxf(a.y + b.y + bb.y, 0.f);
    float uz = fmaxf(a.z + b.z + bb.z, 0.f);
    float uw = fmaxf(a.w + b.w + bb.w, 0.f);
    float dot = ux * w.x + uy * w.y + uz * w.z + uw * w.w;
    for (int o = 16; o > 0; o >>= 1) dot += __shfl_down_sync(0xffffffffu, dot, o);
    if (lane == 0) out[gw] = 1.f / (1.f + expf(-(dot + b2[0])));
}

// ================= host =================
extern "C" void kernel_launch(void* const* d_in, const int* in_sizes, int n_in,
                              void* d_out, int out_size)
{
    const float* prot   = (const float*)d_in[0];
    const float* gen    = (const float*)d_in[1];
    const float* W1     = (const float*)d_in[2];
    const float* b1     = (const float*)d_in[3];
    const float* W2     = (const float*)d_in[4];
    const float* b2     = (const float*)d_in[5];
    const float* gWs    = (const float*)d_in[6];
    const float* gbs    = (const float*)d_in[7];
    const float* gWd    = (const float*)d_in[8];
    const float* gbd    = (const float*)d_in[9];
    const float* gattn  = (const float*)d_in[10];
    const float* pAW1   = (const float*)d_in[11];
    const float* pAb1   = (const float*)d_in[12];
    const float* pAW2   = (const float*)d_in[13];
    const float* gAW1   = (const float*)d_in[14];
    const float* gAb1   = (const float*)d_in[15];
    const float* gAW2   = (const float*)d_in[16];
    const float* predW1 = (const float*)d_in[17];
    const float* predb1 = (const float*)d_in[18];
    const float* predW2 = (const float*)d_in[19];
    const float* predb2 = (const float*)d_in[20];
    const int* e_aa = (const int*)d_in[21];
    const int* e_ta = (const int*)d_in[22];
    const int* e_tt = (const int*)d_in[23];
    const int* e_at = (const int*)d_in[24];
    const int* pos_e = (const int*)d_in[25];
    const int* neg_e = (const int*)d_in[26];
    float* out = (float*)d_out;

    __nv_bfloat16 *p_hab, *p_htb, *p_fsb, *p_fdb, *p_haoutb, *p_htoutb, *p_wt;
    float *p_z, *p_logits, *p_s, *p_pa, *p_pt, *p_watt;
    unsigned* p_m;
    cudaGetSymbolAddress((void**)&p_hab, g_hab);
    cudaGetSymbolAddress((void**)&p_htb, g_htb);
    cudaGetSymbolAddress((void**)&p_fsb, g_fsb);
    cudaGetSymbolAddress((void**)&p_fdb, g_fdb);
    cudaGetSymbolAddress((void**)&p_haoutb, g_haoutb);
    cudaGetSymbolAddress((void**)&p_htoutb, g_htoutb);
    cudaGetSymbolAddress((void**)&p_wt, g_wt);
    cudaGetSymbolAddress((void**)&p_z, g_z);
    cudaGetSymbolAddress((void**)&p_logits, g_logits);
    cudaGetSymbolAddress((void**)&p_m, g_m);
    cudaGetSymbolAddress((void**)&p_s, g_s);
    cudaGetSymbolAddress((void**)&p_pa, g_pa);
    cudaGetSymbolAddress((void**)&p_pt, g_pt);
    cudaGetSymbolAddress((void**)&p_watt, g_watt);

    cudaMemsetAsync(p_z, 0, sizeof(float) * 4 * NN * HIDF);
    cudaMemsetAsync(p_m, 0, sizeof(unsigned) * 4 * NN * 4);
    cudaMemsetAsync(p_s, 0, sizeof(float) * 4 * NN * 4);
    cudaMemsetAsync(p_watt, 0, sizeof(float) * 4);

    // weight transposes (fp32 [K,N] -> bf16 [N,K])
    transpose_bf16_kernel<<<dim3((1024 * 256 + 255) / 256, 1), 256>>>(W2, p_wt + OFF_W2T, 1024, 256);
    transpose_bf16_kernel<<<dim3((512 * 256 + 255) / 256, 1), 256>>>(W1, p_wt + OFF_W1T, 512, 256);
    transpose_bf16_kernel<<<dim3((256 * 128 + 255) / 256, 4), 256>>>(gWs, p_wt + OFF_GWS, 256, 128);
    transpose_bf16_kernel<<<dim3((256 * 128 + 255) / 256, 4), 256>>>(gWd, p_wt + OFF_GWD, 256, 128);
    transpose_bf16_kernel<<<dim3((256 * 128 + 255) / 256, 1), 256>>>(predW1, p_wt + OFF_PW1, 256, 128);

    const int MR = (NN + 127) / 128;  // 391

    // node projections: A is fp32 (converted in-loader), bf16 out
    gemm_mma<1, 1><<<dim3(2, MR), 256>>>(prot, p_wt + OFF_W2T, b2, p_hab, NN, 256, 1024, 1024);
    gemm_mma<1, 1><<<dim3(2, MR), 256>>>(gen,  p_wt + OFF_W1T, b1, p_htb, NN, 256, 512, 512);

    const int* edges[4] = { e_aa, e_ta, e_tt, e_at };
    for (int g = 0; g < 4; g++) {
        const __nv_bfloat16* Xs = (g == 0 || g == 3) ? p_hab : p_htb;
        const __nv_bfloat16* Xd = (g == 0 || g == 1) ? p_hab : p_htb;
        gemm_mma<0, 1><<<dim3(1, MR), 256>>>(Xs, p_wt + OFF_GWS + (size_t)g * 32768, gbs + g * 128, p_fsb, NN, 128, 256, 256);
        gemm_mma<0, 1><<<dim3(1, MR), 256>>>(Xd, p_wt + OFF_GWD + (size_t)g * 32768, gbd + g * 128, p_fdb, NN, 128, 256, 256);
        const int* src = edges[g];
        const int* dst = edges[g] + EE;
        unsigned* mg = p_m + (size_t)g * NN * 4;
        float* sg = p_s + (size_t)g * NN * 4;
        float* zg = p_z + (size_t)g * NN * HIDF;
        edge_logits<<<(EE * 32 + 255) / 256, 256>>>(p_fsb, p_fdb, src, dst, gattn + g * 128, p_logits, mg, EE);
        edge_exp<<<(EE * 4 + 255) / 256, 256>>>(p_logits, dst, mg, sg, EE * 4);
        edge_aggregate<<<(EE * 32 + 255) / 256, 256>>>(p_fsb, src, dst, p_logits, sg, zg, EE);
    }

    sematt_partial<<<NN / 8, 128>>>(p_z + 0 * (size_t)NN * HIDF, pAW1, pAb1, pAW2, p_watt + 0);
    sematt_partial<<<NN / 8, 128>>>(p_z + 1 * (size_t)NN * HIDF, pAW1, pAb1, pAW2, p_watt + 1);
    sematt_partial<<<NN / 8, 128>>>(p_z + 2 * (size_t)NN * HIDF, gAW1, gAb1, gAW2, p_watt + 2);
    sematt_partial<<<NN / 8, 128>>>(p_z + 3 * (size_t)NN * HIDF, gAW1, gAb1, gAW2, p_watt + 3);
    compute_beta<<<1, 1>>>();

    combine_bf16<<<(NN * HIDF / 2 + 255) / 256, 256>>>(p_z + 0 * (size_t)NN * HIDF, p_z + 1 * (size_t)NN * HIDF, p_haoutb, NN * HIDF / 2, 0);
    combine_bf16<<<(NN * HIDF / 2 + 255) / 256, 256>>>(p_z + 2 * (size_t)NN * HIDF, p_z + 3 * (size_t)NN * HIDF, p_htoutb, NN * HIDF / 2, 2);

    // predictor first layer (factorized concat), fp32 out
    gemm_mma<0, 0><<<dim3(1, MR), 256>>>(p_haoutb, p_wt + OFF_PW1,       nullptr, p_pa, NN, 128, 128, 256);
    gemm_mma<0, 0><<<dim3(1, MR), 256>>>(p_htoutb, p_wt + OFF_PW1 + 128, nullptr, p_pt, NN, 128, 128, 256);

    predict_kernel<<<(EP * 32 + 255) / 256, 256>>>(p_pa, p_pt, pos_e, pos_e + EP, predb1, predW2, predb2, out, EP);
    predict_kernel<<<(EP * 32 + 255) / 256, 256>>>(p_pa, p_pt, neg_e, neg_e + EP, predb1, predW2, predb2, out + EP, EP);
}

// round 4
// speedup vs baseline: 2.0873x; 1.0152x over previous
#include <cuda_runtime.h>
#include <cuda_bf16.h>
#include <math.h>
#include <cstdint>

#define NN 50000
#define EE 800000
#define EP 200000
#define HIDF 128

__device__ __forceinline__ uint32_t smem_u32(const void* p) {
    uint32_t a;
    asm("{ .reg .u64 t; cvta.to.shared.u64 t, %1; cvt.u32.u64 %0, t; }" : "=r"(a) : "l"(p));
    return a;
}
__device__ __forceinline__ void cp_async16(uint32_t s, const void* g, bool pred) {
    int sz = pred ? 16 : 0;
    asm volatile("cp.async.cg.shared.global [%0], [%1], 16, %2;" :: "r"(s), "l"(g), "r"(sz));
}
#define CP_COMMIT() asm volatile("cp.async.commit_group;" ::: "memory")
#define CP_WAIT1()  asm volatile("cp.async.wait_group 1;" ::: "memory")
#define CP_WAIT0()  asm volatile("cp.async.wait_group 0;" ::: "memory")

// ================= scratch =================
__device__ __nv_bfloat16 g_protb[NN * 1024];
__device__ __nv_bfloat16 g_genb[NN * 512];
__device__ __nv_bfloat16 g_hab[NN * 256];
__device__ __nv_bfloat16 g_htb[NN * 256];
__device__ __nv_bfloat16 g_Fa[NN * 512];   // batched GAT outputs on AMP features
__device__ __nv_bfloat16 g_Ft[NN * 512];   // batched GAT outputs on Target features
__device__ float g_z[4 * NN * HIDF];
__device__ float g_logits[EE * 4];
__device__ unsigned g_m[4 * NN * 4];
__device__ float g_s[4 * NN * 4];
__device__ __nv_bfloat16 g_haoutb[NN * 128];
__device__ __nv_bfloat16 g_htoutb[NN * 128];
__device__ float g_pa[NN * 128];
__device__ float g_pt[NN * 128];
__device__ float g_watt[4];
__device__ float g_beta[4];
__device__ __nv_bfloat16 g_wt[688128];
__device__ float g_biascat[1024];   // [0..511] A-side, [512..1023] T-side

#define OFF_W2T 0
#define OFF_W1T 262144
#define OFF_WA  393216
#define OFF_WT  524288
#define OFF_PW1 655360

// ================= converts / transposes =================
__global__ void f32_to_bf16_kernel(const float* __restrict__ in, __nv_bfloat16* __restrict__ out, int n4) {
    int i = blockIdx.x * blockDim.x + threadIdx.x;
    if (i >= n4) return;
    float4 v = __ldg(reinterpret_cast<const float4*>(in) + i);
    __nv_bfloat162 h0 = __floats2bfloat162_rn(v.x, v.y);
    __nv_bfloat162 h1 = __floats2bfloat162_rn(v.z, v.w);
    reinterpret_cast<uint2*>(out)[i] =
        make_uint2(*reinterpret_cast<uint32_t*>(&h0), *reinterpret_cast<uint32_t*>(&h1));
}
__global__ void transpose_bf16_kernel(const float* __restrict__ in, __nv_bfloat16* __restrict__ out,
                                      int K, int N) {
    int idx = blockIdx.x * blockDim.x + threadIdx.x;
    if (idx >= K * N) return;
    int k = idx / N, n = idx % N;
    out[(size_t)n * K + k] = __float2bfloat16(in[idx]);
}
__global__ void concat_bias_kernel(const float* __restrict__ gbs, const float* __restrict__ gbd,
                                   float* __restrict__ outa, float* __restrict__ outt) {
    int i = threadIdx.x;  // 128
    outa[i]       = gbs[0 * 128 + i];
    outa[128 + i] = gbd[0 * 128 + i];
    outa[256 + i] = gbd[1 * 128 + i];
    outa[384 + i] = gbs[3 * 128 + i];
    outt[i]       = gbs[1 * 128 + i];
    outt[128 + i] = gbs[2 * 128 + i];
    outt[256 + i] = gbd[2 * 128 + i];
    outt[384 + i] = gbd[3 * 128 + i];
}

// ================= pipelined HMMA GEMM =================
// C[M,N] = A[M,K](bf16) @ Bt[N,K](bf16, row stride ldb)^T + bias
// 128x128x64 tiles, 256 threads (8 warps: 4m x 2n), cp.async double buffer, XOR swizzle.
#define GSM_BIAS 65536
#define GSM_TOTAL (65536 + 512)

__device__ __forceinline__ void gemm_load_tile(
    uint32_t sb, uint32_t aOff, uint32_t bOff,
    const __nv_bfloat16* __restrict__ A, const __nv_bfloat16* __restrict__ Bt,
    int row0, int col0, int k0, int M, int K, int ldb, int tid)
{
#pragma unroll
    for (int it = 0; it < 4; it++) {
        int idx = it * 256 + tid;
        int r = idx >> 3, cc = idx & 7;
        uint32_t dst = sb + aOff + r * 128 + ((cc ^ (r & 7)) << 4);
        cp_async16(dst, A + (size_t)(row0 + r) * K + k0 + cc * 8, row0 + r < M);
    }
#pragma unroll
    for (int it = 0; it < 4; it++) {
        int idx = it * 256 + tid;
        int r = idx >> 3, cc = idx & 7;
        uint32_t dst = sb + bOff + r * 128 + ((cc ^ (r & 7)) << 4);
        cp_async16(dst, Bt + (size_t)(col0 + r) * ldb + k0 + cc * 8, true);
    }
}

template <int BF16OUT>
__global__ void __launch_bounds__(256) gemm_bf16(
    const __nv_bfloat16* __restrict__ A, const __nv_bfloat16* __restrict__ Bt,
    const float* __restrict__ bias, void* __restrict__ Cout,
    int M, int N, int K, int ldb)
{
    extern __shared__ char smem[];
    uint32_t sb = smem_u32(smem);
    const int tid = threadIdx.x;
    const int wid = tid >> 5, lane = tid & 31;
    const int wm = wid & 3, wn = wid >> 2;
    const int row0 = blockIdx.y * 128, col0 = blockIdx.x * 128;
    float* sbias = reinterpret_cast<float*>(smem + GSM_BIAS);

    if (tid < 128) sbias[tid] = bias ? __ldg(bias + col0 + tid) : 0.f;

    float c[2][8][4];
#pragma unroll
    for (int i = 0; i < 2; i++)
#pragma unroll
        for (int j = 0; j < 8; j++)
#pragma unroll
            for (int q = 0; q < 4; q++) c[i][j][q] = 0.f;

    const int niter = K >> 6;
    gemm_load_tile(sb, 0, 16384, A, Bt, row0, col0, 0, M, K, ldb, tid);
    CP_COMMIT();

    for (int it = 0; it < niter; it++) {
        const uint32_t aOff = (it & 1) * 32768u;
        const uint32_t bOff = aOff + 16384u;
        if (it + 1 < niter) {
            uint32_t a2 = ((it + 1) & 1) * 32768u;
            gemm_load_tile(sb, a2, a2 + 16384u, A, Bt, row0, col0, (it + 1) * 64, M, K, ldb, tid);
            CP_COMMIT();
            CP_WAIT1();
        } else {
            CP_WAIT0();
        }
        __syncthreads();

#pragma unroll
        for (int ks = 0; ks < 4; ks++) {
            uint32_t a[2][4];
#pragma unroll
            for (int mt = 0; mt < 2; mt++) {
                int ar = wm * 32 + mt * 16 + (lane & 15);
                int ch = ks * 2 + (lane >> 4);
                uint32_t addr = sb + aOff + ar * 128 + ((ch ^ (ar & 7)) << 4);
                asm volatile("ldmatrix.sync.aligned.m8n8.x4.shared.b16 {%0,%1,%2,%3}, [%4];"
                             : "=r"(a[mt][0]), "=r"(a[mt][1]), "=r"(a[mt][2]), "=r"(a[mt][3]) : "r"(addr));
            }
            uint32_t b[8][2];
#pragma unroll
            for (int nt = 0; nt < 8; nt++) {
                int br = wn * 64 + nt * 8 + (lane & 7);
                int ch = ks * 2 + ((lane >> 3) & 1);
                uint32_t addr = sb + bOff + br * 128 + ((ch ^ (br & 7)) << 4);
                asm volatile("ldmatrix.sync.aligned.m8n8.x2.shared.b16 {%0,%1}, [%2];"
                             : "=r"(b[nt][0]), "=r"(b[nt][1]) : "r"(addr));
            }
#pragma unroll
            for (int mt = 0; mt < 2; mt++)
#pragma unroll
                for (int nt = 0; nt < 8; nt++)
                    asm volatile(
                        "mma.sync.aligned.m16n8k16.row.col.f32.bf16.bf16.f32 "
                        "{%0,%1,%2,%3}, {%4,%5,%6,%7}, {%8,%9}, {%0,%1,%2,%3};"
                        : "+f"(c[mt][nt][0]), "+f"(c[mt][nt][1]), "+f"(c[mt][nt][2]), "+f"(c[mt][nt][3])
                        : "r"(a[mt][0]), "r"(a[mt][1]), "r"(a[mt][2]), "r"(a[mt][3]),
                          "r"(b[nt][0]), "r"(b[nt][1]));
        }
        __syncthreads();
    }

#pragma unroll
    for (int mt = 0; mt < 2; mt++) {
#pragma unroll
        for (int half = 0; half < 2; half++) {
            int gr = row0 + wm * 32 + mt * 16 + (lane >> 2) + half * 8;
            if (gr >= M) continue;
#pragma unroll
            for (int nt = 0; nt < 8; nt++) {
                int lc = wn * 64 + nt * 8 + (lane & 3) * 2;
                float v0 = c[mt][nt][half * 2 + 0] + sbias[lc];
                float v1 = c[mt][nt][half * 2 + 1] + sbias[lc + 1];
                if (BF16OUT) {
                    __nv_bfloat162 h = __floats2bfloat162_rn(v0, v1);
                    *reinterpret_cast<__nv_bfloat162*>(
                        reinterpret_cast<__nv_bfloat16*>(Cout) + (size_t)gr * N + col0 + lc) = h;
                } else {
                    *reinterpret_cast<float2*>(
                        reinterpret_cast<float*>(Cout) + (size_t)gr * N + col0 + lc) = make_float2(v0, v1);
                }
            }
        }
    }
}

// ================= edge kernels =================
__device__ __forceinline__ unsigned fenc(float f) {
    unsigned u = __float_as_uint(f);
    return (u & 0x80000000u) ? ~u : (u | 0x80000000u);
}
__device__ __forceinline__ float fdec(unsigned u) {
    return (u & 0x80000000u) ? __uint_as_float(u ^ 0x80000000u) : __uint_as_float(~u);
}

// strideU2: row stride of fs/fd in uint2 units (512 halves -> 128 uint2? no: 512*2B/8B = 128)
__global__ void edge_logits(const __nv_bfloat16* __restrict__ fs, const __nv_bfloat16* __restrict__ fd,
                            int strideU2,
                            const int* __restrict__ src, const int* __restrict__ dst,
                            const float* __restrict__ attn, float* __restrict__ logits,
                            unsigned* __restrict__ mmax, int E)
{
    int gw = (blockIdx.x * blockDim.x + threadIdx.x) >> 5;
    int lane = threadIdx.x & 31;
    if (gw >= E) return;
    int s = src[gw], d = dst[gw];
    uint2 ua = __ldg(reinterpret_cast<const uint2*>(fs) + (size_t)s * strideU2 + lane);
    uint2 ub = __ldg(reinterpret_cast<const uint2*>(fd) + (size_t)d * strideU2 + lane);
    float4 at = __ldg(reinterpret_cast<const float4*>(attn) + lane);
    float2 a0 = __bfloat1622float2(*reinterpret_cast<__nv_bfloat162*>(&ua.x));
    float2 a1 = __bfloat1622float2(*reinterpret_cast<__nv_bfloat162*>(&ua.y));
    float2 b0 = __bfloat1622float2(*reinterpret_cast<__nv_bfloat162*>(&ub.x));
    float2 b1 = __bfloat1622float2(*reinterpret_cast<__nv_bfloat162*>(&ub.y));
    float vx = a0.x + b0.x, vy = a0.y + b0.y, vz = a1.x + b1.x, vw = a1.y + b1.y;
    vx = vx > 0.f ? vx : 0.2f * vx;
    vy = vy > 0.f ? vy : 0.2f * vy;
    vz = vz > 0.f ? vz : 0.2f * vz;
    vw = vw > 0.f ? vw : 0.2f * vw;
    float p = vx * at.x + vy * at.y + vz * at.z + vw * at.w;
    p += __shfl_down_sync(0xffffffffu, p, 4, 8);
    p += __shfl_down_sync(0xffffffffu, p, 2, 8);
    p += __shfl_down_sync(0xffffffffu, p, 1, 8);
    if ((lane & 7) == 0) {
        int h = lane >> 3;
        logits[gw * 4 + h] = p;
        atomicMax(&mmax[d * 4 + h], fenc(p));
    }
}

__global__ void edge_exp(float* __restrict__ logits, const int* __restrict__ dst,
                         const unsigned* __restrict__ mmax, float* __restrict__ ssum, int E4)
{
    int i = blockIdx.x * blockDim.x + threadIdx.x;
    if (i >= E4) return;
    int e = i >> 2, h = i & 3;
    int d = dst[e];
    float m = fdec(mmax[d * 4 + h]);
    if (!isfinite(m)) m = 0.f;
    float ex = expf(logits[i] - m);
    logits[i] = ex;
    atomicAdd(&ssum[d * 4 + h], ex);
}

__global__ void edge_aggregate(const __nv_bfloat16* __restrict__ fs, int strideU2,
                               const int* __restrict__ src, const int* __restrict__ dst,
                               const float* __restrict__ ex, const float* __restrict__ ssum,
                               float* __restrict__ zout, int E)
{
    int gw = (blockIdx.x * blockDim.x + threadIdx.x) >> 5;
    int lane = threadIdx.x & 31;
    if (gw >= E) return;
    int s = src[gw], d = dst[gw];
    int h = lane >> 3;
    float alpha = ex[gw * 4 + h] / ssum[d * 4 + h];
    uint2 ua = __ldg(reinterpret_cast<const uint2*>(fs) + (size_t)s * strideU2 + lane);
    float2 a0 = __bfloat1622float2(*reinterpret_cast<__nv_bfloat162*>(&ua.x));
    float2 a1 = __bfloat1622float2(*reinterpret_cast<__nv_bfloat162*>(&ua.y));
    float* p = zout + (size_t)d * 128 + lane * 4;
    asm volatile("red.global.add.v4.f32 [%0], {%1,%2,%3,%4};"
                 :: "l"(p), "f"(a0.x * alpha), "f"(a0.y * alpha), "f"(a1.x * alpha), "f"(a1.y * alpha)
                 : "memory");
}

// ================= semantic attention =================
__global__ void sematt_partial(const float* __restrict__ z, const float* __restrict__ Wa,
                               const float* __restrict__ ba, const float* __restrict__ Wo,
                               float* __restrict__ part)
{
    __shared__ float sz[8][128];
    __shared__ float sacc[8];
    int j = threadIdx.x;
    int r0 = blockIdx.x * 8;
    if (j < 8) sacc[j] = 0.f;
#pragma unroll
    for (int r = 0; r < 8; r++) {
        float v = z[(size_t)(r0 + r) * 128 + j];
        sz[r][j] = v > 0.f ? v : 0.f;
    }
    __syncthreads();
    float bj = ba[j];
    float acc[8];
#pragma unroll
    for (int r = 0; r < 8; r++) acc[r] = bj;
    for (int k = 0; k < 128; k++) {
        float w = Wa[k * 128 + j];
#pragma unroll
        for (int r = 0; r < 8; r++) acc[r] = fmaf(sz[r][k], w, acc[r]);
    }
    float wo = Wo[j];
#pragma unroll
    for (int r = 0; r < 8; r++) {
        float t = tanhf(acc[r]) * wo;
        for (int o = 16; o > 0; o >>= 1) t += __shfl_down_sync(0xffffffffu, t, o);
        if ((j & 31) == 0) atomicAdd(&sacc[r], t);
    }
    __syncthreads();
    if (j == 0) {
        float tot = 0.f;
#pragma unroll
        for (int r = 0; r < 8; r++) tot += sacc[r];
        atomicAdd(part, tot);
    }
}

__global__ void compute_beta()
{
    for (int grp = 0; grp < 2; grp++) {
        float w0 = g_watt[2 * grp] * (1.f / NN);
        float w1 = g_watt[2 * grp + 1] * (1.f / NN);
        float m = fmaxf(w0, w1);
        float e0 = expf(w0 - m), e1 = expf(w1 - m);
        float inv = 1.f / (e0 + e1);
        g_beta[2 * grp] = e0 * inv;
        g_beta[2 * grp + 1] = e1 * inv;
    }
}

__global__ void combine_bf16(const float* __restrict__ z0, const float* __restrict__ z1,
                             __nv_bfloat16* __restrict__ out, int n2, int betaIdx)
{
    int i = blockIdx.x * blockDim.x + threadIdx.x;
    if (i >= n2) return;
    float b0 = g_beta[betaIdx], b1 = g_beta[betaIdx + 1];
    float2 a = reinterpret_cast<const float2*>(z0)[i];
    float2 c = reinterpret_cast<const float2*>(z1)[i];
    float o0 = b0 * fmaxf(a.x, 0.f) + b1 * fmaxf(c.x, 0.f);
    float o1 = b0 * fmaxf(a.y, 0.f) + b1 * fmaxf(c.y, 0.f);
    reinterpret_cast<__nv_bfloat162*>(out)[i] = __floats2bfloat162_rn(o0, o1);
}

// ================= predictor =================
__global__ void predict_kernel(const float* __restrict__ pa, const float* __restrict__ pt,
                               const int* __restrict__ src, const int* __restrict__ dst,
                               const float* __restrict__ b1, const float* __restrict__ W2,
                               const float* __restrict__ b2, float* __restrict__ out, int E)
{
    int gw = (blockIdx.x * blockDim.x + threadIdx.x) >> 5;
    int lane = threadIdx.x & 31;
    if (gw >= E) return;
    int s = src[gw], d = dst[gw];
    float4 a = __ldg(reinterpret_cast<const float4*>(pa) + (size_t)s * 32 + lane);
    float4 b = __ldg(reinterpret_cast<const float4*>(pt) + (size_t)d * 32 + lane);
    float4 bb = __ldg(reinterpret_cast<const float4*>(b1) + lane);
    float4 w = __ldg(reinterpret_cast<const float4*>(W2) + lane);
    float ux = fmaxf(a.x + b.x + bb.x, 0.f);
    float uy = fmaxf(a.y + b.y + bb.y, 0.f);
    float uz = fmaxf(a.z + b.z + bb.z, 0.f);
    float uw = fmaxf(a.w + b.w + bb.w, 0.f);
    float dot = ux * w.x + uy * w.y + uz * w.z + uw * w.w;
    for (int o = 16; o > 0; o >>= 1) dot += __shfl_down_sync(0xffffffffu, dot, o);
    if (lane == 0) out[gw] = 1.f / (1.f + expf(-(dot + b2[0])));
}

// ================= host =================
extern "C" void kernel_launch(void* const* d_in, const int* in_sizes, int n_in,
                              void* d_out, int out_size)
{
    const float* prot   = (const float*)d_in[0];
    const float* gen    = (const float*)d_in[1];
    const float* W1     = (const float*)d_in[2];
    const float* b1     = (const float*)d_in[3];
    const float* W2     = (const float*)d_in[4];
    const float* b2     = (const float*)d_in[5];
    const float* gWs    = (const float*)d_in[6];
    const float* gbs    = (const float*)d_in[7];
    const float* gWd    = (const float*)d_in[8];
    const float* gbd    = (const float*)d_in[9];
    const float* gattn  = (const float*)d_in[10];
    const float* pAW1   = (const float*)d_in[11];
    const float* pAb1   = (const float*)d_in[12];
    const float* pAW2   = (const float*)d_in[13];
    const float* gAW1   = (const float*)d_in[14];
    const float* gAb1   = (const float*)d_in[15];
    const float* gAW2   = (const float*)d_in[16];
    const float* predW1 = (const float*)d_in[17];
    const float* predb1 = (const float*)d_in[18];
    const float* predW2 = (const float*)d_in[19];
    const float* predb2 = (const float*)d_in[20];
    const int* e_aa = (const int*)d_in[21];
    const int* e_ta = (const int*)d_in[22];
    const int* e_tt = (const int*)d_in[23];
    const int* e_at = (const int*)d_in[24];
    const int* pos_e = (const int*)d_in[25];
    const int* neg_e = (const int*)d_in[26];
    float* out = (float*)d_out;

    __nv_bfloat16 *p_protb, *p_genb, *p_hab, *p_htb, *p_Fa, *p_Ft, *p_haoutb, *p_htoutb, *p_wt;
    float *p_z, *p_logits, *p_s, *p_pa, *p_pt, *p_watt, *p_biascat;
    unsigned* p_m;
    cudaGetSymbolAddress((void**)&p_protb, g_protb);
    cudaGetSymbolAddress((void**)&p_genb, g_genb);
    cudaGetSymbolAddress((void**)&p_hab, g_hab);
    cudaGetSymbolAddress((void**)&p_htb, g_htb);
    cudaGetSymbolAddress((void**)&p_Fa, g_Fa);
    cudaGetSymbolAddress((void**)&p_Ft, g_Ft);
    cudaGetSymbolAddress((void**)&p_haoutb, g_haoutb);
    cudaGetSymbolAddress((void**)&p_htoutb, g_htoutb);
    cudaGetSymbolAddress((void**)&p_wt, g_wt);
    cudaGetSymbolAddress((void**)&p_z, g_z);
    cudaGetSymbolAddress((void**)&p_logits, g_logits);
    cudaGetSymbolAddress((void**)&p_m, g_m);
    cudaGetSymbolAddress((void**)&p_s, g_s);
    cudaGetSymbolAddress((void**)&p_pa, g_pa);
    cudaGetSymbolAddress((void**)&p_pt, g_pt);
    cudaGetSymbolAddress((void**)&p_watt, g_watt);
    cudaGetSymbolAddress((void**)&p_biascat, g_biascat);

    cudaFuncSetAttribute(gemm_bf16<1>, cudaFuncAttributeMaxDynamicSharedMemorySize, GSM_TOTAL);
    cudaFuncSetAttribute(gemm_bf16<0>, cudaFuncAttributeMaxDynamicSharedMemorySize, GSM_TOTAL);

    cudaMemsetAsync(p_z, 0, sizeof(float) * 4 * NN * HIDF);
    cudaMemsetAsync(p_m, 0, sizeof(unsigned) * 4 * NN * 4);
    cudaMemsetAsync(p_s, 0, sizeof(float) * 4 * NN * 4);
    cudaMemsetAsync(p_watt, 0, sizeof(float) * 4);

    // converts
    f32_to_bf16_kernel<<<(NN * 1024 / 4 + 255) / 256, 256>>>(prot, p_protb, NN * 1024 / 4);
    f32_to_bf16_kernel<<<(NN * 512 / 4 + 255) / 256, 256>>>(gen, p_genb, NN * 512 / 4);

    // weight transposes
    transpose_bf16_kernel<<<(1024 * 256 + 255) / 256, 256>>>(W2, p_wt + OFF_W2T, 1024, 256);
    transpose_bf16_kernel<<<(512 * 256 + 255) / 256, 256>>>(W1, p_wt + OFF_W1T, 512, 256);
    // batched GAT weight slots: A-side [Ws0, Wd0, Wd1, Ws3], T-side [Ws1, Ws2, Wd2, Wd3]
    const int WSZ = 256 * 128;
    transpose_bf16_kernel<<<(WSZ + 255) / 256, 256>>>(gWs + 0 * WSZ, p_wt + OFF_WA + 0 * WSZ, 256, 128);
    transpose_bf16_kernel<<<(WSZ + 255) / 256, 256>>>(gWd + 0 * WSZ, p_wt + OFF_WA + 1 * WSZ, 256, 128);
    transpose_bf16_kernel<<<(WSZ + 255) / 256, 256>>>(gWd + 1 * WSZ, p_wt + OFF_WA + 2 * WSZ, 256, 128);
    transpose_bf16_kernel<<<(WSZ + 255) / 256, 256>>>(gWs + 3 * WSZ, p_wt + OFF_WA + 3 * WSZ, 256, 128);
    transpose_bf16_kernel<<<(WSZ + 255) / 256, 256>>>(gWs + 1 * WSZ, p_wt + OFF_WT + 0 * WSZ, 256, 128);
    transpose_bf16_kernel<<<(WSZ + 255) / 256, 256>>>(gWs + 2 * WSZ, p_wt + OFF_WT + 1 * WSZ, 256, 128);
    transpose_bf16_kernel<<<(WSZ + 255) / 256, 256>>>(gWd + 2 * WSZ, p_wt + OFF_WT + 2 * WSZ, 256, 128);
    transpose_bf16_kernel<<<(WSZ + 255) / 256, 256>>>(gWd + 3 * WSZ, p_wt + OFF_WT + 3 * WSZ, 256, 128);
    transpose_bf16_kernel<<<(256 * 128 + 255) / 256, 256>>>(predW1, p_wt + OFF_PW1, 256, 128);
    concat_bias_kernel<<<1, 128>>>(gbs, gbd, p_biascat, p_biascat + 512);

    const int MR = (NN + 127) / 128;  // 391

    // node projections
    gemm_bf16<1><<<dim3(2, MR), 256, GSM_TOTAL>>>(p_protb, p_wt + OFF_W2T, b2, p_hab, NN, 256, 1024, 1024);
    gemm_bf16<1><<<dim3(2, MR), 256, GSM_TOTAL>>>(p_genb,  p_wt + OFF_W1T, b1, p_htb, NN, 256, 512, 512);

    // batched GAT projections: Fa = hab @ [Ws0 Wd0 Wd1 Ws3], Ft = htb @ [Ws1 Ws2 Wd2 Wd3]
    gemm_bf16<1><<<dim3(4, MR), 256, GSM_TOTAL>>>(p_hab, p_wt + OFF_WA, p_biascat,       p_Fa, NN, 512, 256, 256);
    gemm_bf16<1><<<dim3(4, MR), 256, GSM_TOTAL>>>(p_htb, p_wt + OFF_WT, p_biascat + 512, p_Ft, NN, 512, 256, 256);

    // per-graph fs/fd slices (halves offsets, stride 512 halves = 128 uint2)
    const __nv_bfloat16* FS[4] = { p_Fa + 0,   p_Ft + 0,   p_Ft + 128, p_Fa + 384 };
    const __nv_bfloat16* FD[4] = { p_Fa + 128, p_Fa + 256, p_Ft + 256, p_Ft + 384 };
    const int* edges[4] = { e_aa, e_ta, e_tt, e_at };
    for (int g = 0; g < 4; g++) {
        const int* src = edges[g];
        const int* dst = edges[g] + EE;
        unsigned* mg = p_m + (size_t)g * NN * 4;
        float* sg = p_s + (size_t)g * NN * 4;
        float* zg = p_z + (size_t)g * NN * HIDF;
        edge_logits<<<(EE * 32 + 255) / 256, 256>>>(FS[g], FD[g], 128, src, dst, gattn + g * 128, p_logits, mg, EE);
        edge_exp<<<(EE * 4 + 255) / 256, 256>>>(p_logits, dst, mg, sg, EE * 4);
        edge_aggregate<<<(EE * 32 + 255) / 256, 256>>>(FS[g], 128, src, dst, p_logits, sg, zg, EE);
    }

    sematt_partial<<<NN / 8, 128>>>(p_z + 0 * (size_t)NN * HIDF, pAW1, pAb1, pAW2, p_watt + 0);
    sematt_partial<<<NN / 8, 128>>>(p_z + 1 * (size_t)NN * HIDF, pAW1, pAb1, pAW2, p_watt + 1);
    sematt_partial<<<NN / 8, 128>>>(p_z + 2 * (size_t)NN * HIDF, gAW1, gAb1, gAW2, p_watt + 2);
    sematt_partial<<<NN / 8, 128>>>(p_z + 3 * (size_t)NN * HIDF, gAW1, gAb1, gAW2, p_watt + 3);
    compute_beta<<<1, 1>>>();

    combine_bf16<<<(NN * HIDF / 2 + 255) / 256, 256>>>(p_z + 0 * (size_t)NN * HIDF, p_z + 1 * (size_t)NN * HIDF, p_haoutb, NN * HIDF / 2, 0);
    combine_bf16<<<(NN * HIDF / 2 + 255) / 256, 256>>>(p_z + 2 * (size_t)NN * HIDF, p_z + 3 * (size_t)NN * HIDF, p_htoutb, NN * HIDF / 2, 2);

    gemm_bf16<0><<<dim3(1, MR), 256, GSM_TOTAL>>>(p_haoutb, p_wt + OFF_PW1,       nullptr, p_pa, NN, 128, 128, 256);
    gemm_bf16<0><<<dim3(1, MR), 256, GSM_TOTAL>>>(p_htoutb, p_wt + OFF_PW1 + 128, nullptr, p_pt, NN, 128, 128, 256);

    predict_kernel<<<(EP * 32 + 255) / 256, 256>>>(p_pa, p_pt, pos_e, pos_e + EP, predb1, predW2, predb2, out, EP);
    predict_kernel<<<(EP * 32 + 255) / 256, 256>>>(p_pa, p_pt, neg_e, neg_e + EP, predb1, predW2, predb2, out + EP, EP);
}

// round 5
// speedup vs baseline: 2.1695x; 1.0394x over previous
#include <cuda_runtime.h>
#include <cuda_bf16.h>
#include <math.h>
#include <cstdint>

#define NN 50000
#define EE 800000
#define EP 200000
#define HIDF 128

__device__ __forceinline__ uint32_t smem_u32(const void* p) {
    uint32_t a;
    asm("{ .reg .u64 t; cvta.to.shared.u64 t, %1; cvt.u32.u64 %0, t; }" : "=r"(a) : "l"(p));
    return a;
}
__device__ __forceinline__ void cp_async16(uint32_t s, const void* g, bool pred) {
    int sz = pred ? 16 : 0;
    asm volatile("cp.async.cg.shared.global [%0], [%1], 16, %2;" :: "r"(s), "l"(g), "r"(sz));
}
#define CP_COMMIT() asm volatile("cp.async.commit_group;" ::: "memory")
#define CP_WAIT1()  asm volatile("cp.async.wait_group 1;" ::: "memory")
#define CP_WAIT0()  asm volatile("cp.async.wait_group 0;" ::: "memory")
__device__ __forceinline__ float fast_tanh(float x) {
    float y;
    asm("tanh.approx.f32 %0, %1;" : "=f"(y) : "f"(x));
    return y;
}

// ================= scratch =================
__device__ __nv_bfloat16 g_protb[NN * 1024];
__device__ __nv_bfloat16 g_genb[NN * 512];
__device__ __nv_bfloat16 g_hab[NN * 256];
__device__ __nv_bfloat16 g_htb[NN * 256];
__device__ __nv_bfloat16 g_Fa[NN * 512];
__device__ __nv_bfloat16 g_Ft[NN * 512];
__device__ float g_z[4 * NN * HIDF];
__device__ float g_ex[EE * 4];
__device__ float g_s[4 * NN * 4];
__device__ __nv_bfloat16 g_haoutb[NN * 128];
__device__ __nv_bfloat16 g_htoutb[NN * 128];
__device__ float g_pa[NN * 128];
__device__ float g_pt[NN * 128];
__device__ float g_watt[4];
__device__ float g_beta[4];
__device__ __nv_bfloat16 g_wt[688128];
__device__ float g_biascat[1024];

#define OFF_W2T 0
#define OFF_W1T 262144
#define OFF_WA  393216
#define OFF_WT  524288
#define OFF_PW1 655360

// ================= converts / transposes =================
__global__ void f32_to_bf16_kernel(const float* __restrict__ in, __nv_bfloat16* __restrict__ out, int n4) {
    int i = blockIdx.x * blockDim.x + threadIdx.x;
    if (i >= n4) return;
    float4 v = __ldg(reinterpret_cast<const float4*>(in) + i);
    __nv_bfloat162 h0 = __floats2bfloat162_rn(v.x, v.y);
    __nv_bfloat162 h1 = __floats2bfloat162_rn(v.z, v.w);
    reinterpret_cast<uint2*>(out)[i] =
        make_uint2(*reinterpret_cast<uint32_t*>(&h0), *reinterpret_cast<uint32_t*>(&h1));
}
__global__ void transpose_bf16_kernel(const float* __restrict__ in, __nv_bfloat16* __restrict__ out,
                                      int K, int N) {
    int idx = blockIdx.x * blockDim.x + threadIdx.x;
    if (idx >= K * N) return;
    int k = idx / N, n = idx % N;
    out[(size_t)n * K + k] = __float2bfloat16(in[idx]);
}
__global__ void concat_bias_kernel(const float* __restrict__ gbs, const float* __restrict__ gbd,
                                   float* __restrict__ outa, float* __restrict__ outt) {
    int i = threadIdx.x;  // 128
    outa[i]       = gbs[0 * 128 + i];
    outa[128 + i] = gbd[0 * 128 + i];
    outa[256 + i] = gbd[1 * 128 + i];
    outa[384 + i] = gbs[3 * 128 + i];
    outt[i]       = gbs[1 * 128 + i];
    outt[128 + i] = gbs[2 * 128 + i];
    outt[256 + i] = gbd[2 * 128 + i];
    outt[384 + i] = gbd[3 * 128 + i];
}

// ================= pipelined HMMA GEMM =================
#define GSM_BIAS 65536
#define GSM_TOTAL (65536 + 512)

__device__ __forceinline__ void gemm_load_tile(
    uint32_t sb, uint32_t aOff, uint32_t bOff,
    const __nv_bfloat16* __restrict__ A, const __nv_bfloat16* __restrict__ Bt,
    int row0, int col0, int k0, int M, int K, int ldb, int tid)
{
#pragma unroll
    for (int it = 0; it < 4; it++) {
        int idx = it * 256 + tid;
        int r = idx >> 3, cc = idx & 7;
        uint32_t dst = sb + aOff + r * 128 + ((cc ^ (r & 7)) << 4);
        cp_async16(dst, A + (size_t)(row0 + r) * K + k0 + cc * 8, row0 + r < M);
    }
#pragma unroll
    for (int it = 0; it < 4; it++) {
        int idx = it * 256 + tid;
        int r = idx >> 3, cc = idx & 7;
        uint32_t dst = sb + bOff + r * 128 + ((cc ^ (r & 7)) << 4);
        cp_async16(dst, Bt + (size_t)(col0 + r) * ldb + k0 + cc * 8, true);
    }
}

template <int BF16OUT>
__global__ void __launch_bounds__(256) gemm_bf16(
    const __nv_bfloat16* __restrict__ A, const __nv_bfloat16* __restrict__ Bt,
    const float* __restrict__ bias, void* __restrict__ Cout,
    int M, int N, int K, int ldb)
{
    extern __shared__ char smem[];
    uint32_t sb = smem_u32(smem);
    const int tid = threadIdx.x;
    const int wid = tid >> 5, lane = tid & 31;
    const int wm = wid & 3, wn = wid >> 2;
    const int row0 = blockIdx.y * 128, col0 = blockIdx.x * 128;
    float* sbias = reinterpret_cast<float*>(smem + GSM_BIAS);

    if (tid < 128) sbias[tid] = bias ? __ldg(bias + col0 + tid) : 0.f;

    float c[2][8][4];
#pragma unroll
    for (int i = 0; i < 2; i++)
#pragma unroll
        for (int j = 0; j < 8; j++)
#pragma unroll
            for (int q = 0; q < 4; q++) c[i][j][q] = 0.f;

    const int niter = K >> 6;
    gemm_load_tile(sb, 0, 16384, A, Bt, row0, col0, 0, M, K, ldb, tid);
    CP_COMMIT();

    for (int it = 0; it < niter; it++) {
        const uint32_t aOff = (it & 1) * 32768u;
        const uint32_t bOff = aOff + 16384u;
        if (it + 1 < niter) {
            uint32_t a2 = ((it + 1) & 1) * 32768u;
            gemm_load_tile(sb, a2, a2 + 16384u, A, Bt, row0, col0, (it + 1) * 64, M, K, ldb, tid);
            CP_COMMIT();
            CP_WAIT1();
        } else {
            CP_WAIT0();
        }
        __syncthreads();

#pragma unroll
        for (int ks = 0; ks < 4; ks++) {
            uint32_t a[2][4];
#pragma unroll
            for (int mt = 0; mt < 2; mt++) {
                int ar = wm * 32 + mt * 16 + (lane & 15);
                int ch = ks * 2 + (lane >> 4);
                uint32_t addr = sb + aOff + ar * 128 + ((ch ^ (ar & 7)) << 4);
                asm volatile("ldmatrix.sync.aligned.m8n8.x4.shared.b16 {%0,%1,%2,%3}, [%4];"
                             : "=r"(a[mt][0]), "=r"(a[mt][1]), "=r"(a[mt][2]), "=r"(a[mt][3]) : "r"(addr));
            }
            uint32_t b[8][2];
#pragma unroll
            for (int nt = 0; nt < 8; nt++) {
                int br = wn * 64 + nt * 8 + (lane & 7);
                int ch = ks * 2 + ((lane >> 3) & 1);
                uint32_t addr = sb + bOff + br * 128 + ((ch ^ (br & 7)) << 4);
                asm volatile("ldmatrix.sync.aligned.m8n8.x2.shared.b16 {%0,%1}, [%2];"
                             : "=r"(b[nt][0]), "=r"(b[nt][1]) : "r"(addr));
            }
#pragma unroll
            for (int mt = 0; mt < 2; mt++)
#pragma unroll
                for (int nt = 0; nt < 8; nt++)
                    asm volatile(
                        "mma.sync.aligned.m16n8k16.row.col.f32.bf16.bf16.f32 "
                        "{%0,%1,%2,%3}, {%4,%5,%6,%7}, {%8,%9}, {%0,%1,%2,%3};"
                        : "+f"(c[mt][nt][0]), "+f"(c[mt][nt][1]), "+f"(c[mt][nt][2]), "+f"(c[mt][nt][3])
                        : "r"(a[mt][0]), "r"(a[mt][1]), "r"(a[mt][2]), "r"(a[mt][3]),
                          "r"(b[nt][0]), "r"(b[nt][1]));
        }
        __syncthreads();
    }

#pragma unroll
    for (int mt = 0; mt < 2; mt++) {
#pragma unroll
        for (int half = 0; half < 2; half++) {
            int gr = row0 + wm * 32 + mt * 16 + (lane >> 2) + half * 8;
            if (gr >= M) continue;
#pragma unroll
            for (int nt = 0; nt < 8; nt++) {
                int lc = wn * 64 + nt * 8 + (lane & 3) * 2;
                float v0 = c[mt][nt][half * 2 + 0] + sbias[lc];
                float v1 = c[mt][nt][half * 2 + 1] + sbias[lc + 1];
                if (BF16OUT) {
                    __nv_bfloat162 h = __floats2bfloat162_rn(v0, v1);
                    *reinterpret_cast<__nv_bfloat162*>(
                        reinterpret_cast<__nv_bfloat16*>(Cout) + (size_t)gr * N + col0 + lc) = h;
                } else {
                    *reinterpret_cast<float2*>(
                        reinterpret_cast<float*>(Cout) + (size_t)gr * N + col0 + lc) = make_float2(v0, v1);
                }
            }
        }
    }
}

// ================= edge kernels =================
// Fused pass A: per-edge logits -> ex = exp(logit) -> segment sum.
// (No max-subtraction: logits are O(1) by construction, softmax is shift-invariant.)
__global__ void edge_logits_exp(const __nv_bfloat16* __restrict__ fs, const __nv_bfloat16* __restrict__ fd,
                                int strideU2,
                                const int* __restrict__ src, const int* __restrict__ dst,
                                const float* __restrict__ attn, float* __restrict__ exbuf,
                                float* __restrict__ ssum, int E)
{
    int gw = (blockIdx.x * blockDim.x + threadIdx.x) >> 5;
    int lane = threadIdx.x & 31;
    if (gw >= E) return;
    int s = src[gw], d = dst[gw];
    uint2 ua = __ldg(reinterpret_cast<const uint2*>(fs) + (size_t)s * strideU2 + lane);
    uint2 ub = __ldg(reinterpret_cast<const uint2*>(fd) + (size_t)d * strideU2 + lane);
    float4 at = __ldg(reinterpret_cast<const float4*>(attn) + lane);
    float2 a0 = __bfloat1622float2(*reinterpret_cast<__nv_bfloat162*>(&ua.x));
    float2 a1 = __bfloat1622float2(*reinterpret_cast<__nv_bfloat162*>(&ua.y));
    float2 b0 = __bfloat1622float2(*reinterpret_cast<__nv_bfloat162*>(&ub.x));
    float2 b1 = __bfloat1622float2(*reinterpret_cast<__nv_bfloat162*>(&ub.y));
    float vx = a0.x + b0.x, vy = a0.y + b0.y, vz = a1.x + b1.x, vw = a1.y + b1.y;
    vx = vx > 0.f ? vx : 0.2f * vx;
    vy = vy > 0.f ? vy : 0.2f * vy;
    vz = vz > 0.f ? vz : 0.2f * vz;
    vw = vw > 0.f ? vw : 0.2f * vw;
    float p = vx * at.x + vy * at.y + vz * at.z + vw * at.w;
    p += __shfl_down_sync(0xffffffffu, p, 4, 8);
    p += __shfl_down_sync(0xffffffffu, p, 2, 8);
    p += __shfl_down_sync(0xffffffffu, p, 1, 8);
    if ((lane & 7) == 0) {
        int h = lane >> 3;
        float ex = __expf(p);
        exbuf[gw * 4 + h] = ex;
        atomicAdd(&ssum[d * 4 + h], ex);
    }
}

__global__ void edge_aggregate(const __nv_bfloat16* __restrict__ fs, int strideU2,
                               const int* __restrict__ src, const int* __restrict__ dst,
                               const float* __restrict__ ex, const float* __restrict__ ssum,
                               float* __restrict__ zout, int E)
{
    int gw = (blockIdx.x * blockDim.x + threadIdx.x) >> 5;
    int lane = threadIdx.x & 31;
    if (gw >= E) return;
    int s = src[gw], d = dst[gw];
    int h = lane >> 3;
    float alpha = ex[gw * 4 + h] / ssum[d * 4 + h];
    uint2 ua = __ldg(reinterpret_cast<const uint2*>(fs) + (size_t)s * strideU2 + lane);
    float2 a0 = __bfloat1622float2(*reinterpret_cast<__nv_bfloat162*>(&ua.x));
    float2 a1 = __bfloat1622float2(*reinterpret_cast<__nv_bfloat162*>(&ua.y));
    float* p = zout + (size_t)d * 128 + lane * 4;
    asm volatile("red.global.add.v4.f32 [%0], {%1,%2,%3,%4};"
                 :: "l"(p), "f"(a0.x * alpha), "f"(a0.y * alpha), "f"(a1.x * alpha), "f"(a1.y * alpha)
                 : "memory");
}

// ================= semantic attention =================
__global__ void sematt_partial(const float* __restrict__ z, const float* __restrict__ Wa,
                               const float* __restrict__ ba, const float* __restrict__ Wo,
                               float* __restrict__ part)
{
    __shared__ float sz[8][128];
    __shared__ float sacc[8];
    int j = threadIdx.x;
    int r0 = blockIdx.x * 8;
    if (j < 8) sacc[j] = 0.f;
#pragma unroll
    for (int r = 0; r < 8; r++) {
        float v = z[(size_t)(r0 + r) * 128 + j];
        sz[r][j] = v > 0.f ? v : 0.f;
    }
    __syncthreads();
    float bj = ba[j];
    float acc[8];
#pragma unroll
    for (int r = 0; r < 8; r++) acc[r] = bj;
    for (int k = 0; k < 128; k++) {
        float w = Wa[k * 128 + j];
#pragma unroll
        for (int r = 0; r < 8; r++) acc[r] = fmaf(sz[r][k], w, acc[r]);
    }
    float wo = Wo[j];
#pragma unroll
    for (int r = 0; r < 8; r++) {
        float t = fast_tanh(acc[r]) * wo;
        for (int o = 16; o > 0; o >>= 1) t += __shfl_down_sync(0xffffffffu, t, o);
        if ((j & 31) == 0) atomicAdd(&sacc[r], t);
    }
    __syncthreads();
    if (j == 0) {
        float tot = 0.f;
#pragma unroll
        for (int r = 0; r < 8; r++) tot += sacc[r];
        atomicAdd(part, tot);
    }
}

__global__ void compute_beta()
{
    for (int grp = 0; grp < 2; grp++) {
        float w0 = g_watt[2 * grp] * (1.f / NN);
        float w1 = g_watt[2 * grp + 1] * (1.f / NN);
        float m = fmaxf(w0, w1);
        float e0 = expf(w0 - m), e1 = expf(w1 - m);
        float inv = 1.f / (e0 + e1);
        g_beta[2 * grp] = e0 * inv;
        g_beta[2 * grp + 1] = e1 * inv;
    }
}

__global__ void combine_bf16(const float* __restrict__ z0, const float* __restrict__ z1,
                             __nv_bfloat16* __restrict__ out, int n2, int betaIdx)
{
    int i = blockIdx.x * blockDim.x + threadIdx.x;
    if (i >= n2) return;
    float b0 = g_beta[betaIdx], b1 = g_beta[betaIdx + 1];
    float2 a = reinterpret_cast<const float2*>(z0)[i];
    float2 c = reinterpret_cast<const float2*>(z1)[i];
    float o0 = b0 * fmaxf(a.x, 0.f) + b1 * fmaxf(c.x, 0.f);
    float o1 = b0 * fmaxf(a.y, 0.f) + b1 * fmaxf(c.y, 0.f);
    reinterpret_cast<__nv_bfloat162*>(out)[i] = __floats2bfloat162_rn(o0, o1);
}

// ================= predictor =================
__global__ void predict_kernel(const float* __restrict__ pa, const float* __restrict__ pt,
                               const int* __restrict__ src, const int* __restrict__ dst,
                               const float* __restrict__ b1, const float* __restrict__ W2,
                               const float* __restrict__ b2, float* __restrict__ out, int E)
{
    int gw = (blockIdx.x * blockDim.x + threadIdx.x) >> 5;
    int lane = threadIdx.x & 31;
    if (gw >= E) return;
    int s = src[gw], d = dst[gw];
    float4 a = __ldg(reinterpret_cast<const float4*>(pa) + (size_t)s * 32 + lane);
    float4 b = __ldg(reinterpret_cast<const float4*>(pt) + (size_t)d * 32 + lane);
    float4 bb = __ldg(reinterpret_cast<const float4*>(b1) + lane);
    float4 w = __ldg(reinterpret_cast<const float4*>(W2) + lane);
    float ux = fmaxf(a.x + b.x + bb.x, 0.f);
    float uy = fmaxf(a.y + b.y + bb.y, 0.f);
    float uz = fmaxf(a.z + b.z + bb.z, 0.f);
    float uw = fmaxf(a.w + b.w + bb.w, 0.f);
    float dot = ux * w.x + uy * w.y + uz * w.z + uw * w.w;
    for (int o = 16; o > 0; o >>= 1) dot += __shfl_down_sync(0xffffffffu, dot, o);
    if (lane == 0) out[gw] = 1.f / (1.f + expf(-(dot + b2[0])));
}

// ================= host =================
extern "C" void kernel_launch(void* const* d_in, const int* in_sizes, int n_in,
                              void* d_out, int out_size)
{
    const float* prot   = (const float*)d_in[0];
    const float* gen    = (const float*)d_in[1];
    const float* W1     = (const float*)d_in[2];
    const float* b1     = (const float*)d_in[3];
    const float* W2     = (const float*)d_in[4];
    const float* b2     = (const float*)d_in[5];
    const float* gWs    = (const float*)d_in[6];
    const float* gbs    = (const float*)d_in[7];
    const float* gWd    = (const float*)d_in[8];
    const float* gbd    = (const float*)d_in[9];
    const float* gattn  = (const float*)d_in[10];
    const float* pAW1   = (const float*)d_in[11];
    const float* pAb1   = (const float*)d_in[12];
    const float* pAW2   = (const float*)d_in[13];
    const float* gAW1   = (const float*)d_in[14];
    const float* gAb1   = (const float*)d_in[15];
    const float* gAW2   = (const float*)d_in[16];
    const float* predW1 = (const float*)d_in[17];
    const float* predb1 = (const float*)d_in[18];
    const float* predW2 = (const float*)d_in[19];
    const float* predb2 = (const float*)d_in[20];
    const int* e_aa = (const int*)d_in[21];
    const int* e_ta = (const int*)d_in[22];
    const int* e_tt = (const int*)d_in[23];
    const int* e_at = (const int*)d_in[24];
    const int* pos_e = (const int*)d_in[25];
    const int* neg_e = (const int*)d_in[26];
    float* out = (float*)d_out;

    __nv_bfloat16 *p_protb, *p_genb, *p_hab, *p_htb, *p_Fa, *p_Ft, *p_haoutb, *p_htoutb, *p_wt;
    float *p_z, *p_ex, *p_s, *p_pa, *p_pt, *p_watt, *p_biascat;
    cudaGetSymbolAddress((void**)&p_protb, g_protb);
    cudaGetSymbolAddress((void**)&p_genb, g_genb);
    cudaGetSymbolAddress((void**)&p_hab, g_hab);
    cudaGetSymbolAddress((void**)&p_htb, g_htb);
    cudaGetSymbolAddress((void**)&p_Fa, g_Fa);
    cudaGetSymbolAddress((void**)&p_Ft, g_Ft);
    cudaGetSymbolAddress((void**)&p_haoutb, g_haoutb);
    cudaGetSymbolAddress((void**)&p_htoutb, g_htoutb);
    cudaGetSymbolAddress((void**)&p_wt, g_wt);
    cudaGetSymbolAddress((void**)&p_z, g_z);
    cudaGetSymbolAddress((void**)&p_ex, g_ex);
    cudaGetSymbolAddress((void**)&p_s, g_s);
    cudaGetSymbolAddress((void**)&p_pa, g_pa);
    cudaGetSymbolAddress((void**)&p_pt, g_pt);
    cudaGetSymbolAddress((void**)&p_watt, g_watt);
    cudaGetSymbolAddress((void**)&p_biascat, g_biascat);

    cudaFuncSetAttribute(gemm_bf16<1>, cudaFuncAttributeMaxDynamicSharedMemorySize, GSM_TOTAL);
    cudaFuncSetAttribute(gemm_bf16<0>, cudaFuncAttributeMaxDynamicSharedMemorySize, GSM_TOTAL);

    cudaMemsetAsync(p_z, 0, sizeof(float) * 4 * NN * HIDF);
    cudaMemsetAsync(p_s, 0, sizeof(float) * 4 * NN * 4);
    cudaMemsetAsync(p_watt, 0, sizeof(float) * 4);

    const int MR = (NN + 127) / 128;  // 391
    const int WSZ = 256 * 128;

    // Launch order chosen so ncu (-s 5 -c 1) profiles the big protein GEMM (launch #6).
    f32_to_bf16_kernel<<<(NN * 1024 / 4 + 255) / 256, 256>>>(prot, p_protb, NN * 1024 / 4);     // 1
    f32_to_bf16_kernel<<<(NN * 512 / 4 + 255) / 256, 256>>>(gen, p_genb, NN * 512 / 4);         // 2
    transpose_bf16_kernel<<<(1024 * 256 + 255) / 256, 256>>>(W2, p_wt + OFF_W2T, 1024, 256);    // 3
    transpose_bf16_kernel<<<(512 * 256 + 255) / 256, 256>>>(W1, p_wt + OFF_W1T, 512, 256);      // 4
    concat_bias_kernel<<<1, 128>>>(gbs, gbd, p_biascat, p_biascat + 512);                       // 5
    gemm_bf16<1><<<dim3(2, MR), 256, GSM_TOTAL>>>(p_protb, p_wt + OFF_W2T, b2, p_hab, NN, 256, 1024, 1024);  // 6 <- profiled
    gemm_bf16<1><<<dim3(2, MR), 256, GSM_TOTAL>>>(p_genb,  p_wt + OFF_W1T, b1, p_htb, NN, 256, 512, 512);

    // batched GAT weight slots: A-side [Ws0, Wd0, Wd1, Ws3], T-side [Ws1, Ws2, Wd2, Wd3]
    transpose_bf16_kernel<<<(WSZ + 255) / 256, 256>>>(gWs + 0 * WSZ, p_wt + OFF_WA + 0 * WSZ, 256, 128);
    transpose_bf16_kernel<<<(WSZ + 255) / 256, 256>>>(gWd + 0 * WSZ, p_wt + OFF_WA + 1 * WSZ, 256, 128);
    transpose_bf16_kernel<<<(WSZ + 255) / 256, 256>>>(gWd + 1 * WSZ, p_wt + OFF_WA + 2 * WSZ, 256, 128);
    transpose_bf16_kernel<<<(WSZ + 255) / 256, 256>>>(gWs + 3 * WSZ, p_wt + OFF_WA + 3 * WSZ, 256, 128);
    transpose_bf16_kernel<<<(WSZ + 255) / 256, 256>>>(gWs + 1 * WSZ, p_wt + OFF_WT + 0 * WSZ, 256, 128);
    transpose_bf16_kernel<<<(WSZ + 255) / 256, 256>>>(gWs + 2 * WSZ, p_wt + OFF_WT + 1 * WSZ, 256, 128);
    transpose_bf16_kernel<<<(WSZ + 255) / 256, 256>>>(gWd + 2 * WSZ, p_wt + OFF_WT + 2 * WSZ, 256, 128);
    transpose_bf16_kernel<<<(WSZ + 255) / 256, 256>>>(gWd + 3 * WSZ, p_wt + OFF_WT + 3 * WSZ, 256, 128);
    transpose_bf16_kernel<<<(256 * 128 + 255) / 256, 256>>>(predW1, p_wt + OFF_PW1, 256, 128);

    // batched GAT projections
    gemm_bf16<1><<<dim3(4, MR), 256, GSM_TOTAL>>>(p_hab, p_wt + OFF_WA, p_biascat,       p_Fa, NN, 512, 256, 256);
    gemm_bf16<1><<<dim3(4, MR), 256, GSM_TOTAL>>>(p_htb, p_wt + OFF_WT, p_biascat + 512, p_Ft, NN, 512, 256, 256);

    const __nv_bfloat16* FS[4] = { p_Fa + 0,   p_Ft + 0,   p_Ft + 128, p_Fa + 384 };
    const __nv_bfloat16* FD[4] = { p_Fa + 128, p_Fa + 256, p_Ft + 256, p_Ft + 384 };
    const int* edges[4] = { e_aa, e_ta, e_tt, e_at };
    for (int g = 0; g < 4; g++) {
        const int* src = edges[g];
        const int* dst = edges[g] + EE;
        float* sg = p_s + (size_t)g * NN * 4;
        float* zg = p_z + (size_t)g * NN * HIDF;
        edge_logits_exp<<<(EE * 32 + 255) / 256, 256>>>(FS[g], FD[g], 128, src, dst, gattn + g * 128, p_ex, sg, EE);
        edge_aggregate<<<(EE * 32 + 255) / 256, 256>>>(FS[g], 128, src, dst, p_ex, sg, zg, EE);
    }

    sematt_partial<<<NN / 8, 128>>>(p_z + 0 * (size_t)NN * HIDF, pAW1, pAb1, pAW2, p_watt + 0);
    sematt_partial<<<NN / 8, 128>>>(p_z + 1 * (size_t)NN * HIDF, pAW1, pAb1, pAW2, p_watt + 1);
    sematt_partial<<<NN / 8, 128>>>(p_z + 2 * (size_t)NN * HIDF, gAW1, gAb1, gAW2, p_watt + 2);
    sematt_partial<<<NN / 8, 128>>>(p_z + 3 * (size_t)NN * HIDF, gAW1, gAb1, gAW2, p_watt + 3);
    compute_beta<<<1, 1>>>();

    combine_bf16<<<(NN * HIDF / 2 + 255) / 256, 256>>>(p_z + 0 * (size_t)NN * HIDF, p_z + 1 * (size_t)NN * HIDF, p_haoutb, NN * HIDF / 2, 0);
    combine_bf16<<<(NN * HIDF / 2 + 255) / 256, 256>>>(p_z + 2 * (size_t)NN * HIDF, p_z + 3 * (size_t)NN * HIDF, p_htoutb, NN * HIDF / 2, 2);

    gemm_bf16<0><<<dim3(1, MR), 256, GSM_TOTAL>>>(p_haoutb, p_wt + OFF_PW1,       nullptr, p_pa, NN, 128, 128, 256);
    gemm_bf16<0><<<dim3(1, MR), 256, GSM_TOTAL>>>(p_htoutb, p_wt + OFF_PW1 + 128, nullptr, p_pt, NN, 128, 128, 256);

    predict_kernel<<<(EP * 32 + 255) / 256, 256>>>(p_pa, p_pt, pos_e, pos_e + EP, predb1, predW2, predb2, out, EP);
    predict_kernel<<<(EP * 32 + 255) / 256, 256>>>(p_pa, p_pt, neg_e, neg_e + EP, predb1, predW2, predb2, out + EP, EP);
}

// round 6
// speedup vs baseline: 2.5059x; 1.1550x over previous
#include <cuda_runtime.h>
#include <cuda_bf16.h>
#include <math.h>
#include <cstdint>

#define NN 50000
#define EE 800000
#define EP 200000
#define HIDF 128

__device__ __forceinline__ uint32_t smem_u32(const void* p) {
    uint32_t a;
    asm("{ .reg .u64 t; cvta.to.shared.u64 t, %1; cvt.u32.u64 %0, t; }" : "=r"(a) : "l"(p));
    return a;
}
__device__ __forceinline__ void cp_async16(uint32_t s, const void* g, bool pred) {
    int sz = pred ? 16 : 0;
    asm volatile("cp.async.cg.shared.global [%0], [%1], 16, %2;" :: "r"(s), "l"(g), "r"(sz));
}
#define CP_COMMIT() asm volatile("cp.async.commit_group;" ::: "memory")
#define CP_WAIT1()  asm volatile("cp.async.wait_group 1;" ::: "memory")
#define CP_WAIT0()  asm volatile("cp.async.wait_group 0;" ::: "memory")
__device__ __forceinline__ float fast_tanh(float x) {
    float y;
    asm("tanh.approx.f32 %0, %1;" : "=f"(y) : "f"(x));
    return y;
}

// ================= scratch =================
__device__ __nv_bfloat16 g_protb[NN * 1024];
__device__ __nv_bfloat16 g_genb[NN * 512];
__device__ __nv_bfloat16 g_hab[NN * 256];
__device__ __nv_bfloat16 g_htb[NN * 256];
__device__ __nv_bfloat16 g_Fa[NN * 512];
__device__ __nv_bfloat16 g_Ft[NN * 512];
__device__ float g_z[4 * NN * HIDF];
__device__ __nv_bfloat16 g_haoutb[NN * 128];
__device__ __nv_bfloat16 g_htoutb[NN * 128];
__device__ float g_pa[NN * 128];
__device__ float g_pt[NN * 128];
__device__ float g_watt[4];
__device__ float g_beta[4];
__device__ __nv_bfloat16 g_wt[688128];
__device__ float g_biascat[1024];
// CSR scratch
__device__ int g_deg[4 * NN];
__device__ int g_off[4 * NN];
__device__ int g_cur[4 * NN];
__device__ int g_elist[4 * EE];

#define OFF_W2T 0
#define OFF_W1T 262144
#define OFF_WA  393216
#define OFF_WT  524288
#define OFF_PW1 655360

// ================= CSR build =================
__global__ void hist_kernel(const int* __restrict__ e0, const int* __restrict__ e1,
                            const int* __restrict__ e2, const int* __restrict__ e3) {
    int e = blockIdx.x * blockDim.x + threadIdx.x;
    if (e >= EE) return;
    int g = blockIdx.y;
    const int* eg = (g == 0) ? e0 : (g == 1) ? e1 : (g == 2) ? e2 : e3;
    atomicAdd(&g_deg[g * NN + eg[EE + e]], 1);
}

__global__ void scan_kernel() {
    __shared__ int sdata[1024];
    __shared__ int scarry;
    int g = blockIdx.x, tid = threadIdx.x;
    if (tid == 0) scarry = 0;
    __syncthreads();
    int base = g * NN;
    for (int c = 0; c < (NN + 1023) / 1024; c++) {
        int idx = c * 1024 + tid;
        int v = (idx < NN) ? g_deg[base + idx] : 0;
        sdata[tid] = v;
        __syncthreads();
        for (int o = 1; o < 1024; o <<= 1) {
            int t = (tid >= o) ? sdata[tid - o] : 0;
            __syncthreads();
            sdata[tid] += t;
            __syncthreads();
        }
        int excl = scarry + sdata[tid] - v;
        if (idx < NN) { g_off[base + idx] = excl; g_cur[base + idx] = excl; }
        __syncthreads();
        if (tid == 1023) scarry += sdata[1023];
        __syncthreads();
    }
}

__global__ void scatter_kernel(const int* __restrict__ e0, const int* __restrict__ e1,
                               const int* __restrict__ e2, const int* __restrict__ e3) {
    int e = blockIdx.x * blockDim.x + threadIdx.x;
    if (e >= EE) return;
    int g = blockIdx.y;
    const int* eg = (g == 0) ? e0 : (g == 1) ? e1 : (g == 2) ? e2 : e3;
    int s = eg[e], d = eg[EE + e];
    int pos = atomicAdd(&g_cur[g * NN + d], 1);
    g_elist[(size_t)g * EE + pos] = s;
}

// ================= fused GATv2 per-destination kernel =================
// One warp per dst node: softmax (no max shift; logits O(1)) + weighted aggregation.
__global__ void gat_aggregate(const __nv_bfloat16* __restrict__ fs, const __nv_bfloat16* __restrict__ fd,
                              int strideU2, const float* __restrict__ attn,
                              const int* __restrict__ off, const int* __restrict__ elist,
                              float* __restrict__ zout)
{
    int d = (blockIdx.x * blockDim.x + threadIdx.x) >> 5;
    int lane = threadIdx.x & 31;
    if (d >= NN) return;
    uint2 ud = __ldg(reinterpret_cast<const uint2*>(fd) + (size_t)d * strideU2 + lane);
    float2 d0 = __bfloat1622float2(*reinterpret_cast<__nv_bfloat162*>(&ud.x));
    float2 d1 = __bfloat1622float2(*reinterpret_cast<__nv_bfloat162*>(&ud.y));
    float4 at = __ldg(reinterpret_cast<const float4*>(attn) + lane);
    int base = off[d];
    int end = (d == NN - 1) ? EE : off[d + 1];

    float ssum = 0.f;
    for (int i = base; i < end; i++) {
        int s = elist[i];
        uint2 ua = __ldg(reinterpret_cast<const uint2*>(fs) + (size_t)s * strideU2 + lane);
        float2 a0 = __bfloat1622float2(*reinterpret_cast<__nv_bfloat162*>(&ua.x));
        float2 a1 = __bfloat1622float2(*reinterpret_cast<__nv_bfloat162*>(&ua.y));
        float vx = a0.x + d0.x, vy = a0.y + d0.y, vz = a1.x + d1.x, vw = a1.y + d1.y;
        vx = vx > 0.f ? vx : 0.2f * vx;
        vy = vy > 0.f ? vy : 0.2f * vy;
        vz = vz > 0.f ? vz : 0.2f * vz;
        vw = vw > 0.f ? vw : 0.2f * vw;
        float p = vx * at.x + vy * at.y + vz * at.z + vw * at.w;
        p += __shfl_xor_sync(0xffffffffu, p, 4);
        p += __shfl_xor_sync(0xffffffffu, p, 2);
        p += __shfl_xor_sync(0xffffffffu, p, 1);
        ssum += __expf(p);
    }
    float inv = 1.f / ssum;   // unused when degree==0

    float acc0 = 0.f, acc1 = 0.f, acc2 = 0.f, acc3 = 0.f;
    for (int i = base; i < end; i++) {
        int s = elist[i];
        uint2 ua = __ldg(reinterpret_cast<const uint2*>(fs) + (size_t)s * strideU2 + lane);
        float2 a0 = __bfloat1622float2(*reinterpret_cast<__nv_bfloat162*>(&ua.x));
        float2 a1 = __bfloat1622float2(*reinterpret_cast<__nv_bfloat162*>(&ua.y));
        float vx = a0.x + d0.x, vy = a0.y + d0.y, vz = a1.x + d1.x, vw = a1.y + d1.y;
        vx = vx > 0.f ? vx : 0.2f * vx;
        vy = vy > 0.f ? vy : 0.2f * vy;
        vz = vz > 0.f ? vz : 0.2f * vz;
        vw = vw > 0.f ? vw : 0.2f * vw;
        float p = vx * at.x + vy * at.y + vz * at.z + vw * at.w;
        p += __shfl_xor_sync(0xffffffffu, p, 4);
        p += __shfl_xor_sync(0xffffffffu, p, 2);
        p += __shfl_xor_sync(0xffffffffu, p, 1);
        float alpha = __expf(p) * inv;
        acc0 = fmaf(alpha, a0.x, acc0);
        acc1 = fmaf(alpha, a0.y, acc1);
        acc2 = fmaf(alpha, a1.x, acc2);
        acc3 = fmaf(alpha, a1.y, acc3);
    }
    *reinterpret_cast<float4*>(zout + (size_t)d * 128 + lane * 4) =
        make_float4(acc0, acc1, acc2, acc3);
}

// ================= converts / transposes =================
__global__ void f32_to_bf16_kernel(const float* __restrict__ in, __nv_bfloat16* __restrict__ out, int n4) {
    int i = blockIdx.x * blockDim.x + threadIdx.x;
    if (i >= n4) return;
    float4 v = __ldg(reinterpret_cast<const float4*>(in) + i);
    __nv_bfloat162 h0 = __floats2bfloat162_rn(v.x, v.y);
    __nv_bfloat162 h1 = __floats2bfloat162_rn(v.z, v.w);
    reinterpret_cast<uint2*>(out)[i] =
        make_uint2(*reinterpret_cast<uint32_t*>(&h0), *reinterpret_cast<uint32_t*>(&h1));
}
__global__ void transpose_bf16_kernel(const float* __restrict__ in, __nv_bfloat16* __restrict__ out,
                                      int K, int N) {
    int idx = blockIdx.x * blockDim.x + threadIdx.x;
    if (idx >= K * N) return;
    int k = idx / N, n = idx % N;
    out[(size_t)n * K + k] = __float2bfloat16(in[idx]);
}
__global__ void concat_bias_kernel(const float* __restrict__ gbs, const float* __restrict__ gbd,
                                   float* __restrict__ outa, float* __restrict__ outt) {
    int i = threadIdx.x;  // 128
    outa[i]       = gbs[0 * 128 + i];
    outa[128 + i] = gbd[0 * 128 + i];
    outa[256 + i] = gbd[1 * 128 + i];
    outa[384 + i] = gbs[3 * 128 + i];
    outt[i]       = gbs[1 * 128 + i];
    outt[128 + i] = gbs[2 * 128 + i];
    outt[256 + i] = gbd[2 * 128 + i];
    outt[384 + i] = gbd[3 * 128 + i];
}

// ================= pipelined HMMA GEMM =================
#define GSM_BIAS 65536
#define GSM_TOTAL (65536 + 512)

__device__ __forceinline__ void gemm_load_tile(
    uint32_t sb, uint32_t aOff, uint32_t bOff,
    const __nv_bfloat16* __restrict__ A, const __nv_bfloat16* __restrict__ Bt,
    int row0, int col0, int k0, int M, int K, int ldb, int tid)
{
#pragma unroll
    for (int it = 0; it < 4; it++) {
        int idx = it * 256 + tid;
        int r = idx >> 3, cc = idx & 7;
        uint32_t dst = sb + aOff + r * 128 + ((cc ^ (r & 7)) << 4);
        cp_async16(dst, A + (size_t)(row0 + r) * K + k0 + cc * 8, row0 + r < M);
    }
#pragma unroll
    for (int it = 0; it < 4; it++) {
        int idx = it * 256 + tid;
        int r = idx >> 3, cc = idx & 7;
        uint32_t dst = sb + bOff + r * 128 + ((cc ^ (r & 7)) << 4);
        cp_async16(dst, Bt + (size_t)(col0 + r) * ldb + k0 + cc * 8, true);
    }
}

template <int BF16OUT>
__global__ void __launch_bounds__(256) gemm_bf16(
    const __nv_bfloat16* __restrict__ A, const __nv_bfloat16* __restrict__ Bt,
    const float* __restrict__ bias, void* __restrict__ Cout,
    int M, int N, int K, int ldb)
{
    extern __shared__ char smem[];
    uint32_t sb = smem_u32(smem);
    const int tid = threadIdx.x;
    const int wid = tid >> 5, lane = tid & 31;
    const int wm = wid & 3, wn = wid >> 2;
    const int row0 = blockIdx.y * 128, col0 = blockIdx.x * 128;
    float* sbias = reinterpret_cast<float*>(smem + GSM_BIAS);

    if (tid < 128) sbias[tid] = bias ? __ldg(bias + col0 + tid) : 0.f;

    float c[2][8][4];
#pragma unroll
    for (int i = 0; i < 2; i++)
#pragma unroll
        for (int j = 0; j < 8; j++)
#pragma unroll
            for (int q = 0; q < 4; q++) c[i][j][q] = 0.f;

    const int niter = K >> 6;
    gemm_load_tile(sb, 0, 16384, A, Bt, row0, col0, 0, M, K, ldb, tid);
    CP_COMMIT();

    for (int it = 0; it < niter; it++) {
        const uint32_t aOff = (it & 1) * 32768u;
        const uint32_t bOff = aOff + 16384u;
        if (it + 1 < niter) {
            uint32_t a2 = ((it + 1) & 1) * 32768u;
            gemm_load_tile(sb, a2, a2 + 16384u, A, Bt, row0, col0, (it + 1) * 64, M, K, ldb, tid);
            CP_COMMIT();
            CP_WAIT1();
        } else {
            CP_WAIT0();
        }
        __syncthreads();

#pragma unroll
        for (int ks = 0; ks < 4; ks++) {
            uint32_t a[2][4];
#pragma unroll
            for (int mt = 0; mt < 2; mt++) {
                int ar = wm * 32 + mt * 16 + (lane & 15);
                int ch = ks * 2 + (lane >> 4);
                uint32_t addr = sb + aOff + ar * 128 + ((ch ^ (ar & 7)) << 4);
                asm volatile("ldmatrix.sync.aligned.m8n8.x4.shared.b16 {%0,%1,%2,%3}, [%4];"
                             : "=r"(a[mt][0]), "=r"(a[mt][1]), "=r"(a[mt][2]), "=r"(a[mt][3]) : "r"(addr));
            }
            uint32_t b[8][2];
#pragma unroll
            for (int nt = 0; nt < 8; nt++) {
                int br = wn * 64 + nt * 8 + (lane & 7);
                int ch = ks * 2 + ((lane >> 3) & 1);
                uint32_t addr = sb + bOff + br * 128 + ((ch ^ (br & 7)) << 4);
                asm volatile("ldmatrix.sync.aligned.m8n8.x2.shared.b16 {%0,%1}, [%2];"
                             : "=r"(b[nt][0]), "=r"(b[nt][1]) : "r"(addr));
            }
#pragma unroll
            for (int mt = 0; mt < 2; mt++)
#pragma unroll
                for (int nt = 0; nt < 8; nt++)
                    asm volatile(
                        "mma.sync.aligned.m16n8k16.row.col.f32.bf16.bf16.f32 "
                        "{%0,%1,%2,%3}, {%4,%5,%6,%7}, {%8,%9}, {%0,%1,%2,%3};"
                        : "+f"(c[mt][nt][0]), "+f"(c[mt][nt][1]), "+f"(c[mt][nt][2]), "+f"(c[mt][nt][3])
                        : "r"(a[mt][0]), "r"(a[mt][1]), "r"(a[mt][2]), "r"(a[mt][3]),
                          "r"(b[nt][0]), "r"(b[nt][1]));
        }
        __syncthreads();
    }

#pragma unroll
    for (int mt = 0; mt < 2; mt++) {
#pragma unroll
        for (int half = 0; half < 2; half++) {
            int gr = row0 + wm * 32 + mt * 16 + (lane >> 2) + half * 8;
            if (gr >= M) continue;
#pragma unroll
            for (int nt = 0; nt < 8; nt++) {
                int lc = wn * 64 + nt * 8 + (lane & 3) * 2;
                float v0 = c[mt][nt][half * 2 + 0] + sbias[lc];
                float v1 = c[mt][nt][half * 2 + 1] + sbias[lc + 1];
                if (BF16OUT) {
                    __nv_bfloat162 h = __floats2bfloat162_rn(v0, v1);
                    *reinterpret_cast<__nv_bfloat162*>(
                        reinterpret_cast<__nv_bfloat16*>(Cout) + (size_t)gr * N + col0 + lc) = h;
                } else {
                    *reinterpret_cast<float2*>(
                        reinterpret_cast<float*>(Cout) + (size_t)gr * N + col0 + lc) = make_float2(v0, v1);
                }
            }
        }
    }
}

// ================= semantic attention =================
__global__ void sematt_partial(const float* __restrict__ z, const float* __restrict__ Wa,
                               const float* __restrict__ ba, const float* __restrict__ Wo,
                               float* __restrict__ part)
{
    __shared__ float sz[8][128];
    __shared__ float sacc[8];
    int j = threadIdx.x;
    int r0 = blockIdx.x * 8;
    if (j < 8) sacc[j] = 0.f;
#pragma unroll
    for (int r = 0; r < 8; r++) {
        float v = z[(size_t)(r0 + r) * 128 + j];
        sz[r][j] = v > 0.f ? v : 0.f;
    }
    __syncthreads();
    float bj = ba[j];
    float acc[8];
#pragma unroll
    for (int r = 0; r < 8; r++) acc[r] = bj;
    for (int k = 0; k < 128; k++) {
        float w = Wa[k * 128 + j];
#pragma unroll
        for (int r = 0; r < 8; r++) acc[r] = fmaf(sz[r][k], w, acc[r]);
    }
    float wo = Wo[j];
#pragma unroll
    for (int r = 0; r < 8; r++) {
        float t = fast_tanh(acc[r]) * wo;
        for (int o = 16; o > 0; o >>= 1) t += __shfl_down_sync(0xffffffffu, t, o);
        if ((j & 31) == 0) atomicAdd(&sacc[r], t);
    }
    __syncthreads();
    if (j == 0) {
        float tot = 0.f;
#pragma unroll
        for (int r = 0; r < 8; r++) tot += sacc[r];
        atomicAdd(part, tot);
    }
}

__global__ void compute_beta()
{
    for (int grp = 0; grp < 2; grp++) {
        float w0 = g_watt[2 * grp] * (1.f / NN);
        float w1 = g_watt[2 * grp + 1] * (1.f / NN);
        float m = fmaxf(w0, w1);
        float e0 = expf(w0 - m), e1 = expf(w1 - m);
        float inv = 1.f / (e0 + e1);
        g_beta[2 * grp] = e0 * inv;
        g_beta[2 * grp + 1] = e1 * inv;
    }
}

__global__ void combine_bf16(const float* __restrict__ z0, const float* __restrict__ z1,
                             __nv_bfloat16* __restrict__ out, int n2, int betaIdx)
{
    int i = blockIdx.x * blockDim.x + threadIdx.x;
    if (i >= n2) return;
    float b0 = g_beta[betaIdx], b1 = g_beta[betaIdx + 1];
    float2 a = reinterpret_cast<const float2*>(z0)[i];
    float2 c = reinterpret_cast<const float2*>(z1)[i];
    float o0 = b0 * fmaxf(a.x, 0.f) + b1 * fmaxf(c.x, 0.f);
    float o1 = b0 * fmaxf(a.y, 0.f) + b1 * fmaxf(c.y, 0.f);
    reinterpret_cast<__nv_bfloat162*>(out)[i] = __floats2bfloat162_rn(o0, o1);
}

// ================= predictor =================
__global__ void predict_kernel(const float* __restrict__ pa, const float* __restrict__ pt,
                               const int* __restrict__ src, const int* __restrict__ dst,
                               const float* __restrict__ b1, const float* __restrict__ W2,
                               const float* __restrict__ b2, float* __restrict__ out, int E)
{
    int gw = (blockIdx.x * blockDim.x + threadIdx.x) >> 5;
    int lane = threadIdx.x & 31;
    if (gw >= E) return;
    int s = src[gw], d = dst[gw];
    float4 a = __ldg(reinterpret_cast<const float4*>(pa) + (size_t)s * 32 + lane);
    float4 b = __ldg(reinterpret_cast<const float4*>(pt) + (size_t)d * 32 + lane);
    float4 bb = __ldg(reinterpret_cast<const float4*>(b1) + lane);
    float4 w = __ldg(reinterpret_cast<const float4*>(W2) + lane);
    float ux = fmaxf(a.x + b.x + bb.x, 0.f);
    float uy = fmaxf(a.y + b.y + bb.y, 0.f);
    float uz = fmaxf(a.z + b.z + bb.z, 0.f);
    float uw = fmaxf(a.w + b.w + bb.w, 0.f);
    float dot = ux * w.x + uy * w.y + uz * w.z + uw * w.w;
    for (int o = 16; o > 0; o >>= 1) dot += __shfl_down_sync(0xffffffffu, dot, o);
    if (lane == 0) out[gw] = 1.f / (1.f + expf(-(dot + b2[0])));
}

// ================= host =================
extern "C" void kernel_launch(void* const* d_in, const int* in_sizes, int n_in,
                              void* d_out, int out_size)
{
    const float* prot   = (const float*)d_in[0];
    const float* gen    = (const float*)d_in[1];
    const float* W1     = (const float*)d_in[2];
    const float* b1     = (const float*)d_in[3];
    const float* W2     = (const float*)d_in[4];
    const float* b2     = (const float*)d_in[5];
    const float* gWs    = (const float*)d_in[6];
    const float* gbs    = (const float*)d_in[7];
    const float* gWd    = (const float*)d_in[8];
    const float* gbd    = (const float*)d_in[9];
    const float* gattn  = (const float*)d_in[10];
    const float* pAW1   = (const float*)d_in[11];
    const float* pAb1   = (const float*)d_in[12];
    const float* pAW2   = (const float*)d_in[13];
    const float* gAW1   = (const float*)d_in[14];
    const float* gAb1   = (const float*)d_in[15];
    const float* gAW2   = (const float*)d_in[16];
    const float* predW1 = (const float*)d_in[17];
    const float* predb1 = (const float*)d_in[18];
    const float* predW2 = (const float*)d_in[19];
    const float* predb2 = (const float*)d_in[20];
    const int* e_aa = (const int*)d_in[21];
    const int* e_ta = (const int*)d_in[22];
    const int* e_tt = (const int*)d_in[23];
    const int* e_at = (const int*)d_in[24];
    const int* pos_e = (const int*)d_in[25];
    const int* neg_e = (const int*)d_in[26];
    float* out = (float*)d_out;

    __nv_bfloat16 *p_protb, *p_genb, *p_hab, *p_htb, *p_Fa, *p_Ft, *p_haoutb, *p_htoutb, *p_wt;
    float *p_z, *p_pa, *p_pt, *p_watt, *p_biascat;
    int *p_deg, *p_off, *p_elist;
    cudaGetSymbolAddress((void**)&p_protb, g_protb);
    cudaGetSymbolAddress((void**)&p_genb, g_genb);
    cudaGetSymbolAddress((void**)&p_hab, g_hab);
    cudaGetSymbolAddress((void**)&p_htb, g_htb);
    cudaGetSymbolAddress((void**)&p_Fa, g_Fa);
    cudaGetSymbolAddress((void**)&p_Ft, g_Ft);
    cudaGetSymbolAddress((void**)&p_haoutb, g_haoutb);
    cudaGetSymbolAddress((void**)&p_htoutb, g_htoutb);
    cudaGetSymbolAddress((void**)&p_wt, g_wt);
    cudaGetSymbolAddress((void**)&p_z, g_z);
    cudaGetSymbolAddress((void**)&p_pa, g_pa);
    cudaGetSymbolAddress((void**)&p_pt, g_pt);
    cudaGetSymbolAddress((void**)&p_watt, g_watt);
    cudaGetSymbolAddress((void**)&p_biascat, g_biascat);
    cudaGetSymbolAddress((void**)&p_deg, g_deg);
    cudaGetSymbolAddress((void**)&p_off, g_off);
    cudaGetSymbolAddress((void**)&p_elist, g_elist);

    cudaFuncSetAttribute(gemm_bf16<1>, cudaFuncAttributeMaxDynamicSharedMemorySize, GSM_TOTAL);
    cudaFuncSetAttribute(gemm_bf16<0>, cudaFuncAttributeMaxDynamicSharedMemorySize, GSM_TOTAL);

    cudaMemsetAsync(p_deg, 0, sizeof(int) * 4 * NN);
    cudaMemsetAsync(p_watt, 0, sizeof(float) * 4);

    const int MR = (NN + 127) / 128;  // 391
    const int WSZ = 256 * 128;

    // CSR build (independent of GEMM chain)
    hist_kernel<<<dim3((EE + 255) / 256, 4), 256>>>(e_aa, e_ta, e_tt, e_at);
    scan_kernel<<<4, 1024>>>();
    scatter_kernel<<<dim3((EE + 255) / 256, 4), 256>>>(e_aa, e_ta, e_tt, e_at);

    // converts + weight prep
    f32_to_bf16_kernel<<<(NN * 1024 / 4 + 255) / 256, 256>>>(prot, p_protb, NN * 1024 / 4);
    f32_to_bf16_kernel<<<(NN * 512 / 4 + 255) / 256, 256>>>(gen, p_genb, NN * 512 / 4);
    transpose_bf16_kernel<<<(1024 * 256 + 255) / 256, 256>>>(W2, p_wt + OFF_W2T, 1024, 256);
    transpose_bf16_kernel<<<(512 * 256 + 255) / 256, 256>>>(W1, p_wt + OFF_W1T, 512, 256);
    concat_bias_kernel<<<1, 128>>>(gbs, gbd, p_biascat, p_biascat + 512);
    // A-side [Ws0, Wd0, Wd1, Ws3], T-side [Ws1, Ws2, Wd2, Wd3]
    transpose_bf16_kernel<<<(WSZ + 255) / 256, 256>>>(gWs + 0 * WSZ, p_wt + OFF_WA + 0 * WSZ, 256, 128);
    transpose_bf16_kernel<<<(WSZ + 255) / 256, 256>>>(gWd + 0 * WSZ, p_wt + OFF_WA + 1 * WSZ, 256, 128);
    transpose_bf16_kernel<<<(WSZ + 255) / 256, 256>>>(gWd + 1 * WSZ, p_wt + OFF_WA + 2 * WSZ, 256, 128);
    transpose_bf16_kernel<<<(WSZ + 255) / 256, 256>>>(gWs + 3 * WSZ, p_wt + OFF_WA + 3 * WSZ, 256, 128);
    transpose_bf16_kernel<<<(WSZ + 255) / 256, 256>>>(gWs + 1 * WSZ, p_wt + OFF_WT + 0 * WSZ, 256, 128);
    transpose_bf16_kernel<<<(WSZ + 255) / 256, 256>>>(gWs + 2 * WSZ, p_wt + OFF_WT + 1 * WSZ, 256, 128);
    transpose_bf16_kernel<<<(WSZ + 255) / 256, 256>>>(gWd + 2 * WSZ, p_wt + OFF_WT + 2 * WSZ, 256, 128);
    transpose_bf16_kernel<<<(WSZ + 255) / 256, 256>>>(gWd + 3 * WSZ, p_wt + OFF_WT + 3 * WSZ, 256, 128);
    transpose_bf16_kernel<<<(256 * 128 + 255) / 256, 256>>>(predW1, p_wt + OFF_PW1, 256, 128);

    // node projections
    gemm_bf16<1><<<dim3(2, MR), 256, GSM_TOTAL>>>(p_protb, p_wt + OFF_W2T, b2, p_hab, NN, 256, 1024, 1024);
    gemm_bf16<1><<<dim3(2, MR), 256, GSM_TOTAL>>>(p_genb,  p_wt + OFF_W1T, b1, p_htb, NN, 256, 512, 512);

    // batched GAT projections
    gemm_bf16<1><<<dim3(4, MR), 256, GSM_TOTAL>>>(p_hab, p_wt + OFF_WA, p_biascat,       p_Fa, NN, 512, 256, 256);
    gemm_bf16<1><<<dim3(4, MR), 256, GSM_TOTAL>>>(p_htb, p_wt + OFF_WT, p_biascat + 512, p_Ft, NN, 512, 256, 256);

    // fused GATv2 per-destination aggregation
    const __nv_bfloat16* FS[4] = { p_Fa + 0,   p_Ft + 0,   p_Ft + 128, p_Fa + 384 };
    const __nv_bfloat16* FD[4] = { p_Fa + 128, p_Fa + 256, p_Ft + 256, p_Ft + 384 };
    for (int g = 0; g < 4; g++) {
        gat_aggregate<<<(NN * 32 + 255) / 256, 256>>>(
            FS[g], FD[g], 128, gattn + g * 128,
            p_off + (size_t)g * NN, p_elist + (size_t)g * EE,
            p_z + (size_t)g * NN * HIDF);
    }

    sematt_partial<<<NN / 8, 128>>>(p_z + 0 * (size_t)NN * HIDF, pAW1, pAb1, pAW2, p_watt + 0);
    sematt_partial<<<NN / 8, 128>>>(p_z + 1 * (size_t)NN * HIDF, pAW1, pAb1, pAW2, p_watt + 1);
    sematt_partial<<<NN / 8, 128>>>(p_z + 2 * (size_t)NN * HIDF, gAW1, gAb1, gAW2, p_watt + 2);
    sematt_partial<<<NN / 8, 128>>>(p_z + 3 * (size_t)NN * HIDF, gAW1, gAb1, gAW2, p_watt + 3);
    compute_beta<<<1, 1>>>();

    combine_bf16<<<(NN * HIDF / 2 + 255) / 256, 256>>>(p_z + 0 * (size_t)NN * HIDF, p_z + 1 * (size_t)NN * HIDF, p_haoutb, NN * HIDF / 2, 0);
    combine_bf16<<<(NN * HIDF / 2 + 255) / 256, 256>>>(p_z + 2 * (size_t)NN * HIDF, p_z + 3 * (size_t)NN * HIDF, p_htoutb, NN * HIDF / 2, 2);

    gemm_bf16<0><<<dim3(1, MR), 256, GSM_TOTAL>>>(p_haoutb, p_wt + OFF_PW1,       nullptr, p_pa, NN, 128, 128, 256);
    gemm_bf16<0><<<dim3(1, MR), 256, GSM_TOTAL>>>(p_htoutb, p_wt + OFF_PW1 + 128, nullptr, p_pt, NN, 128, 128, 256);

    predict_kernel<<<(EP * 32 + 255) / 256, 256>>>(p_pa, p_pt, pos_e, pos_e + EP, predb1, predW2, predb2, out, EP);
    predict_kernel<<<(EP * 32 + 255) / 256, 256>>>(p_pa, p_pt, neg_e, neg_e + EP, predb1, predW2, predb2, out + EP, EP);
}

// round 7
// speedup vs baseline: 3.0393x; 1.2129x over previous
#include <cuda_runtime.h>
#include <cuda_bf16.h>
#include <math.h>
#include <cstdint>

#define NN 50000
#define EE 800000
#define EP 200000
#define HIDF 128

__device__ __forceinline__ uint32_t smem_u32(const void* p) {
    uint32_t a;
    asm("{ .reg .u64 t; cvta.to.shared.u64 t, %1; cvt.u32.u64 %0, t; }" : "=r"(a) : "l"(p));
    return a;
}
__device__ __forceinline__ void cp_async16(uint32_t s, const void* g, bool pred) {
    int sz = pred ? 16 : 0;
    asm volatile("cp.async.cg.shared.global [%0], [%1], 16, %2;" :: "r"(s), "l"(g), "r"(sz));
}
#define CP_COMMIT() asm volatile("cp.async.commit_group;" ::: "memory")
#define CP_WAIT1()  asm volatile("cp.async.wait_group 1;" ::: "memory")
#define CP_WAIT0()  asm volatile("cp.async.wait_group 0;" ::: "memory")
__device__ __forceinline__ float fast_tanh(float x) {
    float y;
    asm("tanh.approx.f32 %0, %1;" : "=f"(y) : "f"(x));
    return y;
}

// ================= scratch =================
__device__ __nv_bfloat16 g_protb[NN * 1024];
__device__ __nv_bfloat16 g_genb[NN * 512];
__device__ __nv_bfloat16 g_hab[NN * 256];
__device__ __nv_bfloat16 g_htb[NN * 256];
__device__ __nv_bfloat16 g_Fa[NN * 512];
__device__ __nv_bfloat16 g_Ft[NN * 512];
__device__ __nv_bfloat16 g_zb[4 * NN * HIDF];     // bf16 GAT outputs
__device__ __nv_bfloat16 g_haoutb[NN * 128];
__device__ __nv_bfloat16 g_htoutb[NN * 128];
__device__ float g_pa[NN * 128];
__device__ float g_pt[NN * 128];
__device__ float g_watt[4];
__device__ float g_beta[4];
__device__ __nv_bfloat16 g_wt[688128];
__device__ float g_biascat[1024];
// CSR scratch
__device__ int g_deg[4 * NN];
__device__ int g_off[4 * NN];
__device__ int g_cur[4 * NN];
__device__ int g_elist[4 * EE];

#define OFF_W2T 0
#define OFF_W1T 262144
#define OFF_WA  393216
#define OFF_PW1 655360
#define WSZ 32768   // 256*128

// ================= CSR build =================
__global__ void hist_kernel(const int* __restrict__ e0, const int* __restrict__ e1,
                            const int* __restrict__ e2, const int* __restrict__ e3) {
    int e = blockIdx.x * blockDim.x + threadIdx.x;
    if (e >= EE) return;
    int g = blockIdx.y;
    const int* eg = (g == 0) ? e0 : (g == 1) ? e1 : (g == 2) ? e2 : e3;
    atomicAdd(&g_deg[g * NN + eg[EE + e]], 1);
}

__global__ void scan_kernel() {
    __shared__ int sdata[1024];
    __shared__ int scarry;
    int g = blockIdx.x, tid = threadIdx.x;
    if (tid == 0) scarry = 0;
    __syncthreads();
    int base = g * NN;
    for (int c = 0; c < (NN + 1023) / 1024; c++) {
        int idx = c * 1024 + tid;
        int v = (idx < NN) ? g_deg[base + idx] : 0;
        sdata[tid] = v;
        __syncthreads();
        for (int o = 1; o < 1024; o <<= 1) {
            int t = (tid >= o) ? sdata[tid - o] : 0;
            __syncthreads();
            sdata[tid] += t;
            __syncthreads();
        }
        int excl = scarry + sdata[tid] - v;
        if (idx < NN) { g_off[base + idx] = excl; g_cur[base + idx] = excl; }
        __syncthreads();
        if (tid == 1023) scarry += sdata[1023];
        __syncthreads();
    }
}

__global__ void scatter_kernel(const int* __restrict__ e0, const int* __restrict__ e1,
                               const int* __restrict__ e2, const int* __restrict__ e3) {
    int e = blockIdx.x * blockDim.x + threadIdx.x;
    if (e >= EE) return;
    int g = blockIdx.y;
    const int* eg = (g == 0) ? e0 : (g == 1) ? e1 : (g == 2) ? e2 : e3;
    int s = eg[e], d = eg[EE + e];
    int pos = atomicAdd(&g_cur[g * NN + d], 1);
    g_elist[(size_t)g * EE + pos] = s;
}

// ================= fused single-pass GATv2 per-destination kernel =================
// z[d] = (sum_i ex_i * fs_i) / (sum_i ex_i); no max shift (logits O(1)), no alpha materialization.
__global__ void gat_aggregate(const __nv_bfloat16* __restrict__ fs, const __nv_bfloat16* __restrict__ fd,
                              int strideU2, const float* __restrict__ attn,
                              const int* __restrict__ off, const int* __restrict__ elist,
                              __nv_bfloat16* __restrict__ zout)
{
    int d = (blockIdx.x * blockDim.x + threadIdx.x) >> 5;
    int lane = threadIdx.x & 31;
    if (d >= NN) return;
    int base = off[d];
    int end = (d == NN - 1) ? EE : off[d + 1];
    uint2* zo = reinterpret_cast<uint2*>(zout) + (size_t)d * 32 + lane;

    if (base == end) {   // zero in-degree
        *zo = make_uint2(0u, 0u);
        return;
    }

    uint2 ud = __ldg(reinterpret_cast<const uint2*>(fd) + (size_t)d * strideU2 + lane);
    float2 d0 = __bfloat1622float2(*reinterpret_cast<__nv_bfloat162*>(&ud.x));
    float2 d1 = __bfloat1622float2(*reinterpret_cast<__nv_bfloat162*>(&ud.y));
    float4 at = __ldg(reinterpret_cast<const float4*>(attn) + lane);

    float ssum = 0.f;
    float acc0 = 0.f, acc1 = 0.f, acc2 = 0.f, acc3 = 0.f;
    for (int i = base; i < end; i++) {
        int s = elist[i];
        uint2 ua = __ldg(reinterpret_cast<const uint2*>(fs) + (size_t)s * strideU2 + lane);
        float2 a0 = __bfloat1622float2(*reinterpret_cast<__nv_bfloat162*>(&ua.x));
        float2 a1 = __bfloat1622float2(*reinterpret_cast<__nv_bfloat162*>(&ua.y));
        float vx = a0.x + d0.x, vy = a0.y + d0.y, vz = a1.x + d1.x, vw = a1.y + d1.y;
        vx = vx > 0.f ? vx : 0.2f * vx;
        vy = vy > 0.f ? vy : 0.2f * vy;
        vz = vz > 0.f ? vz : 0.2f * vz;
        vw = vw > 0.f ? vw : 0.2f * vw;
        float p = vx * at.x + vy * at.y + vz * at.z + vw * at.w;
        p += __shfl_xor_sync(0xffffffffu, p, 4);
        p += __shfl_xor_sync(0xffffffffu, p, 2);
        p += __shfl_xor_sync(0xffffffffu, p, 1);
        float ex = __expf(p);
        ssum += ex;
        acc0 = fmaf(ex, a0.x, acc0);
        acc1 = fmaf(ex, a0.y, acc1);
        acc2 = fmaf(ex, a1.x, acc2);
        acc3 = fmaf(ex, a1.y, acc3);
    }
    float inv = 1.f / ssum;
    __nv_bfloat162 h0 = __floats2bfloat162_rn(acc0 * inv, acc1 * inv);
    __nv_bfloat162 h1 = __floats2bfloat162_rn(acc2 * inv, acc3 * inv);
    *zo = make_uint2(*reinterpret_cast<uint32_t*>(&h0), *reinterpret_cast<uint32_t*>(&h1));
}

// ================= converts / transposes =================
__global__ void f32_to_bf16_kernel(const float* __restrict__ in, __nv_bfloat16* __restrict__ out, int n4) {
    int i = blockIdx.x * blockDim.x + threadIdx.x;
    if (i >= n4) return;
    float4 v = __ldg(reinterpret_cast<const float4*>(in) + i);
    __nv_bfloat162 h0 = __floats2bfloat162_rn(v.x, v.y);
    __nv_bfloat162 h1 = __floats2bfloat162_rn(v.z, v.w);
    reinterpret_cast<uint2*>(out)[i] =
        make_uint2(*reinterpret_cast<uint32_t*>(&h0), *reinterpret_cast<uint32_t*>(&h1));
}
__global__ void transpose_bf16_kernel(const float* __restrict__ in, __nv_bfloat16* __restrict__ out,
                                      int K, int N) {
    int idx = blockIdx.x * blockDim.x + threadIdx.x;
    if (idx >= K * N) return;
    int k = idx / N, n = idx % N;
    out[(size_t)n * K + k] = __float2bfloat16(in[idx]);
}
// 8 GAT weight transposes in one launch: slot -> (src matrix, dst slot)
__global__ void transpose_gat_kernel(const float* __restrict__ gWs, const float* __restrict__ gWd,
                                     __nv_bfloat16* __restrict__ wt) {
    int idx = blockIdx.x * blockDim.x + threadIdx.x;
    if (idx >= 256 * 128) return;
    int slot = blockIdx.y;   // 0..7
    // A-side: Ws0, Wd0, Wd1, Ws3 ; T-side: Ws1, Ws2, Wd2, Wd3
    const int useS[8] = {1, 0, 0, 1, 1, 1, 0, 0};
    const int gidx[8] = {0, 0, 1, 3, 1, 2, 2, 3};
    const float* src = (useS[slot] ? gWs : gWd) + (size_t)gidx[slot] * WSZ;
    __nv_bfloat16* dst = wt + OFF_WA + (size_t)slot * WSZ;
    int k = idx / 128, n = idx % 128;
    dst[(size_t)n * 256 + k] = __float2bfloat16(src[idx]);
}
__global__ void concat_bias_kernel(const float* __restrict__ gbs, const float* __restrict__ gbd,
                                   float* __restrict__ outa, float* __restrict__ outt) {
    int i = threadIdx.x;  // 128
    outa[i]       = gbs[0 * 128 + i];
    outa[128 + i] = gbd[0 * 128 + i];
    outa[256 + i] = gbd[1 * 128 + i];
    outa[384 + i] = gbs[3 * 128 + i];
    outt[i]       = gbs[1 * 128 + i];
    outt[128 + i] = gbs[2 * 128 + i];
    outt[256 + i] = gbd[2 * 128 + i];
    outt[384 + i] = gbd[3 * 128 + i];
}

// ================= pipelined HMMA GEMM =================
#define GSM_BIAS 65536
#define GSM_TOTAL (65536 + 512)

__device__ __forceinline__ void gemm_load_tile(
    uint32_t sb, uint32_t aOff, uint32_t bOff,
    const __nv_bfloat16* __restrict__ A, const __nv_bfloat16* __restrict__ Bt,
    int row0, int col0, int k0, int M, int K, int ldb, int tid)
{
#pragma unroll
    for (int it = 0; it < 4; it++) {
        int idx = it * 256 + tid;
        int r = idx >> 3, cc = idx & 7;
        uint32_t dst = sb + aOff + r * 128 + ((cc ^ (r & 7)) << 4);
        cp_async16(dst, A + (size_t)(row0 + r) * K + k0 + cc * 8, row0 + r < M);
    }
#pragma unroll
    for (int it = 0; it < 4; it++) {
        int idx = it * 256 + tid;
        int r = idx >> 3, cc = idx & 7;
        uint32_t dst = sb + bOff + r * 128 + ((cc ^ (r & 7)) << 4);
        cp_async16(dst, Bt + (size_t)(col0 + r) * ldb + k0 + cc * 8, true);
    }
}

template <int BF16OUT>
__global__ void __launch_bounds__(256) gemm_bf16(
    const __nv_bfloat16* __restrict__ A, const __nv_bfloat16* __restrict__ Bt,
    const float* __restrict__ bias, void* __restrict__ Cout,
    int M, int N, int K, int ldb)
{
    extern __shared__ char smem[];
    uint32_t sb = smem_u32(smem);
    const int tid = threadIdx.x;
    const int wid = tid >> 5, lane = tid & 31;
    const int wm = wid & 3, wn = wid >> 2;
    const int row0 = blockIdx.y * 128, col0 = blockIdx.x * 128;
    float* sbias = reinterpret_cast<float*>(smem + GSM_BIAS);

    if (tid < 128) sbias[tid] = bias ? __ldg(bias + col0 + tid) : 0.f;

    float c[2][8][4];
#pragma unroll
    for (int i = 0; i < 2; i++)
#pragma unroll
        for (int j = 0; j < 8; j++)
#pragma unroll
            for (int q = 0; q < 4; q++) c[i][j][q] = 0.f;

    const int niter = K >> 6;
    gemm_load_tile(sb, 0, 16384, A, Bt, row0, col0, 0, M, K, ldb, tid);
    CP_COMMIT();

    for (int it = 0; it < niter; it++) {
        const uint32_t aOff = (it & 1) * 32768u;
        const uint32_t bOff = aOff + 16384u;
        if (it + 1 < niter) {
            uint32_t a2 = ((it + 1) & 1) * 32768u;
            gemm_load_tile(sb, a2, a2 + 16384u, A, Bt, row0, col0, (it + 1) * 64, M, K, ldb, tid);
            CP_COMMIT();
            CP_WAIT1();
        } else {
            CP_WAIT0();
        }
        __syncthreads();

#pragma unroll
        for (int ks = 0; ks < 4; ks++) {
            uint32_t a[2][4];
#pragma unroll
            for (int mt = 0; mt < 2; mt++) {
                int ar = wm * 32 + mt * 16 + (lane & 15);
                int ch = ks * 2 + (lane >> 4);
                uint32_t addr = sb + aOff + ar * 128 + ((ch ^ (ar & 7)) << 4);
                asm volatile("ldmatrix.sync.aligned.m8n8.x4.shared.b16 {%0,%1,%2,%3}, [%4];"
                             : "=r"(a[mt][0]), "=r"(a[mt][1]), "=r"(a[mt][2]), "=r"(a[mt][3]) : "r"(addr));
            }
            uint32_t b[8][2];
#pragma unroll
            for (int nt = 0; nt < 8; nt++) {
                int br = wn * 64 + nt * 8 + (lane & 7);
                int ch = ks * 2 + ((lane >> 3) & 1);
                uint32_t addr = sb + bOff + br * 128 + ((ch ^ (br & 7)) << 4);
                asm volatile("ldmatrix.sync.aligned.m8n8.x2.shared.b16 {%0,%1}, [%2];"
                             : "=r"(b[nt][0]), "=r"(b[nt][1]) : "r"(addr));
            }
#pragma unroll
            for (int mt = 0; mt < 2; mt++)
#pragma unroll
                for (int nt = 0; nt < 8; nt++)
                    asm volatile(
                        "mma.sync.aligned.m16n8k16.row.col.f32.bf16.bf16.f32 "
                        "{%0,%1,%2,%3}, {%4,%5,%6,%7}, {%8,%9}, {%0,%1,%2,%3};"
                        : "+f"(c[mt][nt][0]), "+f"(c[mt][nt][1]), "+f"(c[mt][nt][2]), "+f"(c[mt][nt][3])
                        : "r"(a[mt][0]), "r"(a[mt][1]), "r"(a[mt][2]), "r"(a[mt][3]),
                          "r"(b[nt][0]), "r"(b[nt][1]));
        }
        __syncthreads();
    }

#pragma unroll
    for (int mt = 0; mt < 2; mt++) {
#pragma unroll
        for (int half = 0; half < 2; half++) {
            int gr = row0 + wm * 32 + mt * 16 + (lane >> 2) + half * 8;
            if (gr >= M) continue;
#pragma unroll
            for (int nt = 0; nt < 8; nt++) {
                int lc = wn * 64 + nt * 8 + (lane & 3) * 2;
                float v0 = c[mt][nt][half * 2 + 0] + sbias[lc];
                float v1 = c[mt][nt][half * 2 + 1] + sbias[lc + 1];
                if (BF16OUT) {
                    __nv_bfloat162 h = __floats2bfloat162_rn(v0, v1);
                    *reinterpret_cast<__nv_bfloat162*>(
                        reinterpret_cast<__nv_bfloat16*>(Cout) + (size_t)gr * N + col0 + lc) = h;
                } else {
                    *reinterpret_cast<float2*>(
                        reinterpret_cast<float*>(Cout) + (size_t)gr * N + col0 + lc) = make_float2(v0, v1);
                }
            }
        }
    }
}

// ================= semantic attention (all 4 metapaths in one launch) =================
__global__ void sematt_all(const __nv_bfloat16* __restrict__ zb,
                           const float* __restrict__ pW1, const float* __restrict__ pb1, const float* __restrict__ pW2,
                           const float* __restrict__ gW1, const float* __restrict__ gb1, const float* __restrict__ gW2,
                           float* __restrict__ watt)
{
    __shared__ float sz[8][128];
    __shared__ float sacc[8];
    int m = blockIdx.y;
    const __nv_bfloat16* z = zb + (size_t)m * NN * 128;
    const float* Wa = (m < 2) ? pW1 : gW1;
    const float* ba = (m < 2) ? pb1 : gb1;
    const float* Wo = (m < 2) ? pW2 : gW2;
    float* part = watt + m;

    int j = threadIdx.x;
    int r0 = blockIdx.x * 8;
    if (j < 8) sacc[j] = 0.f;
#pragma unroll
    for (int r = 0; r < 8; r++) {
        float v = __bfloat162float(z[(size_t)(r0 + r) * 128 + j]);
        sz[r][j] = v > 0.f ? v : 0.f;
    }
    __syncthreads();
    float bj = ba[j];
    float acc[8];
#pragma unroll
    for (int r = 0; r < 8; r++) acc[r] = bj;
    for (int k = 0; k < 128; k++) {
        float w = Wa[k * 128 + j];
#pragma unroll
        for (int r = 0; r < 8; r++) acc[r] = fmaf(sz[r][k], w, acc[r]);
    }
    float wo = Wo[j];
#pragma unroll
    for (int r = 0; r < 8; r++) {
        float t = fast_tanh(acc[r]) * wo;
        for (int o = 16; o > 0; o >>= 1) t += __shfl_down_sync(0xffffffffu, t, o);
        if ((j & 31) == 0) atomicAdd(&sacc[r], t);
    }
    __syncthreads();
    if (j == 0) {
        float tot = 0.f;
#pragma unroll
        for (int r = 0; r < 8; r++) tot += sacc[r];
        atomicAdd(part, tot);
    }
}

__global__ void compute_beta()
{
    for (int grp = 0; grp < 2; grp++) {
        float w0 = g_watt[2 * grp] * (1.f / NN);
        float w1 = g_watt[2 * grp + 1] * (1.f / NN);
        float m = fmaxf(w0, w1);
        float e0 = expf(w0 - m), e1 = expf(w1 - m);
        float inv = 1.f / (e0 + e1);
        g_beta[2 * grp] = e0 * inv;
        g_beta[2 * grp + 1] = e1 * inv;
    }
}

__global__ void combine_bf16(const __nv_bfloat16* __restrict__ z0, const __nv_bfloat16* __restrict__ z1,
                             __nv_bfloat16* __restrict__ out, int n2, int betaIdx)
{
    int i = blockIdx.x * blockDim.x + threadIdx.x;
    if (i >= n2) return;
    float b0 = g_beta[betaIdx], b1 = g_beta[betaIdx + 1];
    float2 a = __bfloat1622float2(reinterpret_cast<const __nv_bfloat162*>(z0)[i]);
    float2 c = __bfloat1622float2(reinterpret_cast<const __nv_bfloat162*>(z1)[i]);
    float o0 = b0 * fmaxf(a.x, 0.f) + b1 * fmaxf(c.x, 0.f);
    float o1 = b0 * fmaxf(a.y, 0.f) + b1 * fmaxf(c.y, 0.f);
    reinterpret_cast<__nv_bfloat162*>(out)[i] = __floats2bfloat162_rn(o0, o1);
}

// ================= predictor =================
__global__ void predict_kernel(const float* __restrict__ pa, const float* __restrict__ pt,
                               const int* __restrict__ src, const int* __restrict__ dst,
                               const float* __restrict__ b1, const float* __restrict__ W2,
                               const float* __restrict__ b2, float* __restrict__ out, int E)
{
    int gw = (blockIdx.x * blockDim.x + threadIdx.x) >> 5;
    int lane = threadIdx.x & 31;
    if (gw >= E) return;
    int s = src[gw], d = dst[gw];
    float4 a = __ldg(reinterpret_cast<const float4*>(pa) + (size_t)s * 32 + lane);
    float4 b = __ldg(reinterpret_cast<const float4*>(pt) + (size_t)d * 32 + lane);
    float4 bb = __ldg(reinterpret_cast<const float4*>(b1) + lane);
    float4 w = __ldg(reinterpret_cast<const float4*>(W2) + lane);
    float ux = fmaxf(a.x + b.x + bb.x, 0.f);
    float uy = fmaxf(a.y + b.y + bb.y, 0.f);
    float uz = fmaxf(a.z + b.z + bb.z, 0.f);
    float uw = fmaxf(a.w + b.w + bb.w, 0.f);
    float dot = ux * w.x + uy * w.y + uz * w.z + uw * w.w;
    for (int o = 16; o > 0; o >>= 1) dot += __shfl_down_sync(0xffffffffu, dot, o);
    if (lane == 0) out[gw] = 1.f / (1.f + expf(-(dot + b2[0])));
}

// ================= host =================
extern "C" void kernel_launch(void* const* d_in, const int* in_sizes, int n_in,
                              void* d_out, int out_size)
{
    const float* prot   = (const float*)d_in[0];
    const float* gen    = (const float*)d_in[1];
    const float* W1     = (const float*)d_in[2];
    const float* b1     = (const float*)d_in[3];
    const float* W2     = (const float*)d_in[4];
    const float* b2     = (const float*)d_in[5];
    const float* gWs    = (const float*)d_in[6];
    const float* gbs    = (const float*)d_in[7];
    const float* gWd    = (const float*)d_in[8];
    const float* gbd    = (const float*)d_in[9];
    const float* gattn  = (const float*)d_in[10];
    const float* pAW1   = (const float*)d_in[11];
    const float* pAb1   = (const float*)d_in[12];
    const float* pAW2   = (const float*)d_in[13];
    const float* gAW1   = (const float*)d_in[14];
    const float* gAb1   = (const float*)d_in[15];
    const float* gAW2   = (const float*)d_in[16];
    const float* predW1 = (const float*)d_in[17];
    const float* predb1 = (const float*)d_in[18];
    const float* predW2 = (const float*)d_in[19];
    const float* predb2 = (const float*)d_in[20];
    const int* e_aa = (const int*)d_in[21];
    const int* e_ta = (const int*)d_in[22];
    const int* e_tt = (const int*)d_in[23];
    const int* e_at = (const int*)d_in[24];
    const int* pos_e = (const int*)d_in[25];
    const int* neg_e = (const int*)d_in[26];
    float* out = (float*)d_out;

    __nv_bfloat16 *p_protb, *p_genb, *p_hab, *p_htb, *p_Fa, *p_Ft, *p_zb, *p_haoutb, *p_htoutb, *p_wt;
    float *p_pa, *p_pt, *p_watt, *p_biascat;
    int *p_deg, *p_off, *p_elist;
    cudaGetSymbolAddress((void**)&p_protb, g_protb);
    cudaGetSymbolAddress((void**)&p_genb, g_genb);
    cudaGetSymbolAddress((void**)&p_hab, g_hab);
    cudaGetSymbolAddress((void**)&p_htb, g_htb);
    cudaGetSymbolAddress((void**)&p_Fa, g_Fa);
    cudaGetSymbolAddress((void**)&p_Ft, g_Ft);
    cudaGetSymbolAddress((void**)&p_zb, g_zb);
    cudaGetSymbolAddress((void**)&p_haoutb, g_haoutb);
    cudaGetSymbolAddress((void**)&p_htoutb, g_htoutb);
    cudaGetSymbolAddress((void**)&p_wt, g_wt);
    cudaGetSymbolAddress((void**)&p_pa, g_pa);
    cudaGetSymbolAddress((void**)&p_pt, g_pt);
    cudaGetSymbolAddress((void**)&p_watt, g_watt);
    cudaGetSymbolAddress((void**)&p_biascat, g_biascat);
    cudaGetSymbolAddress((void**)&p_deg, g_deg);
    cudaGetSymbolAddress((void**)&p_off, g_off);
    cudaGetSymbolAddress((void**)&p_elist, g_elist);

    cudaFuncSetAttribute(gemm_bf16<1>, cudaFuncAttributeMaxDynamicSharedMemorySize, GSM_TOTAL);
    cudaFuncSetAttribute(gemm_bf16<0>, cudaFuncAttributeMaxDynamicSharedMemorySize, GSM_TOTAL);

    const int MR = (NN + 127) / 128;  // 391

    // launches ordered so #6 (ncu -s 5 -c 1) is the big protein GEMM
    f32_to_bf16_kernel<<<(NN * 1024 / 4 + 255) / 256, 256>>>(prot, p_protb, NN * 1024 / 4);   // 1
    transpose_bf16_kernel<<<(1024 * 256 + 255) / 256, 256>>>(W2, p_wt + OFF_W2T, 1024, 256);  // 2
    cudaMemsetAsync(p_deg, 0, sizeof(int) * 4 * NN);                                          // 3
    cudaMemsetAsync(p_watt, 0, sizeof(float) * 4);                                            // 4
    hist_kernel<<<dim3((EE + 255) / 256, 4), 256>>>(e_aa, e_ta, e_tt, e_at);                  // 5
    gemm_bf16<1><<<dim3(2, MR), 256, GSM_TOTAL>>>(p_protb, p_wt + OFF_W2T, b2, p_hab, NN, 256, 1024, 1024);  // 6 <- profiled
    scan_kernel<<<4, 1024>>>();                                                               // 7
    scatter_kernel<<<dim3((EE + 255) / 256, 4), 256>>>(e_aa, e_ta, e_tt, e_at);               // 8

    f32_to_bf16_kernel<<<(NN * 512 / 4 + 255) / 256, 256>>>(gen, p_genb, NN * 512 / 4);
    transpose_bf16_kernel<<<(512 * 256 + 255) / 256, 256>>>(W1, p_wt + OFF_W1T, 512, 256);
    concat_bias_kernel<<<1, 128>>>(gbs, gbd, p_biascat, p_biascat + 512);
    gemm_bf16<1><<<dim3(2, MR), 256, GSM_TOTAL>>>(p_genb, p_wt + OFF_W1T, b1, p_htb, NN, 256, 512, 512);

    transpose_gat_kernel<<<dim3((WSZ + 255) / 256, 8), 256>>>(gWs, gWd, p_wt);
    transpose_bf16_kernel<<<(256 * 128 + 255) / 256, 256>>>(predW1, p_wt + OFF_PW1, 256, 128);

    // batched GAT projections
    gemm_bf16<1><<<dim3(4, MR), 256, GSM_TOTAL>>>(p_hab, p_wt + OFF_WA,           p_biascat,       p_Fa, NN, 512, 256, 256);
    gemm_bf16<1><<<dim3(4, MR), 256, GSM_TOTAL>>>(p_htb, p_wt + OFF_WA + 4 * WSZ, p_biascat + 512, p_Ft, NN, 512, 256, 256);

    // single-pass GATv2 aggregation
    const __nv_bfloat16* FS[4] = { p_Fa + 0,   p_Ft + 0,   p_Ft + 128, p_Fa + 384 };
    const __nv_bfloat16* FD[4] = { p_Fa + 128, p_Fa + 256, p_Ft + 256, p_Ft + 384 };
    for (int g = 0; g < 4; g++) {
        gat_aggregate<<<(NN * 32 + 255) / 256, 256>>>(
            FS[g], FD[g], 128, gattn + g * 128,
            p_off + (size_t)g * NN, p_elist + (size_t)g * EE,
            p_zb + (size_t)g * NN * HIDF);
    }

    sematt_all<<<dim3(NN / 8, 4), 128>>>(p_zb, pAW1, pAb1, pAW2, gAW1, gAb1, gAW2, p_watt);
    compute_beta<<<1, 1>>>();

    combine_bf16<<<(NN * HIDF / 2 + 255) / 256, 256>>>(p_zb + 0 * (size_t)NN * HIDF, p_zb + 1 * (size_t)NN * HIDF, p_haoutb, NN * HIDF / 2, 0);
    combine_bf16<<<(NN * HIDF / 2 + 255) / 256, 256>>>(p_zb + 2 * (size_t)NN * HIDF, p_zb + 3 * (size_t)NN * HIDF, p_htoutb, NN * HIDF / 2, 2);

    gemm_bf16<0><<<dim3(1, MR), 256, GSM_TOTAL>>>(p_haoutb, p_wt + OFF_PW1,       nullptr, p_pa, NN, 128, 128, 256);
    gemm_bf16<0><<<dim3(1, MR), 256, GSM_TOTAL>>>(p_htoutb, p_wt + OFF_PW1 + 128, nullptr, p_pt, NN, 128, 128, 256);

    predict_kernel<<<(EP * 32 + 255) / 256, 256>>>(p_pa, p_pt, pos_e, pos_e + EP, predb1, predW2, predb2, out, EP);
    predict_kernel<<<(EP * 32 + 255) / 256, 256>>>(p_pa, p_pt, neg_e, neg_e + EP, predb1, predW2, predb2, out + EP, EP);
}

// round 9
// speedup vs baseline: 3.9870x; 1.3118x over previous
#include <cuda_runtime.h>
#include <cuda_bf16.h>
#include <math.h>
#include <cstdint>

#define NN 50000
#define EE 800000
#define EP 200000
#define HIDF 128

__device__ __forceinline__ uint32_t smem_u32(const void* p) {
    uint32_t a;
    asm("{ .reg .u64 t; cvta.to.shared.u64 t, %1; cvt.u32.u64 %0, t; }" : "=r"(a) : "l"(p));
    return a;
}
__device__ __forceinline__ void cp_async16(uint32_t s, const void* g, bool pred) {
    int sz = pred ? 16 : 0;
    asm volatile("cp.async.cg.shared.global [%0], [%1], 16, %2;" :: "r"(s), "l"(g), "r"(sz));
}
#define CP_COMMIT() asm volatile("cp.async.commit_group;" ::: "memory")
#define CP_WAIT1()  asm volatile("cp.async.wait_group 1;" ::: "memory")
#define CP_WAIT0()  asm volatile("cp.async.wait_group 0;" ::: "memory")
__device__ __forceinline__ float fast_tanh(float x) {
    float y;
    asm("tanh.approx.f32 %0, %1;" : "=f"(y) : "f"(x));
    return y;
}

// ================= scratch =================
__device__ __nv_bfloat16 g_protb[NN * 1024];
__device__ __nv_bfloat16 g_genb[NN * 512];
__device__ __nv_bfloat16 g_hab[NN * 256];
__device__ __nv_bfloat16 g_htb[NN * 256];
__device__ __nv_bfloat16 g_Fa[NN * 512];
__device__ __nv_bfloat16 g_Ft[NN * 512];
__device__ __nv_bfloat16 g_zb[4 * NN * HIDF];     // relu(z), bf16
__device__ __nv_bfloat16 g_haoutb[NN * 128];
__device__ __nv_bfloat16 g_htoutb[NN * 128];
__device__ __nv_bfloat16 g_pab[NN * 128];
__device__ __nv_bfloat16 g_ptb[NN * 128];
__device__ float g_watt[4];
__device__ float g_beta[4];
__device__ __nv_bfloat16 g_wt[720896];
__device__ float g_biascat[1024];
// CSR scratch
__device__ int g_deg[4 * NN];
__device__ int g_off[4 * NN];
__device__ int g_cur[4 * NN];
__device__ int g_elist[4 * EE];

#define OFF_W2T 0
#define OFF_W1T 262144
#define OFF_WA  393216
#define OFF_PW1 655360
#define OFF_SEM 688128
#define WSZ 32768   // 256*128

// ================= CSR build =================
__global__ void hist_kernel(const int* __restrict__ e0, const int* __restrict__ e1,
                            const int* __restrict__ e2, const int* __restrict__ e3) {
    int e = blockIdx.x * blockDim.x + threadIdx.x;
    if (e >= EE) return;
    int g = blockIdx.y;
    const int* eg = (g == 0) ? e0 : (g == 1) ? e1 : (g == 2) ? e2 : e3;
    atomicAdd(&g_deg[g * NN + eg[EE + e]], 1);
}

__global__ void scan_kernel() {
    __shared__ int sdata[1024];
    __shared__ int scarry;
    int g = blockIdx.x, tid = threadIdx.x;
    if (tid == 0) scarry = 0;
    __syncthreads();
    int base = g * NN;
    for (int c = 0; c < (NN + 1023) / 1024; c++) {
        int idx = c * 1024 + tid;
        int v = (idx < NN) ? g_deg[base + idx] : 0;
        sdata[tid] = v;
        __syncthreads();
        for (int o = 1; o < 1024; o <<= 1) {
            int t = (tid >= o) ? sdata[tid - o] : 0;
            __syncthreads();
            sdata[tid] += t;
            __syncthreads();
        }
        int excl = scarry + sdata[tid] - v;
        if (idx < NN) { g_off[base + idx] = excl; g_cur[base + idx] = excl; }
        __syncthreads();
        if (tid == 1023) scarry += sdata[1023];
        __syncthreads();
    }
}

__global__ void scatter_kernel(const int* __restrict__ e0, const int* __restrict__ e1,
                               const int* __restrict__ e2, const int* __restrict__ e3) {
    int e = blockIdx.x * blockDim.x + threadIdx.x;
    if (e >= EE) return;
    int g = blockIdx.y;
    const int* eg = (g == 0) ? e0 : (g == 1) ? e1 : (g == 2) ? e2 : e3;
    int s = eg[e], d = eg[EE + e];
    int pos = atomicAdd(&g_cur[g * NN + d], 1);
    g_elist[(size_t)g * EE + pos] = s;
}

// ================= fused single-pass GATv2 per-destination kernel =================
// writes relu(z) in bf16
__global__ void gat_aggregate(const __nv_bfloat16* __restrict__ fs, const __nv_bfloat16* __restrict__ fd,
                              int strideU2, const float* __restrict__ attn,
                              const int* __restrict__ off, const int* __restrict__ elist,
                              __nv_bfloat16* __restrict__ zout)
{
    int d = (blockIdx.x * blockDim.x + threadIdx.x) >> 5;
    int lane = threadIdx.x & 31;
    if (d >= NN) return;
    int base = off[d];
    int end = (d == NN - 1) ? EE : off[d + 1];
    uint2* zo = reinterpret_cast<uint2*>(zout) + (size_t)d * 32 + lane;

    if (base == end) { *zo = make_uint2(0u, 0u); return; }

    uint2 ud = __ldg(reinterpret_cast<const uint2*>(fd) + (size_t)d * strideU2 + lane);
    float2 d0 = __bfloat1622float2(*reinterpret_cast<__nv_bfloat162*>(&ud.x));
    float2 d1 = __bfloat1622float2(*reinterpret_cast<__nv_bfloat162*>(&ud.y));
    float4 at = __ldg(reinterpret_cast<const float4*>(attn) + lane);

    float ssum = 0.f;
    float acc0 = 0.f, acc1 = 0.f, acc2 = 0.f, acc3 = 0.f;
    for (int i = base; i < end; i++) {
        int s = elist[i];
        uint2 ua = __ldg(reinterpret_cast<const uint2*>(fs) + (size_t)s * strideU2 + lane);
        float2 a0 = __bfloat1622float2(*reinterpret_cast<__nv_bfloat162*>(&ua.x));
        float2 a1 = __bfloat1622float2(*reinterpret_cast<__nv_bfloat162*>(&ua.y));
        float vx = a0.x + d0.x, vy = a0.y + d0.y, vz = a1.x + d1.x, vw = a1.y + d1.y;
        vx = vx > 0.f ? vx : 0.2f * vx;
        vy = vy > 0.f ? vy : 0.2f * vy;
        vz = vz > 0.f ? vz : 0.2f * vz;
        vw = vw > 0.f ? vw : 0.2f * vw;
        float p = vx * at.x + vy * at.y + vz * at.z + vw * at.w;
        p += __shfl_xor_sync(0xffffffffu, p, 4);
        p += __shfl_xor_sync(0xffffffffu, p, 2);
        p += __shfl_xor_sync(0xffffffffu, p, 1);
        float ex = __expf(p);
        ssum += ex;
        acc0 = fmaf(ex, a0.x, acc0);
        acc1 = fmaf(ex, a0.y, acc1);
        acc2 = fmaf(ex, a1.x, acc2);
        acc3 = fmaf(ex, a1.y, acc3);
    }
    float inv = 1.f / ssum;
    __nv_bfloat162 h0 = __floats2bfloat162_rn(fmaxf(acc0 * inv, 0.f), fmaxf(acc1 * inv, 0.f));
    __nv_bfloat162 h1 = __floats2bfloat162_rn(fmaxf(acc2 * inv, 0.f), fmaxf(acc3 * inv, 0.f));
    *zo = make_uint2(*reinterpret_cast<uint32_t*>(&h0), *reinterpret_cast<uint32_t*>(&h1));
}

// ================= converts / transposes =================
__global__ void f32_to_bf16_kernel(const float* __restrict__ in, __nv_bfloat16* __restrict__ out, int n4) {
    int i = blockIdx.x * blockDim.x + threadIdx.x;
    if (i >= n4) return;
    float4 v = __ldg(reinterpret_cast<const float4*>(in) + i);
    __nv_bfloat162 h0 = __floats2bfloat162_rn(v.x, v.y);
    __nv_bfloat162 h1 = __floats2bfloat162_rn(v.z, v.w);
    reinterpret_cast<uint2*>(out)[i] =
        make_uint2(*reinterpret_cast<uint32_t*>(&h0), *reinterpret_cast<uint32_t*>(&h1));
}
__global__ void transpose_bf16_kernel(const float* __restrict__ in, __nv_bfloat16* __restrict__ out,
                                      int K, int N) {
    int idx = blockIdx.x * blockDim.x + threadIdx.x;
    if (idx >= K * N) return;
    int k = idx / N, n = idx % N;
    out[(size_t)n * K + k] = __float2bfloat16(in[idx]);
}
__global__ void transpose_gat_kernel(const float* __restrict__ gWs, const float* __restrict__ gWd,
                                     __nv_bfloat16* __restrict__ wt) {
    int idx = blockIdx.x * blockDim.x + threadIdx.x;
    if (idx >= 256 * 128) return;
    int slot = blockIdx.y;   // 0..7
    const int useS[8] = {1, 0, 0, 1, 1, 1, 0, 0};
    const int gidx[8] = {0, 0, 1, 3, 1, 2, 2, 3};
    const float* src = (useS[slot] ? gWs : gWd) + (size_t)gidx[slot] * WSZ;
    __nv_bfloat16* dst = wt + OFF_WA + (size_t)slot * WSZ;
    int k = idx / 128, n = idx % 128;
    dst[(size_t)n * 256 + k] = __float2bfloat16(src[idx]);
}
__global__ void concat_bias_kernel(const float* __restrict__ gbs, const float* __restrict__ gbd,
                                   float* __restrict__ outa, float* __restrict__ outt) {
    int i = threadIdx.x;  // 128
    outa[i]       = gbs[0 * 128 + i];
    outa[128 + i] = gbd[0 * 128 + i];
    outa[256 + i] = gbd[1 * 128 + i];
    outa[384 + i] = gbs[3 * 128 + i];
    outt[i]       = gbs[1 * 128 + i];
    outt[128 + i] = gbs[2 * 128 + i];
    outt[256 + i] = gbd[2 * 128 + i];
    outt[384 + i] = gbd[3 * 128 + i];
}

// ================= pipelined HMMA GEMM =================
#define GSM_BIAS 65536
#define GSM_TOTAL (65536 + 512)
#define SEM_SM_TOTAL (65536 + 1088)   // sba 512 + swo 512 + sred 64

__device__ __forceinline__ void gemm_load_tile(
    uint32_t sb, uint32_t aOff, uint32_t bOff,
    const __nv_bfloat16* __restrict__ A, const __nv_bfloat16* __restrict__ Bt,
    int row0, int col0, int k0, int M, int K, int ldb, int tid)
{
#pragma unroll
    for (int it = 0; it < 4; it++) {
        int idx = it * 256 + tid;
        int r = idx >> 3, cc = idx & 7;
        uint32_t dst = sb + aOff + r * 128 + ((cc ^ (r & 7)) << 4);
        cp_async16(dst, A + (size_t)(row0 + r) * K + k0 + cc * 8, row0 + r < M);
    }
#pragma unroll
    for (int it = 0; it < 4; it++) {
        int idx = it * 256 + tid;
        int r = idx >> 3, cc = idx & 7;
        uint32_t dst = sb + bOff + r * 128 + ((cc ^ (r & 7)) << 4);
        cp_async16(dst, Bt + (size_t)(col0 + r) * ldb + k0 + cc * 8, true);
    }
}

// shared MMA core: loads fragments for current buffer and accumulates
__device__ __forceinline__ void gemm_mma_chunk(uint32_t sb, uint32_t aOff, uint32_t bOff,
                                               int wm, int wn, int lane, float c[2][8][4])
{
#pragma unroll
    for (int ks = 0; ks < 4; ks++) {
        uint32_t a[2][4];
#pragma unroll
        for (int mt = 0; mt < 2; mt++) {
            int ar = wm * 32 + mt * 16 + (lane & 15);
            int ch = ks * 2 + (lane >> 4);
            uint32_t addr = sb + aOff + ar * 128 + ((ch ^ (ar & 7)) << 4);
            asm volatile("ldmatrix.sync.aligned.m8n8.x4.shared.b16 {%0,%1,%2,%3}, [%4];"
                         : "=r"(a[mt][0]), "=r"(a[mt][1]), "=r"(a[mt][2]), "=r"(a[mt][3]) : "r"(addr));
        }
#pragma unroll
        for (int nt = 0; nt < 8; nt++) {
            uint32_t b[2];
            int br = wn * 64 + nt * 8 + (lane & 7);
            int ch = ks * 2 + ((lane >> 3) & 1);
            uint32_t addr = sb + bOff + br * 128 + ((ch ^ (br & 7)) << 4);
            asm volatile("ldmatrix.sync.aligned.m8n8.x2.shared.b16 {%0,%1}, [%2];"
                         : "=r"(b[0]), "=r"(b[1]) : "r"(addr));
#pragma unroll
            for (int mt = 0; mt < 2; mt++)
                asm volatile(
                    "mma.sync.aligned.m16n8k16.row.col.f32.bf16.bf16.f32 "
                    "{%0,%1,%2,%3}, {%4,%5,%6,%7}, {%8,%9}, {%0,%1,%2,%3};"
                    : "+f"(c[mt][nt][0]), "+f"(c[mt][nt][1]), "+f"(c[mt][nt][2]), "+f"(c[mt][nt][3])
                    : "r"(a[mt][0]), "r"(a[mt][1]), "r"(a[mt][2]), "r"(a[mt][3]),
                      "r"(b[0]), "r"(b[1]));
        }
    }
}

template <int BF16OUT>
__global__ void __launch_bounds__(256, 2) gemm_bf16(
    const __nv_bfloat16* __restrict__ A, const __nv_bfloat16* __restrict__ Bt,
    const float* __restrict__ bias, void* __restrict__ Cout,
    int M, int N, int K, int ldb)
{
    extern __shared__ char smem[];
    uint32_t sb = smem_u32(smem);
    const int tid = threadIdx.x;
    const int wid = tid >> 5, lane = tid & 31;
    const int wm = wid & 3, wn = wid >> 2;
    const int row0 = blockIdx.y * 128, col0 = blockIdx.x * 128;
    float* sbias = reinterpret_cast<float*>(smem + GSM_BIAS);

    if (tid < 128) sbias[tid] = bias ? __ldg(bias + col0 + tid) : 0.f;

    float c[2][8][4];
#pragma unroll
    for (int i = 0; i < 2; i++)
#pragma unroll
        for (int j = 0; j < 8; j++)
#pragma unroll
            for (int q = 0; q < 4; q++) c[i][j][q] = 0.f;

    const int niter = K >> 6;
    gemm_load_tile(sb, 0, 16384, A, Bt, row0, col0, 0, M, K, ldb, tid);
    CP_COMMIT();

    for (int it = 0; it < niter; it++) {
        const uint32_t aOff = (it & 1) * 32768u;
        const uint32_t bOff = aOff + 16384u;
        if (it + 1 < niter) {
            uint32_t a2 = ((it + 1) & 1) * 32768u;
            gemm_load_tile(sb, a2, a2 + 16384u, A, Bt, row0, col0, (it + 1) * 64, M, K, ldb, tid);
            CP_COMMIT();
            CP_WAIT1();
        } else {
            CP_WAIT0();
        }
        __syncthreads();
        gemm_mma_chunk(sb, aOff, bOff, wm, wn, lane, c);
        __syncthreads();
    }

#pragma unroll
    for (int mt = 0; mt < 2; mt++) {
#pragma unroll
        for (int half = 0; half < 2; half++) {
            int gr = row0 + wm * 32 + mt * 16 + (lane >> 2) + half * 8;
            if (gr >= M) continue;
#pragma unroll
            for (int nt = 0; nt < 8; nt++) {
                int lc = wn * 64 + nt * 8 + (lane & 3) * 2;
                float v0 = c[mt][nt][half * 2 + 0] + sbias[lc];
                float v1 = c[mt][nt][half * 2 + 1] + sbias[lc + 1];
                if (BF16OUT) {
                    __nv_bfloat162 h = __floats2bfloat162_rn(v0, v1);
                    *reinterpret_cast<__nv_bfloat162*>(
                        reinterpret_cast<__nv_bfloat16*>(Cout) + (size_t)gr * N + col0 + lc) = h;
                } else {
                    *reinterpret_cast<float2*>(
                        reinterpret_cast<float*>(Cout) + (size_t)gr * N + col0 + lc) = make_float2(v0, v1);
                }
            }
        }
    }
}

// ================= semantic attention via HMMA =================
// watt[m] += sum over 128-row tile of tanh(relu(z)@Wa + ba) @ Wo
__global__ void __launch_bounds__(256, 2) sematt_gemm(
    const __nv_bfloat16* __restrict__ zb, const __nv_bfloat16* __restrict__ wt,
    const float* __restrict__ pb1, const float* __restrict__ pW2,
    const float* __restrict__ gb1, const float* __restrict__ gW2,
    float* __restrict__ watt)
{
    extern __shared__ char smem[];
    uint32_t sb = smem_u32(smem);
    const int tid = threadIdx.x;
    const int wid = tid >> 5, lane = tid & 31;
    const int wm = wid & 3, wn = wid >> 2;
    const int m = blockIdx.z;
    const int row0 = blockIdx.y * 128;

    const __nv_bfloat16* A = zb + (size_t)m * NN * 128;
    const __nv_bfloat16* Bt = wt + OFF_SEM + (m < 2 ? 0 : 16384);
    const float* ba = (m < 2) ? pb1 : gb1;
    const float* Wo = (m < 2) ? pW2 : gW2;

    float* sba = reinterpret_cast<float*>(smem + GSM_BIAS);       // 128 f
    float* swo = sba + 128;                                       // 128 f
    float* sred = swo + 128;                                      // 8 f (within 1088B pad)
    if (tid < 128) { sba[tid] = __ldg(ba + tid); swo[tid] = __ldg(Wo + tid); }

    float c[2][8][4];
#pragma unroll
    for (int i = 0; i < 2; i++)
#pragma unroll
        for (int j = 0; j < 8; j++)
#pragma unroll
            for (int q = 0; q < 4; q++) c[i][j][q] = 0.f;

    gemm_load_tile(sb, 0, 16384, A, Bt, row0, 0, 0, NN, 128, 128, tid);
    CP_COMMIT();
    gemm_load_tile(sb, 32768, 49152, A, Bt, row0, 0, 64, NN, 128, 128, tid);
    CP_COMMIT();
    CP_WAIT1();
    __syncthreads();
    gemm_mma_chunk(sb, 0, 16384, wm, wn, lane, c);
    CP_WAIT0();
    __syncthreads();
    gemm_mma_chunk(sb, 32768, 49152, wm, wn, lane, c);

    float lsum = 0.f;
#pragma unroll
    for (int mt = 0; mt < 2; mt++) {
#pragma unroll
        for (int half = 0; half < 2; half++) {
            int gr = row0 + wm * 32 + mt * 16 + (lane >> 2) + half * 8;
            if (gr >= NN) continue;
#pragma unroll
            for (int nt = 0; nt < 8; nt++) {
                int lc = wn * 64 + nt * 8 + (lane & 3) * 2;
                float v0 = c[mt][nt][half * 2 + 0] + sba[lc];
                float v1 = c[mt][nt][half * 2 + 1] + sba[lc + 1];
                lsum += fast_tanh(v0) * swo[lc] + fast_tanh(v1) * swo[lc + 1];
            }
        }
    }
#pragma unroll
    for (int o = 16; o > 0; o >>= 1) lsum += __shfl_xor_sync(0xffffffffu, lsum, o);
    if (lane == 0) sred[wid] = lsum;
    __syncthreads();
    if (tid == 0) {
        float tot = 0.f;
#pragma unroll
        for (int w = 0; w < 8; w++) tot += sred[w];
        atomicAdd(&watt[m], tot);
    }
}

__global__ void compute_beta()
{
    for (int grp = 0; grp < 2; grp++) {
        float w0 = g_watt[2 * grp] * (1.f / NN);
        float w1 = g_watt[2 * grp + 1] * (1.f / NN);
        float m = fmaxf(w0, w1);
        float e0 = expf(w0 - m), e1 = expf(w1 - m);
        float inv = 1.f / (e0 + e1);
        g_beta[2 * grp] = e0 * inv;
        g_beta[2 * grp + 1] = e1 * inv;
    }
}

// grid.y=2: group 0 -> haout from z0,z1; group 1 -> htout from z2,z3. z already relu'ed.
__global__ void combine_bf16(const __nv_bfloat16* __restrict__ zb,
                             __nv_bfloat16* __restrict__ outa, __nv_bfloat16* __restrict__ outt, int n2)
{
    int i = blockIdx.x * blockDim.x + threadIdx.x;
    if (i >= n2) return;
    int grp = blockIdx.y;
    const __nv_bfloat162* z0 = reinterpret_cast<const __nv_bfloat162*>(zb + (size_t)(2 * grp) * NN * 128);
    const __nv_bfloat162* z1 = reinterpret_cast<const __nv_bfloat162*>(zb + (size_t)(2 * grp + 1) * NN * 128);
    __nv_bfloat16* out = grp ? outt : outa;
    float b0 = g_beta[2 * grp], b1 = g_beta[2 * grp + 1];
    float2 a = __bfloat1622float2(z0[i]);
    float2 c = __bfloat1622float2(z1[i]);
    reinterpret_cast<__nv_bfloat162*>(out)[i] =
        __floats2bfloat162_rn(b0 * a.x + b1 * c.x, b0 * a.y + b1 * c.y);
}

// ================= predictor =================
__global__ void predict_kernel(const __nv_bfloat16* __restrict__ pa, const __nv_bfloat16* __restrict__ pt,
                               const int* __restrict__ src, const int* __restrict__ dst,
                               const float* __restrict__ b1, const float* __restrict__ W2,
                               const float* __restrict__ b2, float* __restrict__ out, int E)
{
    int gw = (blockIdx.x * blockDim.x + threadIdx.x) >> 5;
    int lane = threadIdx.x & 31;
    if (gw >= E) return;
    int s = src[gw], d = dst[gw];
    uint2 ua = __ldg(reinterpret_cast<const uint2*>(pa) + (size_t)s * 32 + lane);
    uint2 ub = __ldg(reinterpret_cast<const uint2*>(pt) + (size_t)d * 32 + lane);
    float4 bb = __ldg(reinterpret_cast<const float4*>(b1) + lane);
    float4 w = __ldg(reinterpret_cast<const float4*>(W2) + lane);
    float2 a0 = __bfloat1622float2(*reinterpret_cast<__nv_bfloat162*>(&ua.x));
    float2 a1 = __bfloat1622float2(*reinterpret_cast<__nv_bfloat162*>(&ua.y));
    float2 t0 = __bfloat1622float2(*reinterpret_cast<__nv_bfloat162*>(&ub.x));
    float2 t1 = __bfloat1622float2(*reinterpret_cast<__nv_bfloat162*>(&ub.y));
    float ux = fmaxf(a0.x + t0.x + bb.x, 0.f);
    float uy = fmaxf(a0.y + t0.y + bb.y, 0.f);
    float uz = fmaxf(a1.x + t1.x + bb.z, 0.f);
    float uw = fmaxf(a1.y + t1.y + bb.w, 0.f);
    float dot = ux * w.x + uy * w.y + uz * w.z + uw * w.w;
    for (int o = 16; o > 0; o >>= 1) dot += __shfl_down_sync(0xffffffffu, dot, o);
    if (lane == 0) out[gw] = 1.f / (1.f + expf(-(dot + b2[0])));
}

// ================= host =================
extern "C" void kernel_launch(void* const* d_in, const int* in_sizes, int n_in,
                              void* d_out, int out_size)
{
    const float* prot   = (const float*)d_in[0];
    const float* gen    = (const float*)d_in[1];
    const float* W1     = (const float*)d_in[2];
    const float* b1     = (const float*)d_in[3];
    const float* W2     = (const float*)d_in[4];
    const float* b2     = (const float*)d_in[5];
    const float* gWs    = (const float*)d_in[6];
    const float* gbs    = (const float*)d_in[7];
    const float* gWd    = (const float*)d_in[8];
    const float* gbd    = (const float*)d_in[9];
    const float* gattn  = (const float*)d_in[10];
    const float* pAW1   = (const float*)d_in[11];
    const float* pAb1   = (const float*)d_in[12];
    const float* pAW2   = (const float*)d_in[13];
    const float* gAW1   = (const float*)d_in[14];
    const float* gAb1   = (const float*)d_in[15];
    const float* gAW2   = (const float*)d_in[16];
    const float* predW1 = (const float*)d_in[17];
    const float* predb1 = (const float*)d_in[18];
    const float* predW2 = (const float*)d_in[19];
    const float* predb2 = (const float*)d_in[20];
    const int* e_aa = (const int*)d_in[21];
    const int* e_ta = (const int*)d_in[22];
    const int* e_tt = (const int*)d_in[23];
    const int* e_at = (const int*)d_in[24];
    const int* pos_e = (const int*)d_in[25];
    const int* neg_e = (const int*)d_in[26];
    float* out = (float*)d_out;

    __nv_bfloat16 *p_protb, *p_genb, *p_hab, *p_htb, *p_Fa, *p_Ft, *p_zb, *p_haoutb, *p_htoutb, *p_pab, *p_ptb, *p_wt;
    float *p_watt, *p_biascat;
    int *p_deg, *p_off, *p_elist;
    cudaGetSymbolAddress((void**)&p_protb, g_protb);
    cudaGetSymbolAddress((void**)&p_genb, g_genb);
    cudaGetSymbolAddress((void**)&p_hab, g_hab);
    cudaGetSymbolAddress((void**)&p_htb, g_htb);
    cudaGetSymbolAddress((void**)&p_Fa, g_Fa);
    cudaGetSymbolAddress((void**)&p_Ft, g_Ft);
    cudaGetSymbolAddress((void**)&p_zb, g_zb);
    cudaGetSymbolAddress((void**)&p_haoutb, g_haoutb);
    cudaGetSymbolAddress((void**)&p_htoutb, g_htoutb);
    cudaGetSymbolAddress((void**)&p_pab, g_pab);
    cudaGetSymbolAddress((void**)&p_ptb, g_ptb);
    cudaGetSymbolAddress((void**)&p_wt, g_wt);
    cudaGetSymbolAddress((void**)&p_watt, g_watt);
    cudaGetSymbolAddress((void**)&p_biascat, g_biascat);
    cudaGetSymbolAddress((void**)&p_deg, g_deg);
    cudaGetSymbolAddress((void**)&p_off, g_off);
    cudaGetSymbolAddress((void**)&p_elist, g_elist);

    cudaFuncSetAttribute(gemm_bf16<1>, cudaFuncAttributeMaxDynamicSharedMemorySize, GSM_TOTAL);
    cudaFuncSetAttribute(gemm_bf16<0>, cudaFuncAttributeMaxDynamicSharedMemorySize, GSM_TOTAL);
    cudaFuncSetAttribute(sematt_gemm, cudaFuncAttributeMaxDynamicSharedMemorySize, SEM_SM_TOTAL);

    const int MR = (NN + 127) / 128;  // 391

    // launches ordered so #6 (ncu -s 5 -c 1) is the big protein GEMM
    f32_to_bf16_kernel<<<(NN * 1024 / 4 + 255) / 256, 256>>>(prot, p_protb, NN * 1024 / 4);   // 1
    transpose_bf16_kernel<<<(1024 * 256 + 255) / 256, 256>>>(W2, p_wt + OFF_W2T, 1024, 256);  // 2
    cudaMemsetAsync(p_deg, 0, sizeof(int) * 4 * NN);                                          // 3
    cudaMemsetAsync(p_watt, 0, sizeof(float) * 4);                                            // 4
    hist_kernel<<<dim3((EE + 255) / 256, 4), 256>>>(e_aa, e_ta, e_tt, e_at);                  // 5
    gemm_bf16<1><<<dim3(2, MR), 256, GSM_TOTAL>>>(p_protb, p_wt + OFF_W2T, b2, p_hab, NN, 256, 1024, 1024);  // 6
    scan_kernel<<<4, 1024>>>();                                                               // 7
    scatter_kernel<<<dim3((EE + 255) / 256, 4), 256>>>(e_aa, e_ta, e_tt, e_at);               // 8

    f32_to_bf16_kernel<<<(NN * 512 / 4 + 255) / 256, 256>>>(gen, p_genb, NN * 512 / 4);
    transpose_bf16_kernel<<<(512 * 256 + 255) / 256, 256>>>(W1, p_wt + OFF_W1T, 512, 256);
    concat_bias_kernel<<<1, 128>>>(gbs, gbd, p_biascat, p_biascat + 512);
    gemm_bf16<1><<<dim3(2, MR), 256, GSM_TOTAL>>>(p_genb, p_wt + OFF_W1T, b1, p_htb, NN, 256, 512, 512);

    transpose_gat_kernel<<<dim3((WSZ + 255) / 256, 8), 256>>>(gWs, gWd, p_wt);
    transpose_bf16_kernel<<<(256 * 128 + 255) / 256, 256>>>(predW1, p_wt + OFF_PW1, 256, 128);
    transpose_bf16_kernel<<<(128 * 128 + 255) / 256, 256>>>(pAW1, p_wt + OFF_SEM, 128, 128);
    transpose_bf16_kernel<<<(128 * 128 + 255) / 256, 256>>>(gAW1, p_wt + OFF_SEM + 16384, 128, 128);

    // batched GAT projections
    gemm_bf16<1><<<dim3(4, MR), 256, GSM_TOTAL>>>(p_hab, p_wt + OFF_WA,           p_biascat,       p_Fa, NN, 512, 256, 256);
    gemm_bf16<1><<<dim3(4, MR), 256, GSM_TOTAL>>>(p_htb, p_wt + OFF_WA + 4 * WSZ, p_biascat + 512, p_Ft, NN, 512, 256, 256);

    // single-pass GATv2 aggregation (writes relu(z) bf16)
    const __nv_bfloat16* FS[4] = { p_Fa + 0,   p_Ft + 0,   p_Ft + 128, p_Fa + 384 };
    const __nv_bfloat16* FD[4] = { p_Fa + 128, p_Fa + 256, p_Ft + 256, p_Ft + 384 };
    for (int g = 0; g < 4; g++) {
        gat_aggregate<<<(NN * 32 + 255) / 256, 256>>>(
            FS[g], FD[g], 128, gattn + g * 128,
            p_off + (size_t)g * NN, p_elist + (size_t)g * EE,
            p_zb + (size_t)g * NN * HIDF);
    }

    // semantic attention on tensor cores
    sematt_gemm<<<dim3(1, MR, 4), 256, SEM_SM_TOTAL>>>(p_zb, p_wt, pAb1, pAW2, gAb1, gAW2, p_watt);
    compute_beta<<<1, 1>>>();

    combine_bf16<<<dim3((NN * HIDF / 2 + 255) / 256, 2), 256>>>(p_zb, p_haoutb, p_htoutb, NN * HIDF / 2);

    gemm_bf16<1><<<dim3(1, MR), 256, GSM_TOTAL>>>(p_haoutb, p_wt + OFF_PW1,       nullptr, p_pab, NN, 128, 128, 256);
    gemm_bf16<1><<<dim3(1, MR), 256, GSM_TOTAL>>>(p_htoutb, p_wt + OFF_PW1 + 128, nullptr, p_ptb, NN, 128, 128, 256);

    predict_kernel<<<(EP * 32 + 255) / 256, 256>>>(p_pab, p_ptb, pos_e, pos_e + EP, predb1, predW2, predb2, out, EP);
    predict_kernel<<<(EP * 32 + 255) / 256, 256>>>(p_pab, p_ptb, neg_e, neg_e + EP, predb1, predW2, predb2, out + EP, EP);
}

// round 10
// speedup vs baseline: 4.2386x; 1.0631x over previous
#include <cuda_runtime.h>
#include <cuda_bf16.h>
#include <math.h>
#include <cstdint>

#define NN 50000
#define EE 800000
#define EP 200000
#define HIDF 128

__device__ __forceinline__ uint32_t smem_u32(const void* p) {
    uint32_t a;
    asm("{ .reg .u64 t; cvta.to.shared.u64 t, %1; cvt.u32.u64 %0, t; }" : "=r"(a) : "l"(p));
    return a;
}
__device__ __forceinline__ void cp_async16(uint32_t s, const void* g, bool pred) {
    int sz = pred ? 16 : 0;
    asm volatile("cp.async.cg.shared.global [%0], [%1], 16, %2;" :: "r"(s), "l"(g), "r"(sz));
}
#define CP_COMMIT() asm volatile("cp.async.commit_group;" ::: "memory")
#define CP_WAIT1()  asm volatile("cp.async.wait_group 1;" ::: "memory")
#define CP_WAIT0()  asm volatile("cp.async.wait_group 0;" ::: "memory")
__device__ __forceinline__ float fast_tanh(float x) {
    float y;
    asm("tanh.approx.f32 %0, %1;" : "=f"(y) : "f"(x));
    return y;
}

// ================= scratch =================
__device__ __nv_bfloat16 g_protb[NN * 1024];
__device__ __nv_bfloat16 g_genb[NN * 512];
__device__ __nv_bfloat16 g_hab[NN * 256];
__device__ __nv_bfloat16 g_htb[NN * 256];
__device__ __nv_bfloat16 g_Fa[NN * 512];
__device__ __nv_bfloat16 g_Ft[NN * 512];
__device__ __nv_bfloat16 g_zb[4 * NN * HIDF];     // relu(z), bf16
__device__ __nv_bfloat16 g_haoutb[NN * 128];
__device__ __nv_bfloat16 g_htoutb[NN * 128];
__device__ __nv_bfloat16 g_pab[NN * 128];
__device__ __nv_bfloat16 g_ptb[NN * 128];
__device__ float g_watt[4];
__device__ float g_beta[4];
__device__ __nv_bfloat16 g_wt[720896];
__device__ float g_biascat[1024];
// CSR scratch
__device__ int g_deg[4 * NN];
__device__ int g_off[4 * NN];
__device__ int g_cur[4 * NN];
__device__ int g_elist[4 * EE];

#define OFF_W2T 0
#define OFF_W1T 262144
#define OFF_WA  393216
#define OFF_PW1 655360
#define OFF_SEM 688128
#define WSZ 32768   // 256*128

// ================= CSR build =================
__global__ void hist_kernel(const int* __restrict__ e0, const int* __restrict__ e1,
                            const int* __restrict__ e2, const int* __restrict__ e3) {
    int e = blockIdx.x * blockDim.x + threadIdx.x;
    if (e >= EE) return;
    int g = blockIdx.y;
    const int* eg = (g == 0) ? e0 : (g == 1) ? e1 : (g == 2) ? e2 : e3;
    atomicAdd(&g_deg[g * NN + eg[EE + e]], 1);
}

__global__ void scan_kernel() {
    __shared__ int sdata[1024];
    __shared__ int scarry;
    int g = blockIdx.x, tid = threadIdx.x;
    if (tid == 0) scarry = 0;
    __syncthreads();
    int base = g * NN;
    for (int c = 0; c < (NN + 1023) / 1024; c++) {
        int idx = c * 1024 + tid;
        int v = (idx < NN) ? g_deg[base + idx] : 0;
        sdata[tid] = v;
        __syncthreads();
        for (int o = 1; o < 1024; o <<= 1) {
            int t = (tid >= o) ? sdata[tid - o] : 0;
            __syncthreads();
            sdata[tid] += t;
            __syncthreads();
        }
        int excl = scarry + sdata[tid] - v;
        if (idx < NN) { g_off[base + idx] = excl; g_cur[base + idx] = excl; }
        __syncthreads();
        if (tid == 1023) scarry += sdata[1023];
        __syncthreads();
    }
}

__global__ void scatter_kernel(const int* __restrict__ e0, const int* __restrict__ e1,
                               const int* __restrict__ e2, const int* __restrict__ e3) {
    int e = blockIdx.x * blockDim.x + threadIdx.x;
    if (e >= EE) return;
    int g = blockIdx.y;
    const int* eg = (g == 0) ? e0 : (g == 1) ? e1 : (g == 2) ? e2 : e3;
    int s = eg[e], d = eg[EE + e];
    int pos = atomicAdd(&g_cur[g * NN + d], 1);
    g_elist[(size_t)g * EE + pos] = s;
}

// ================= fused single-pass GATv2 per-destination kernel =================
// z[d] = relu( (sum ex_i * fs_i) / (sum ex_i) ), bf16; 2-way unrolled gather loop.
__global__ void gat_aggregate(const __nv_bfloat16* __restrict__ fs, const __nv_bfloat16* __restrict__ fd,
                              int strideU2, const float* __restrict__ attn,
                              const int* __restrict__ off, const int* __restrict__ elist,
                              __nv_bfloat16* __restrict__ zout)
{
    int d = (blockIdx.x * blockDim.x + threadIdx.x) >> 5;
    int lane = threadIdx.x & 31;
    if (d >= NN) return;
    int base = off[d];
    int end = (d == NN - 1) ? EE : off[d + 1];
    uint2* zo = reinterpret_cast<uint2*>(zout) + (size_t)d * 32 + lane;

    if (base == end) { *zo = make_uint2(0u, 0u); return; }

    uint2 ud = __ldg(reinterpret_cast<const uint2*>(fd) + (size_t)d * strideU2 + lane);
    float2 d0 = __bfloat1622float2(*reinterpret_cast<__nv_bfloat162*>(&ud.x));
    float2 d1 = __bfloat1622float2(*reinterpret_cast<__nv_bfloat162*>(&ud.y));
    float4 at = __ldg(reinterpret_cast<const float4*>(attn) + lane);

    float ssum = 0.f;
    float acc0 = 0.f, acc1 = 0.f, acc2 = 0.f, acc3 = 0.f;

    int i = base;
    for (; i + 2 <= end; i += 2) {
        int s0 = elist[i], s1 = elist[i + 1];
        uint2 u0 = __ldg(reinterpret_cast<const uint2*>(fs) + (size_t)s0 * strideU2 + lane);
        uint2 u1 = __ldg(reinterpret_cast<const uint2*>(fs) + (size_t)s1 * strideU2 + lane);
        float2 a0 = __bfloat1622float2(*reinterpret_cast<__nv_bfloat162*>(&u0.x));
        float2 a1 = __bfloat1622float2(*reinterpret_cast<__nv_bfloat162*>(&u0.y));
        float2 b0 = __bfloat1622float2(*reinterpret_cast<__nv_bfloat162*>(&u1.x));
        float2 b1 = __bfloat1622float2(*reinterpret_cast<__nv_bfloat162*>(&u1.y));
        float px, py, pz, pw, qx, qy, qz, qw;
        px = a0.x + d0.x; py = a0.y + d0.y; pz = a1.x + d1.x; pw = a1.y + d1.y;
        qx = b0.x + d0.x; qy = b0.y + d0.y; qz = b1.x + d1.x; qw = b1.y + d1.y;
        px = px > 0.f ? px : 0.2f * px;  py = py > 0.f ? py : 0.2f * py;
        pz = pz > 0.f ? pz : 0.2f * pz;  pw = pw > 0.f ? pw : 0.2f * pw;
        qx = qx > 0.f ? qx : 0.2f * qx;  qy = qy > 0.f ? qy : 0.2f * qy;
        qz = qz > 0.f ? qz : 0.2f * qz;  qw = qw > 0.f ? qw : 0.2f * qw;
        float p = px * at.x + py * at.y + pz * at.z + pw * at.w;
        float q = qx * at.x + qy * at.y + qz * at.z + qw * at.w;
        p += __shfl_xor_sync(0xffffffffu, p, 4);
        q += __shfl_xor_sync(0xffffffffu, q, 4);
        p += __shfl_xor_sync(0xffffffffu, p, 2);
        q += __shfl_xor_sync(0xffffffffu, q, 2);
        p += __shfl_xor_sync(0xffffffffu, p, 1);
        q += __shfl_xor_sync(0xffffffffu, q, 1);
        float e0 = __expf(p), e1 = __expf(q);
        ssum += e0 + e1;
        acc0 = fmaf(e0, a0.x, fmaf(e1, b0.x, acc0));
        acc1 = fmaf(e0, a0.y, fmaf(e1, b0.y, acc1));
        acc2 = fmaf(e0, a1.x, fmaf(e1, b1.x, acc2));
        acc3 = fmaf(e0, a1.y, fmaf(e1, b1.y, acc3));
    }
    if (i < end) {
        int s = elist[i];
        uint2 ua = __ldg(reinterpret_cast<const uint2*>(fs) + (size_t)s * strideU2 + lane);
        float2 a0 = __bfloat1622float2(*reinterpret_cast<__nv_bfloat162*>(&ua.x));
        float2 a1 = __bfloat1622float2(*reinterpret_cast<__nv_bfloat162*>(&ua.y));
        float vx = a0.x + d0.x, vy = a0.y + d0.y, vz = a1.x + d1.x, vw = a1.y + d1.y;
        vx = vx > 0.f ? vx : 0.2f * vx;
        vy = vy > 0.f ? vy : 0.2f * vy;
        vz = vz > 0.f ? vz : 0.2f * vz;
        vw = vw > 0.f ? vw : 0.2f * vw;
        float p = vx * at.x + vy * at.y + vz * at.z + vw * at.w;
        p += __shfl_xor_sync(0xffffffffu, p, 4);
        p += __shfl_xor_sync(0xffffffffu, p, 2);
        p += __shfl_xor_sync(0xffffffffu, p, 1);
        float ex = __expf(p);
        ssum += ex;
        acc0 = fmaf(ex, a0.x, acc0);
        acc1 = fmaf(ex, a0.y, acc1);
        acc2 = fmaf(ex, a1.x, acc2);
        acc3 = fmaf(ex, a1.y, acc3);
    }
    float inv = 1.f / ssum;
    __nv_bfloat162 h0 = __floats2bfloat162_rn(fmaxf(acc0 * inv, 0.f), fmaxf(acc1 * inv, 0.f));
    __nv_bfloat162 h1 = __floats2bfloat162_rn(fmaxf(acc2 * inv, 0.f), fmaxf(acc3 * inv, 0.f));
    *zo = make_uint2(*reinterpret_cast<uint32_t*>(&h0), *reinterpret_cast<uint32_t*>(&h1));
}

// ================= converts / transposes =================
__global__ void f32_to_bf16_kernel(const float* __restrict__ in, __nv_bfloat16* __restrict__ out, int n4) {
    int i = blockIdx.x * blockDim.x + threadIdx.x;
    if (i >= n4) return;
    float4 v = __ldg(reinterpret_cast<const float4*>(in) + i);
    __nv_bfloat162 h0 = __floats2bfloat162_rn(v.x, v.y);
    __nv_bfloat162 h1 = __floats2bfloat162_rn(v.z, v.w);
    reinterpret_cast<uint2*>(out)[i] =
        make_uint2(*reinterpret_cast<uint32_t*>(&h0), *reinterpret_cast<uint32_t*>(&h1));
}
__global__ void transpose_bf16_kernel(const float* __restrict__ in, __nv_bfloat16* __restrict__ out,
                                      int K, int N) {
    int idx = blockIdx.x * blockDim.x + threadIdx.x;
    if (idx >= K * N) return;
    int k = idx / N, n = idx % N;
    out[(size_t)n * K + k] = __float2bfloat16(in[idx]);
}
__global__ void transpose_gat_kernel(const float* __restrict__ gWs, const float* __restrict__ gWd,
                                     __nv_bfloat16* __restrict__ wt) {
    int idx = blockIdx.x * blockDim.x + threadIdx.x;
    if (idx >= 256 * 128) return;
    int slot = blockIdx.y;   // 0..7
    const int useS[8] = {1, 0, 0, 1, 1, 1, 0, 0};
    const int gidx[8] = {0, 0, 1, 3, 1, 2, 2, 3};
    const float* src = (useS[slot] ? gWs : gWd) + (size_t)gidx[slot] * WSZ;
    __nv_bfloat16* dst = wt + OFF_WA + (size_t)slot * WSZ;
    int k = idx / 128, n = idx % 128;
    dst[(size_t)n * 256 + k] = __float2bfloat16(src[idx]);
}
__global__ void concat_bias_kernel(const float* __restrict__ gbs, const float* __restrict__ gbd,
                                   float* __restrict__ outa, float* __restrict__ outt) {
    int i = threadIdx.x;  // 128
    outa[i]       = gbs[0 * 128 + i];
    outa[128 + i] = gbd[0 * 128 + i];
    outa[256 + i] = gbd[1 * 128 + i];
    outa[384 + i] = gbs[3 * 128 + i];
    outt[i]       = gbs[1 * 128 + i];
    outt[128 + i] = gbs[2 * 128 + i];
    outt[256 + i] = gbd[2 * 128 + i];
    outt[384 + i] = gbd[3 * 128 + i];
}

// ================= pipelined HMMA GEMM =================
#define GSM_BIAS 65536
#define GSM_TOTAL (65536 + 512)
#define SEM_SM_TOTAL (65536 + 1088)

__device__ __forceinline__ void gemm_load_tile(
    uint32_t sb, uint32_t aOff, uint32_t bOff,
    const __nv_bfloat16* __restrict__ A, const __nv_bfloat16* __restrict__ Bt,
    int row0, int col0, int k0, int M, int K, int ldb, int tid)
{
#pragma unroll
    for (int it = 0; it < 4; it++) {
        int idx = it * 256 + tid;
        int r = idx >> 3, cc = idx & 7;
        uint32_t dst = sb + aOff + r * 128 + ((cc ^ (r & 7)) << 4);
        cp_async16(dst, A + (size_t)(row0 + r) * K + k0 + cc * 8, row0 + r < M);
    }
#pragma unroll
    for (int it = 0; it < 4; it++) {
        int idx = it * 256 + tid;
        int r = idx >> 3, cc = idx & 7;
        uint32_t dst = sb + bOff + r * 128 + ((cc ^ (r & 7)) << 4);
        cp_async16(dst, Bt + (size_t)(col0 + r) * ldb + k0 + cc * 8, true);
    }
}

// MMA core: A via 2x ldmatrix.x4, B via 4x ldmatrix.x4 (two n-tiles per load)
__device__ __forceinline__ void gemm_mma_chunk(uint32_t sb, uint32_t aOff, uint32_t bOff,
                                               int wm, int wn, int lane, float c[2][8][4])
{
#pragma unroll
    for (int ks = 0; ks < 4; ks++) {
        uint32_t a[2][4];
#pragma unroll
        for (int mt = 0; mt < 2; mt++) {
            int ar = wm * 32 + mt * 16 + (lane & 15);
            int ch = ks * 2 + (lane >> 4);
            uint32_t addr = sb + aOff + ar * 128 + ((ch ^ (ar & 7)) << 4);
            asm volatile("ldmatrix.sync.aligned.m8n8.x4.shared.b16 {%0,%1,%2,%3}, [%4];"
                         : "=r"(a[mt][0]), "=r"(a[mt][1]), "=r"(a[mt][2]), "=r"(a[mt][3]) : "r"(addr));
        }
#pragma unroll
        for (int nt = 0; nt < 8; nt += 2) {
            uint32_t b[4];
            // lanes 0-15 -> tile nt (k-half = bit3), lanes 16-31 -> tile nt+1
            int ntl = nt + (lane >> 4);
            int br = wn * 64 + ntl * 8 + (lane & 7);
            int ch = ks * 2 + ((lane >> 3) & 1);
            uint32_t addr = sb + bOff + br * 128 + ((ch ^ (br & 7)) << 4);
            asm volatile("ldmatrix.sync.aligned.m8n8.x4.shared.b16 {%0,%1,%2,%3}, [%4];"
                         : "=r"(b[0]), "=r"(b[1]), "=r"(b[2]), "=r"(b[3]) : "r"(addr));
#pragma unroll
            for (int mt = 0; mt < 2; mt++) {
                asm volatile(
                    "mma.sync.aligned.m16n8k16.row.col.f32.bf16.bf16.f32 "
                    "{%0,%1,%2,%3}, {%4,%5,%6,%7}, {%8,%9}, {%0,%1,%2,%3};"
                    : "+f"(c[mt][nt][0]), "+f"(c[mt][nt][1]), "+f"(c[mt][nt][2]), "+f"(c[mt][nt][3])
                    : "r"(a[mt][0]), "r"(a[mt][1]), "r"(a[mt][2]), "r"(a[mt][3]),
                      "r"(b[0]), "r"(b[1]));
                asm volatile(
                    "mma.sync.aligned.m16n8k16.row.col.f32.bf16.bf16.f32 "
                    "{%0,%1,%2,%3}, {%4,%5,%6,%7}, {%8,%9}, {%0,%1,%2,%3};"
                    : "+f"(c[mt][nt + 1][0]), "+f"(c[mt][nt + 1][1]), "+f"(c[mt][nt + 1][2]), "+f"(c[mt][nt + 1][3])
                    : "r"(a[mt][0]), "r"(a[mt][1]), "r"(a[mt][2]), "r"(a[mt][3]),
                      "r"(b[2]), "r"(b[3]));
            }
        }
    }
}

template <int BF16OUT>
__global__ void __launch_bounds__(256, 2) gemm_bf16(
    const __nv_bfloat16* __restrict__ A, const __nv_bfloat16* __restrict__ Bt,
    const float* __restrict__ bias, void* __restrict__ Cout,
    int M, int N, int K, int ldb)
{
    extern __shared__ char smem[];
    uint32_t sb = smem_u32(smem);
    const int tid = threadIdx.x;
    const int wid = tid >> 5, lane = tid & 31;
    const int wm = wid & 3, wn = wid >> 2;
    const int row0 = blockIdx.y * 128, col0 = blockIdx.x * 128;
    float* sbias = reinterpret_cast<float*>(smem + GSM_BIAS);

    if (tid < 128) sbias[tid] = bias ? __ldg(bias + col0 + tid) : 0.f;

    float c[2][8][4];
#pragma unroll
    for (int i = 0; i < 2; i++)
#pragma unroll
        for (int j = 0; j < 8; j++)
#pragma unroll
            for (int q = 0; q < 4; q++) c[i][j][q] = 0.f;

    const int niter = K >> 6;
    gemm_load_tile(sb, 0, 16384, A, Bt, row0, col0, 0, M, K, ldb, tid);
    CP_COMMIT();

    for (int it = 0; it < niter; it++) {
        const uint32_t aOff = (it & 1) * 32768u;
        const uint32_t bOff = aOff + 16384u;
        if (it + 1 < niter) {
            uint32_t a2 = ((it + 1) & 1) * 32768u;
            gemm_load_tile(sb, a2, a2 + 16384u, A, Bt, row0, col0, (it + 1) * 64, M, K, ldb, tid);
            CP_COMMIT();
            CP_WAIT1();
        } else {
            CP_WAIT0();
        }
        __syncthreads();
        gemm_mma_chunk(sb, aOff, bOff, wm, wn, lane, c);
        __syncthreads();
    }

#pragma unroll
    for (int mt = 0; mt < 2; mt++) {
#pragma unroll
        for (int half = 0; half < 2; half++) {
            int gr = row0 + wm * 32 + mt * 16 + (lane >> 2) + half * 8;
            if (gr >= M) continue;
#pragma unroll
            for (int nt = 0; nt < 8; nt++) {
                int lc = wn * 64 + nt * 8 + (lane & 3) * 2;
                float v0 = c[mt][nt][half * 2 + 0] + sbias[lc];
                float v1 = c[mt][nt][half * 2 + 1] + sbias[lc + 1];
                if (BF16OUT) {
                    __nv_bfloat162 h = __floats2bfloat162_rn(v0, v1);
                    *reinterpret_cast<__nv_bfloat162*>(
                        reinterpret_cast<__nv_bfloat16*>(Cout) + (size_t)gr * N + col0 + lc) = h;
                } else {
                    *reinterpret_cast<float2*>(
                        reinterpret_cast<float*>(Cout) + (size_t)gr * N + col0 + lc) = make_float2(v0, v1);
                }
            }
        }
    }
}

// ================= semantic attention via HMMA =================
__global__ void __launch_bounds__(256, 2) sematt_gemm(
    const __nv_bfloat16* __restrict__ zb, const __nv_bfloat16* __restrict__ wt,
    const float* __restrict__ pb1, const float* __restrict__ pW2,
    const float* __restrict__ gb1, const float* __restrict__ gW2,
    float* __restrict__ watt)
{
    extern __shared__ char smem[];
    uint32_t sb = smem_u32(smem);
    const int tid = threadIdx.x;
    const int wid = tid >> 5, lane = tid & 31;
    const int wm = wid & 3, wn = wid >> 2;
    const int m = blockIdx.z;
    const int row0 = blockIdx.y * 128;

    const __nv_bfloat16* A = zb + (size_t)m * NN * 128;
    const __nv_bfloat16* Bt = wt + OFF_SEM + (m < 2 ? 0 : 16384);
    const float* ba = (m < 2) ? pb1 : gb1;
    const float* Wo = (m < 2) ? pW2 : gW2;

    float* sba = reinterpret_cast<float*>(smem + GSM_BIAS);
    float* swo = sba + 128;
    float* sred = swo + 128;
    if (tid < 128) { sba[tid] = __ldg(ba + tid); swo[tid] = __ldg(Wo + tid); }

    float c[2][8][4];
#pragma unroll
    for (int i = 0; i < 2; i++)
#pragma unroll
        for (int j = 0; j < 8; j++)
#pragma unroll
            for (int q = 0; q < 4; q++) c[i][j][q] = 0.f;

    gemm_load_tile(sb, 0, 16384, A, Bt, row0, 0, 0, NN, 128, 128, tid);
    CP_COMMIT();
    gemm_load_tile(sb, 32768, 49152, A, Bt, row0, 0, 64, NN, 128, 128, tid);
    CP_COMMIT();
    CP_WAIT1();
    __syncthreads();
    gemm_mma_chunk(sb, 0, 16384, wm, wn, lane, c);
    CP_WAIT0();
    __syncthreads();
    gemm_mma_chunk(sb, 32768, 49152, wm, wn, lane, c);

    float lsum = 0.f;
#pragma unroll
    for (int mt = 0; mt < 2; mt++) {
#pragma unroll
        for (int half = 0; half < 2; half++) {
            int gr = row0 + wm * 32 + mt * 16 + (lane >> 2) + half * 8;
            if (gr >= NN) continue;
#pragma unroll
            for (int nt = 0; nt < 8; nt++) {
                int lc = wn * 64 + nt * 8 + (lane & 3) * 2;
                float v0 = c[mt][nt][half * 2 + 0] + sba[lc];
                float v1 = c[mt][nt][half * 2 + 1] + sba[lc + 1];
                lsum += fast_tanh(v0) * swo[lc] + fast_tanh(v1) * swo[lc + 1];
            }
        }
    }
#pragma unroll
    for (int o = 16; o > 0; o >>= 1) lsum += __shfl_xor_sync(0xffffffffu, lsum, o);
    if (lane == 0) sred[wid] = lsum;
    __syncthreads();
    if (tid == 0) {
        float tot = 0.f;
#pragma unroll
        for (int w = 0; w < 8; w++) tot += sred[w];
        atomicAdd(&watt[m], tot);
    }
}

__global__ void compute_beta()
{
    for (int grp = 0; grp < 2; grp++) {
        float w0 = g_watt[2 * grp] * (1.f / NN);
        float w1 = g_watt[2 * grp + 1] * (1.f / NN);
        float m = fmaxf(w0, w1);
        float e0 = expf(w0 - m), e1 = expf(w1 - m);
        float inv = 1.f / (e0 + e1);
        g_beta[2 * grp] = e0 * inv;
        g_beta[2 * grp + 1] = e1 * inv;
    }
}

__global__ void combine_bf16(const __nv_bfloat16* __restrict__ zb,
                             __nv_bfloat16* __restrict__ outa, __nv_bfloat16* __restrict__ outt, int n2)
{
    int i = blockIdx.x * blockDim.x + threadIdx.x;
    if (i >= n2) return;
    int grp = blockIdx.y;
    const __nv_bfloat162* z0 = reinterpret_cast<const __nv_bfloat162*>(zb + (size_t)(2 * grp) * NN * 128);
    const __nv_bfloat162* z1 = reinterpret_cast<const __nv_bfloat162*>(zb + (size_t)(2 * grp + 1) * NN * 128);
    __nv_bfloat16* out = grp ? outt : outa;
    float b0 = g_beta[2 * grp], b1 = g_beta[2 * grp + 1];
    float2 a = __bfloat1622float2(z0[i]);
    float2 c = __bfloat1622float2(z1[i]);
    reinterpret_cast<__nv_bfloat162*>(out)[i] =
        __floats2bfloat162_rn(b0 * a.x + b1 * c.x, b0 * a.y + b1 * c.y);
}

// ================= predictor (pos+neg in one launch via grid.y) =================
__global__ void predict_kernel(const __nv_bfloat16* __restrict__ pa, const __nv_bfloat16* __restrict__ pt,
                               const int* __restrict__ pos_e, const int* __restrict__ neg_e,
                               const float* __restrict__ b1, const float* __restrict__ W2,
                               const float* __restrict__ b2, float* __restrict__ out)
{
    int gw = (blockIdx.x * blockDim.x + threadIdx.x) >> 5;
    int lane = threadIdx.x & 31;
    if (gw >= EP) return;
    const int* ee = blockIdx.y ? neg_e : pos_e;
    float* o = out + (size_t)blockIdx.y * EP;
    int s = ee[gw], d = ee[EP + gw];
    uint2 ua = __ldg(reinterpret_cast<const uint2*>(pa) + (size_t)s * 32 + lane);
    uint2 ub = __ldg(reinterpret_cast<const uint2*>(pt) + (size_t)d * 32 + lane);
    float4 bb = __ldg(reinterpret_cast<const float4*>(b1) + lane);
    float4 w = __ldg(reinterpret_cast<const float4*>(W2) + lane);
    float2 a0 = __bfloat1622float2(*reinterpret_cast<__nv_bfloat162*>(&ua.x));
    float2 a1 = __bfloat1622float2(*reinterpret_cast<__nv_bfloat162*>(&ua.y));
    float2 t0 = __bfloat1622float2(*reinterpret_cast<__nv_bfloat162*>(&ub.x));
    float2 t1 = __bfloat1622float2(*reinterpret_cast<__nv_bfloat162*>(&ub.y));
    float ux = fmaxf(a0.x + t0.x + bb.x, 0.f);
    float uy = fmaxf(a0.y + t0.y + bb.y, 0.f);
    float uz = fmaxf(a1.x + t1.x + bb.z, 0.f);
    float uw = fmaxf(a1.y + t1.y + bb.w, 0.f);
    float dot = ux * w.x + uy * w.y + uz * w.z + uw * w.w;
    for (int o2 = 16; o2 > 0; o2 >>= 1) dot += __shfl_down_sync(0xffffffffu, dot, o2);
    if (lane == 0) o[gw] = 1.f / (1.f + expf(-(dot + b2[0])));
}

// ================= host =================
extern "C" void kernel_launch(void* const* d_in, const int* in_sizes, int n_in,
                              void* d_out, int out_size)
{
    const float* prot   = (const float*)d_in[0];
    const float* gen    = (const float*)d_in[1];
    const float* W1     = (const float*)d_in[2];
    const float* b1     = (const float*)d_in[3];
    const float* W2     = (const float*)d_in[4];
    const float* b2     = (const float*)d_in[5];
    const float* gWs    = (const float*)d_in[6];
    const float* gbs    = (const float*)d_in[7];
    const float* gWd    = (const float*)d_in[8];
    const float* gbd    = (const float*)d_in[9];
    const float* gattn  = (const float*)d_in[10];
    const float* pAW1   = (const float*)d_in[11];
    const float* pAb1   = (const float*)d_in[12];
    const float* pAW2   = (const float*)d_in[13];
    const float* gAW1   = (const float*)d_in[14];
    const float* gAb1   = (const float*)d_in[15];
    const float* gAW2   = (const float*)d_in[16];
    const float* predW1 = (const float*)d_in[17];
    const float* predb1 = (const float*)d_in[18];
    const float* predW2 = (const float*)d_in[19];
    const float* predb2 = (const float*)d_in[20];
    const int* e_aa = (const int*)d_in[21];
    const int* e_ta = (const int*)d_in[22];
    const int* e_tt = (const int*)d_in[23];
    const int* e_at = (const int*)d_in[24];
    const int* pos_e = (const int*)d_in[25];
    const int* neg_e = (const int*)d_in[26];
    float* out = (float*)d_out;

    __nv_bfloat16 *p_protb, *p_genb, *p_hab, *p_htb, *p_Fa, *p_Ft, *p_zb, *p_haoutb, *p_htoutb, *p_pab, *p_ptb, *p_wt;
    float *p_watt, *p_biascat;
    int *p_deg, *p_off, *p_elist;
    cudaGetSymbolAddress((void**)&p_protb, g_protb);
    cudaGetSymbolAddress((void**)&p_genb, g_genb);
    cudaGetSymbolAddress((void**)&p_hab, g_hab);
    cudaGetSymbolAddress((void**)&p_htb, g_htb);
    cudaGetSymbolAddress((void**)&p_Fa, g_Fa);
    cudaGetSymbolAddress((void**)&p_Ft, g_Ft);
    cudaGetSymbolAddress((void**)&p_zb, g_zb);
    cudaGetSymbolAddress((void**)&p_haoutb, g_haoutb);
    cudaGetSymbolAddress((void**)&p_htoutb, g_htoutb);
    cudaGetSymbolAddress((void**)&p_pab, g_pab);
    cudaGetSymbolAddress((void**)&p_ptb, g_ptb);
    cudaGetSymbolAddress((void**)&p_wt, g_wt);
    cudaGetSymbolAddress((void**)&p_watt, g_watt);
    cudaGetSymbolAddress((void**)&p_biascat, g_biascat);
    cudaGetSymbolAddress((void**)&p_deg, g_deg);
    cudaGetSymbolAddress((void**)&p_off, g_off);
    cudaGetSymbolAddress((void**)&p_elist, g_elist);

    cudaFuncSetAttribute(gemm_bf16<1>, cudaFuncAttributeMaxDynamicSharedMemorySize, GSM_TOTAL);
    cudaFuncSetAttribute(gemm_bf16<0>, cudaFuncAttributeMaxDynamicSharedMemorySize, GSM_TOTAL);
    cudaFuncSetAttribute(sematt_gemm, cudaFuncAttributeMaxDynamicSharedMemorySize, SEM_SM_TOTAL);

    const int MR = (NN + 127) / 128;  // 391

    // launches ordered so #6 (ncu -s 5 -c 1) is the big protein GEMM
    f32_to_bf16_kernel<<<(NN * 1024 / 4 + 255) / 256, 256>>>(prot, p_protb, NN * 1024 / 4);   // 1
    transpose_bf16_kernel<<<(1024 * 256 + 255) / 256, 256>>>(W2, p_wt + OFF_W2T, 1024, 256);  // 2
    cudaMemsetAsync(p_deg, 0, sizeof(int) * 4 * NN);                                          // 3
    cudaMemsetAsync(p_watt, 0, sizeof(float) * 4);                                            // 4
    hist_kernel<<<dim3((EE + 255) / 256, 4), 256>>>(e_aa, e_ta, e_tt, e_at);                  // 5
    gemm_bf16<1><<<dim3(2, MR), 256, GSM_TOTAL>>>(p_protb, p_wt + OFF_W2T, b2, p_hab, NN, 256, 1024, 1024);  // 6
    scan_kernel<<<4, 1024>>>();                                                               // 7
    scatter_kernel<<<dim3((EE + 255) / 256, 4), 256>>>(e_aa, e_ta, e_tt, e_at);               // 8

    f32_to_bf16_kernel<<<(NN * 512 / 4 + 255) / 256, 256>>>(gen, p_genb, NN * 512 / 4);
    transpose_bf16_kernel<<<(512 * 256 + 255) / 256, 256>>>(W1, p_wt + OFF_W1T, 512, 256);
    concat_bias_kernel<<<1, 128>>>(gbs, gbd, p_biascat, p_biascat + 512);
    gemm_bf16<1><<<dim3(2, MR), 256, GSM_TOTAL>>>(p_genb, p_wt + OFF_W1T, b1, p_htb, NN, 256, 512, 512);

    transpose_gat_kernel<<<dim3((WSZ + 255) / 256, 8), 256>>>(gWs, gWd, p_wt);
    transpose_bf16_kernel<<<(256 * 128 + 255) / 256, 256>>>(predW1, p_wt + OFF_PW1, 256, 128);
    transpose_bf16_kernel<<<(128 * 128 + 255) / 256, 256>>>(pAW1, p_wt + OFF_SEM, 128, 128);
    transpose_bf16_kernel<<<(128 * 128 + 255) / 256, 256>>>(gAW1, p_wt + OFF_SEM + 16384, 128, 128);

    // batched GAT projections
    gemm_bf16<1><<<dim3(4, MR), 256, GSM_TOTAL>>>(p_hab, p_wt + OFF_WA,           p_biascat,       p_Fa, NN, 512, 256, 256);
    gemm_bf16<1><<<dim3(4, MR), 256, GSM_TOTAL>>>(p_htb, p_wt + OFF_WA + 4 * WSZ, p_biascat + 512, p_Ft, NN, 512, 256, 256);

    // single-pass GATv2 aggregation (writes relu(z) bf16)
    const __nv_bfloat16* FS[4] = { p_Fa + 0,   p_Ft + 0,   p_Ft + 128, p_Fa + 384 };
    const __nv_bfloat16* FD[4] = { p_Fa + 128, p_Fa + 256, p_Ft + 256, p_Ft + 384 };
    for (int g = 0; g < 4; g++) {
        gat_aggregate<<<(NN * 32 + 255) / 256, 256>>>(
            FS[g], FD[g], 128, gattn + g * 128,
            p_off + (size_t)g * NN, p_elist + (size_t)g * EE,
            p_zb + (size_t)g * NN * HIDF);
    }

    // semantic attention on tensor cores
    sematt_gemm<<<dim3(1, MR, 4), 256, SEM_SM_TOTAL>>>(p_zb, p_wt, pAb1, pAW2, gAb1, gAW2, p_watt);
    compute_beta<<<1, 1>>>();

    combine_bf16<<<dim3((NN * HIDF / 2 + 255) / 256, 2), 256>>>(p_zb, p_haoutb, p_htoutb, NN * HIDF / 2);

    gemm_bf16<1><<<dim3(1, MR), 256, GSM_TOTAL>>>(p_haoutb, p_wt + OFF_PW1,       nullptr, p_pab, NN, 128, 128, 256);
    gemm_bf16<1><<<dim3(1, MR), 256, GSM_TOTAL>>>(p_htoutb, p_wt + OFF_PW1 + 128, nullptr, p_ptb, NN, 128, 128, 256);

    predict_kernel<<<dim3((EP * 32 + 255) / 256, 2), 256>>>(p_pab, p_ptb, pos_e, neg_e, predb1, predW2, predb2, out);
}